// round 2
// baseline (speedup 1.0000x reference)
#include <cuda_runtime.h>
#include <cstdint>

// Problem constants
#define TOK   131072      // 8*128*128*256 / 256  (tokens)
#define CCH   256         // channels
#define SEQ   128         // sequence length per attention problem
#define NSEQ  1024        // number of sequences
#define NHEADS 8
#define EDIM  32

// Scratch (device globals — no runtime allocation allowed)
__device__ float g_qkv[(size_t)TOK * 768];   // per token: [q(256) | k(256) | v(256)], post scale/shift
__device__ float g_att[(size_t)TOK * 256];   // attention output, head-major channels

// ---------------------------------------------------------------------------
// Kernel 1: fused projection.
// For a 64-token x 64-channel tile, computes q,k,v,scale,shift with one shared
// K-loop (K=256, BK=32) and writes scale*x+shift fused results to g_qkv.
// ---------------------------------------------------------------------------
#define BM 64
#define BN 64
#define BK 32

__global__ __launch_bounds__(256) void proj_kernel(
    const float* __restrict__ X, const float* __restrict__ CTX,
    const float* __restrict__ Wq, const float* __restrict__ Wkv,
    const float* __restrict__ Wscale, const float* __restrict__ Wshift)
{
    extern __shared__ float sm[];
    float* sAx = sm;               // [64][32]  X tile
    float* sAc = sAx + BM*BK;      // [64][32]  CTX tile
    float* sBq = sAc + BM*BK;      // [32][64]  (K-transposed)
    float* sBk = sBq + BK*BN;
    float* sBv = sBk + BK*BN;
    float* sBs = sBv + BK*BN;
    float* sBh = sBs + BK*BN;

    const int m0 = blockIdx.x * BM;
    const int n0 = blockIdx.y * BN;
    const int tid = threadIdx.x;
    const int tx = tid & 15;
    const int ty = tid >> 4;

    float aq[4][4] = {}, ak[4][4] = {}, av[4][4] = {}, as_[4][4] = {}, ah[4][4] = {};

    for (int k0 = 0; k0 < CCH; k0 += BK) {
        __syncthreads();
        // Load A tiles (direct) and 5 B tiles (transposed). 512 float4 per tile.
        #pragma unroll
        for (int u = 0; u < 2; ++u) {
            const int idx = tid * 2 + u;          // 0..511
            const int r  = idx >> 3;              // tile row 0..63
            const int c4 = (idx & 7) << 2;        // k-offset 0..28

            *(float4*)&sAx[r*BK + c4] = *(const float4*)&X  [(size_t)(m0 + r)*CCH + k0 + c4];
            *(float4*)&sAc[r*BK + c4] = *(const float4*)&CTX[(size_t)(m0 + r)*CCH + k0 + c4];

            float4 b;
            b = *(const float4*)&Wq    [(size_t)(n0 + r)*CCH + k0 + c4];
            sBq[(c4+0)*BN + r] = b.x; sBq[(c4+1)*BN + r] = b.y; sBq[(c4+2)*BN + r] = b.z; sBq[(c4+3)*BN + r] = b.w;
            b = *(const float4*)&Wkv   [(size_t)(n0 + r)*CCH + k0 + c4];
            sBk[(c4+0)*BN + r] = b.x; sBk[(c4+1)*BN + r] = b.y; sBk[(c4+2)*BN + r] = b.z; sBk[(c4+3)*BN + r] = b.w;
            b = *(const float4*)&Wkv   [(size_t)(CCH + n0 + r)*CCH + k0 + c4];
            sBv[(c4+0)*BN + r] = b.x; sBv[(c4+1)*BN + r] = b.y; sBv[(c4+2)*BN + r] = b.z; sBv[(c4+3)*BN + r] = b.w;
            b = *(const float4*)&Wscale[(size_t)(n0 + r)*CCH + k0 + c4];
            sBs[(c4+0)*BN + r] = b.x; sBs[(c4+1)*BN + r] = b.y; sBs[(c4+2)*BN + r] = b.z; sBs[(c4+3)*BN + r] = b.w;
            b = *(const float4*)&Wshift[(size_t)(n0 + r)*CCH + k0 + c4];
            sBh[(c4+0)*BN + r] = b.x; sBh[(c4+1)*BN + r] = b.y; sBh[(c4+2)*BN + r] = b.z; sBh[(c4+3)*BN + r] = b.w;
        }
        __syncthreads();

        #pragma unroll 8
        for (int kk = 0; kk < BK; ++kk) {
            float ax[4], ac[4];
            #pragma unroll
            for (int i = 0; i < 4; ++i) {
                ax[i] = sAx[(ty*4 + i)*BK + kk];
                ac[i] = sAc[(ty*4 + i)*BK + kk];
            }
            float bq[4], bk[4], bv[4], bs[4], bh[4];
            *(float4*)bq = *(const float4*)&sBq[kk*BN + tx*4];
            *(float4*)bk = *(const float4*)&sBk[kk*BN + tx*4];
            *(float4*)bv = *(const float4*)&sBv[kk*BN + tx*4];
            *(float4*)bs = *(const float4*)&sBs[kk*BN + tx*4];
            *(float4*)bh = *(const float4*)&sBh[kk*BN + tx*4];
            #pragma unroll
            for (int i = 0; i < 4; ++i) {
                #pragma unroll
                for (int j = 0; j < 4; ++j) {
                    aq [i][j] += ax[i]*bq[j];
                    ak [i][j] += ax[i]*bk[j];
                    av [i][j] += ax[i]*bv[j];
                    as_[i][j] += ac[i]*bs[j];
                    ah [i][j] += ac[i]*bh[j];
                }
            }
        }
    }

    // Epilogue: fused scale*x + shift, vectorized stores.
    #pragma unroll
    for (int i = 0; i < 4; ++i) {
        const int m = m0 + ty*4 + i;
        const size_t base = (size_t)m*768 + n0 + tx*4;
        float tq[4], tk[4], tv[4];
        #pragma unroll
        for (int j = 0; j < 4; ++j) {
            const float sc = as_[i][j];
            const float sh = ah[i][j];
            tq[j] = sc*aq[i][j] + sh;
            tk[j] = sc*ak[i][j] + sh;
            tv[j] = sc*av[i][j] + sh;
        }
        *(float4*)&g_qkv[base      ] = *(float4*)tq;
        *(float4*)&g_qkv[base + 256] = *(float4*)tk;
        *(float4*)&g_qkv[base + 512] = *(float4*)tv;
    }
}

// ---------------------------------------------------------------------------
// Kernel 2: attention. One CTA per (sequence, head). S materialized in smem.
// ---------------------------------------------------------------------------
#define SS_STRIDE 132   // 128 + 4 padding (float4-aligned)

__global__ __launch_bounds__(512) void attn_kernel()
{
    extern __shared__ float sm[];
    float* sq  = sm;               // [128][32]
    float* skT = sq  + SEQ*EDIM;   // [32][128] (transposed)
    float* sv  = skT + EDIM*SEQ;   // [128][32]
    float* ss  = sv  + SEQ*EDIM;   // [128][SS_STRIDE]

    const int bid  = blockIdx.x;
    const int nseq = bid >> 3;
    const int h    = bid & 7;
    const int t0   = nseq * SEQ;
    const int tid  = threadIdx.x;

    // Load Q,K,V for this head; K transposed for conflict-free reads.
    #pragma unroll
    for (int u = 0; u < 2; ++u) {
        const int idx = tid*2 + u;            // 0..1023
        const int s   = idx >> 3;             // token 0..127
        const int c4  = (idx & 7) << 2;       // channel 0..28
        const size_t gbase = (size_t)(t0 + s)*768 + h*EDIM + c4;
        float4 q4 = *(const float4*)&g_qkv[gbase];
        *(float4*)&sq[s*EDIM + c4] = q4;
        float4 k4 = *(const float4*)&g_qkv[gbase + 256];
        skT[(c4+0)*SEQ + s] = k4.x; skT[(c4+1)*SEQ + s] = k4.y;
        skT[(c4+2)*SEQ + s] = k4.z; skT[(c4+3)*SEQ + s] = k4.w;
        float4 v4 = *(const float4*)&g_qkv[gbase + 512];
        *(float4*)&sv[s*EDIM + c4] = v4;
    }
    __syncthreads();

    // S = Q K^T / sqrt(32): each thread computes a 4x8 micro-tile.
    {
        const int i0 = (tid >> 4) * 4;    // query rows
        const int j0 = (tid & 15) * 8;    // key cols
        float acc[4][8] = {};
        #pragma unroll 4
        for (int c = 0; c < EDIM; ++c) {
            float qv[4];
            #pragma unroll
            for (int i = 0; i < 4; ++i) qv[i] = sq[(i0+i)*EDIM + c];
            float kv[8];
            *(float4*)(kv  ) = *(const float4*)&skT[c*SEQ + j0];
            *(float4*)(kv+4) = *(const float4*)&skT[c*SEQ + j0 + 4];
            #pragma unroll
            for (int i = 0; i < 4; ++i)
                #pragma unroll
                for (int j = 0; j < 8; ++j)
                    acc[i][j] += qv[i]*kv[j];
        }
        const float scl = 0.17677669529663688f;  // 1/sqrt(32)
        #pragma unroll
        for (int i = 0; i < 4; ++i) {
            float t0_[4], t1_[4];
            #pragma unroll
            for (int j = 0; j < 4; ++j) { t0_[j] = acc[i][j]*scl; t1_[j] = acc[i][j+4]*scl; }
            *(float4*)&ss[(i0+i)*SS_STRIDE + j0    ] = *(float4*)t0_;
            *(float4*)&ss[(i0+i)*SS_STRIDE + j0 + 4] = *(float4*)t1_;
        }
    }
    __syncthreads();

    // Row softmax: one warp per row, 16 warps.
    {
        const int warp = tid >> 5, lane = tid & 31;
        for (int r = warp; r < SEQ; r += 16) {
            float* row = ss + r*SS_STRIDE;
            float v0 = row[lane], v1 = row[lane+32], v2 = row[lane+64], v3 = row[lane+96];
            float mx = fmaxf(fmaxf(v0, v1), fmaxf(v2, v3));
            #pragma unroll
            for (int o = 16; o > 0; o >>= 1) mx = fmaxf(mx, __shfl_xor_sync(0xffffffffu, mx, o));
            float e0 = __expf(v0 - mx), e1 = __expf(v1 - mx), e2 = __expf(v2 - mx), e3 = __expf(v3 - mx);
            float sum = e0 + e1 + e2 + e3;
            #pragma unroll
            for (int o = 16; o > 0; o >>= 1) sum += __shfl_xor_sync(0xffffffffu, sum, o);
            const float inv = 1.0f / sum;
            row[lane]    = e0*inv; row[lane+32] = e1*inv;
            row[lane+64] = e2*inv; row[lane+96] = e3*inv;
        }
    }
    __syncthreads();

    // O = S V: each thread computes one row x 8 cols.
    {
        const int i  = tid >> 2;          // row 0..127
        const int c0 = (tid & 3) * 8;     // col 0,8,16,24
        float acc[8] = {};
        #pragma unroll 4
        for (int j = 0; j < SEQ; ++j) {
            const float s = ss[i*SS_STRIDE + j];
            float vv[8];
            *(float4*)(vv  ) = *(const float4*)&sv[j*EDIM + c0];
            *(float4*)(vv+4) = *(const float4*)&sv[j*EDIM + c0 + 4];
            #pragma unroll
            for (int c = 0; c < 8; ++c) acc[c] += s*vv[c];
        }
        const size_t obase = (size_t)(t0 + i)*CCH + h*EDIM + c0;
        *(float4*)&g_att[obase    ] = *(float4*)(acc);
        *(float4*)&g_att[obase + 4] = *(float4*)(acc + 4);
    }
}

// ---------------------------------------------------------------------------
// Kernel 3: output projection. out = g_att @ Wout^T
// ---------------------------------------------------------------------------
__global__ __launch_bounds__(256) void out_kernel(
    const float* __restrict__ Wout, float* __restrict__ out)
{
    __shared__ float sA[BM*BK];   // [64][32]
    __shared__ float sB[BK*BN];   // [32][64] transposed

    const int m0 = blockIdx.x * BM;
    const int n0 = blockIdx.y * BN;
    const int tid = threadIdx.x;
    const int tx = tid & 15;
    const int ty = tid >> 4;

    float acc[4][4] = {};

    for (int k0 = 0; k0 < CCH; k0 += BK) {
        __syncthreads();
        #pragma unroll
        for (int u = 0; u < 2; ++u) {
            const int idx = tid*2 + u;
            const int r  = idx >> 3;
            const int c4 = (idx & 7) << 2;
            *(float4*)&sA[r*BK + c4] = *(const float4*)&g_att[(size_t)(m0 + r)*CCH + k0 + c4];
            float4 b = *(const float4*)&Wout[(size_t)(n0 + r)*CCH + k0 + c4];
            sB[(c4+0)*BN + r] = b.x; sB[(c4+1)*BN + r] = b.y;
            sB[(c4+2)*BN + r] = b.z; sB[(c4+3)*BN + r] = b.w;
        }
        __syncthreads();

        #pragma unroll 8
        for (int kk = 0; kk < BK; ++kk) {
            float ax[4];
            #pragma unroll
            for (int i = 0; i < 4; ++i) ax[i] = sA[(ty*4 + i)*BK + kk];
            float bb[4];
            *(float4*)bb = *(const float4*)&sB[kk*BN + tx*4];
            #pragma unroll
            for (int i = 0; i < 4; ++i)
                #pragma unroll
                for (int j = 0; j < 4; ++j)
                    acc[i][j] += ax[i]*bb[j];
        }
    }

    #pragma unroll
    for (int i = 0; i < 4; ++i) {
        float t[4];
        #pragma unroll
        for (int j = 0; j < 4; ++j) t[j] = acc[i][j];
        *(float4*)&out[(size_t)(m0 + ty*4 + i)*CCH + n0 + tx*4] = *(float4*)t;
    }
}

// ---------------------------------------------------------------------------
extern "C" void kernel_launch(void* const* d_in, const int* in_sizes, int n_in,
                              void* d_out, int out_size)
{
    (void)in_sizes; (void)n_in; (void)out_size;
    const float* X      = (const float*)d_in[0];
    const float* CTX    = (const float*)d_in[1];
    const float* Wq     = (const float*)d_in[2];
    const float* Wkv    = (const float*)d_in[3];
    const float* Wout   = (const float*)d_in[4];
    const float* Wscale = (const float*)d_in[5];
    const float* Wshift = (const float*)d_in[6];
    float* out = (float*)d_out;

    const int proj_smem = (2*BM*BK + 5*BK*BN) * (int)sizeof(float);        // 57344 B
    const int attn_smem = (3*SEQ*EDIM + SEQ*SS_STRIDE) * (int)sizeof(float); // 116736 B
    cudaFuncSetAttribute(proj_kernel, cudaFuncAttributeMaxDynamicSharedMemorySize, proj_smem);
    cudaFuncSetAttribute(attn_kernel, cudaFuncAttributeMaxDynamicSharedMemorySize, attn_smem);

    proj_kernel<<<dim3(TOK/BM, CCH/BN), 256, proj_smem>>>(X, CTX, Wq, Wkv, Wscale, Wshift);
    attn_kernel<<<NSEQ*NHEADS, 512, attn_smem>>>();
    out_kernel<<<dim3(TOK/BM, CCH/BN), 256>>>(Wout, out);
}

// round 6
// speedup vs baseline: 1.8820x; 1.8820x over previous
#include <cuda_runtime.h>
#include <cuda_fp16.h>
#include <cstdint>

#define TOK   131072
#define CCH   256
#define SEQ   128
#define NSEQ  1024
#define NHEADS 8
#define EDIM  32

__device__ float g_qkv[(size_t)TOK * 768];   // [q|k|v] per token, post scale/shift
__device__ float g_att[(size_t)TOK * 256];   // attention output

extern __shared__ __align__(16) char smraw[];

// ---------------- helpers ----------------
__device__ __forceinline__ uint32_t smem_u32(const void* p) {
    uint32_t a;
    asm("{ .reg .u64 t; cvta.to.shared.u64 t, %1; cvt.u32.u64 %0, t; }" : "=r"(a) : "l"(p));
    return a;
}
__device__ __forceinline__ void ldsm4(uint32_t* r, uint32_t a) {
    asm volatile("ldmatrix.sync.aligned.m8n8.x4.shared.b16 {%0,%1,%2,%3}, [%4];"
        : "=r"(r[0]), "=r"(r[1]), "=r"(r[2]), "=r"(r[3]) : "r"(a));
}
__device__ __forceinline__ void mmaf16(float* d, const uint32_t* a, uint32_t b0, uint32_t b1) {
    asm volatile("mma.sync.aligned.m16n8k16.row.col.f32.f16.f16.f32 "
        "{%0,%1,%2,%3}, {%4,%5,%6,%7}, {%8,%9}, {%0,%1,%2,%3};"
        : "+f"(d[0]), "+f"(d[1]), "+f"(d[2]), "+f"(d[3])
        : "r"(a[0]), "r"(a[1]), "r"(a[2]), "r"(a[3]), "r"(b0), "r"(b1));
}

// fp32 float4 -> fp16 hi/lo pairs (packed half2 as uint32)
struct H4 { uint2 hi, lo; };
__device__ __forceinline__ H4 splitf4(float4 v) {
    __half2 h0 = __floats2half2_rn(v.x, v.y);
    __half2 h1 = __floats2half2_rn(v.z, v.w);
    float2 f0 = __half22float2(h0), f1 = __half22float2(h1);
    __half2 l0 = __floats2half2_rn(v.x - f0.x, v.y - f0.y);
    __half2 l1 = __floats2half2_rn(v.z - f1.x, v.w - f1.y);
    H4 r;
    r.hi.x = *(uint32_t*)&h0; r.hi.y = *(uint32_t*)&h1;
    r.lo.x = *(uint32_t*)&l0; r.lo.y = *(uint32_t*)&l1;
    return r;
}

// Tile rows are 32 fp16 (64B) padded to 80B: 8 consecutive rows hit 8 distinct
// 4-bank groups (20*r mod 32 all distinct) -> conflict-free ldmatrix.
#define RSTR 80
__device__ __forceinline__ uint32_t fragA(uint32_t matbase, int row0, int kb, int lane) {
    return matbase + (uint32_t)(row0 + (lane & 15)) * RSTR
                   + (uint32_t)(kb * 32 + ((lane >> 4) << 4));
}

// ---------------------------------------------------------------------------
// Kernel 1: fused projection via mma.sync fp16 3-term split.
// CTA: 128 tokens x 32 channels, all 5 outputs (q,k,v from X; scale,shift
// from CTX), fused scale*x+shift epilogue.
// smem: Xhi Xlo Chi Clo (128x32 each) + 5 weights hi/lo (32x32 each)
// ---------------------------------------------------------------------------
#define XHI 0
#define XLO 10240
#define CHI 20480
#define CLO 30720
#define WHI(t) (40960 + (t)*5120)
#define WLO(t) (40960 + (t)*5120 + 2560)
#define PROJ_SMEM 66560

__global__ __launch_bounds__(256, 1) void proj_kernel(
    const float* __restrict__ X, const float* __restrict__ CTX,
    const float* __restrict__ Wq, const float* __restrict__ Wkv,
    const float* __restrict__ Wscale, const float* __restrict__ Wshift)
{
    const int tid = threadIdx.x;
    const int wid = tid >> 5, lane = tid & 31;
    const int n0 = blockIdx.x * 32;
    const int m0 = blockIdx.y * 128;
    const uint32_t sbase = smem_u32(smraw);

    float4 rx[4], rc[4], rw[5];

    auto ldg = [&](int k0) {
        #pragma unroll
        for (int u = 0; u < 4; ++u) {
            int idx = tid + u*256, r = idx >> 3, kq = idx & 7;
            rx[u] = *(const float4*)&X  [(size_t)(m0 + r)*CCH + k0 + kq*4];
            rc[u] = *(const float4*)&CTX[(size_t)(m0 + r)*CCH + k0 + kq*4];
        }
        {
            int r = tid >> 3, kq = tid & 7;
            size_t o = (size_t)(n0 + r)*CCH + k0 + kq*4;
            rw[0] = *(const float4*)&Wq[o];
            rw[1] = *(const float4*)&Wkv[o];
            rw[2] = *(const float4*)&Wkv[o + (size_t)CCH*CCH];
            rw[3] = *(const float4*)&Wscale[o];
            rw[4] = *(const float4*)&Wshift[o];
        }
    };
    auto sts = [&]() {
        #pragma unroll
        for (int u = 0; u < 4; ++u) {
            int idx = tid + u*256, r = idx >> 3, kq = idx & 7;
            uint32_t off = (uint32_t)(r*RSTR + kq*8);
            H4 hx = splitf4(rx[u]);
            *(uint2*)(smraw + XHI + off) = hx.hi;
            *(uint2*)(smraw + XLO + off) = hx.lo;
            H4 hc = splitf4(rc[u]);
            *(uint2*)(smraw + CHI + off) = hc.hi;
            *(uint2*)(smraw + CLO + off) = hc.lo;
        }
        {
            int r = tid >> 3, kq = tid & 7;
            uint32_t off = (uint32_t)(r*RSTR + kq*8);
            #pragma unroll
            for (int t = 0; t < 5; ++t) {
                H4 h = splitf4(rw[t]);
                *(uint2*)(smraw + WHI(t) + off) = h.hi;
                *(uint2*)(smraw + WLO(t) + off) = h.lo;
            }
        }
    };

    float acc[5][2][2][4] = {};
    const int wm = (wid >> 1) * 32;
    const int wn = (wid & 1) * 16;

    ldg(0);
    #pragma unroll 1
    for (int c = 0; c < 8; ++c) {
        sts();
        __syncthreads();
        if (c < 7) ldg((c + 1) * 32);

        #pragma unroll
        for (int kb = 0; kb < 2; ++kb) {
            uint32_t axh[2][4], axl[2][4], ach[2][4], acl[2][4];
            #pragma unroll
            for (int mi = 0; mi < 2; ++mi) {
                ldsm4(axh[mi], fragA(sbase + XHI, wm + mi*16, kb, lane));
                ldsm4(axl[mi], fragA(sbase + XLO, wm + mi*16, kb, lane));
                ldsm4(ach[mi], fragA(sbase + CHI, wm + mi*16, kb, lane));
                ldsm4(acl[mi], fragA(sbase + CLO, wm + mi*16, kb, lane));
            }
            #pragma unroll
            for (int t = 0; t < 5; ++t) {
                uint32_t bh[4], bl[4];
                ldsm4(bh, fragA(sbase + WHI(t), wn, kb, lane));
                ldsm4(bl, fragA(sbase + WLO(t), wn, kb, lane));
                const uint32_t (*Ah)[4] = (t < 3) ? axh : ach;
                const uint32_t (*Al)[4] = (t < 3) ? axl : acl;
                #pragma unroll
                for (int mi = 0; mi < 2; ++mi)
                    #pragma unroll
                    for (int ni = 0; ni < 2; ++ni) {
                        mmaf16(acc[t][mi][ni], Ah[mi], bh[ni], bh[ni+2]);
                        mmaf16(acc[t][mi][ni], Al[mi], bh[ni], bh[ni+2]);
                        mmaf16(acc[t][mi][ni], Ah[mi], bl[ni], bl[ni+2]);
                    }
            }
        }
        __syncthreads();
    }

    // Epilogue: fused scale*x + shift
    const int g = lane >> 2, tg = lane & 3;
    #pragma unroll
    for (int mi = 0; mi < 2; ++mi)
        #pragma unroll
        for (int ni = 0; ni < 2; ++ni)
            #pragma unroll
            for (int h2 = 0; h2 < 2; ++h2) {
                const int row = m0 + wm + mi*16 + g + h2*8;
                const int col = n0 + wn + ni*8 + tg*2;
                const int i0 = h2*2;
                float sc0 = acc[3][mi][ni][i0],   sc1 = acc[3][mi][ni][i0+1];
                float sh0 = acc[4][mi][ni][i0],   sh1 = acc[4][mi][ni][i0+1];
                float2 q = make_float2(fmaf(sc0, acc[0][mi][ni][i0], sh0),
                                       fmaf(sc1, acc[0][mi][ni][i0+1], sh1));
                float2 k = make_float2(fmaf(sc0, acc[1][mi][ni][i0], sh0),
                                       fmaf(sc1, acc[1][mi][ni][i0+1], sh1));
                float2 v = make_float2(fmaf(sc0, acc[2][mi][ni][i0], sh0),
                                       fmaf(sc1, acc[2][mi][ni][i0+1], sh1));
                size_t base = (size_t)row*768 + col;
                *(float2*)&g_qkv[base      ] = q;
                *(float2*)&g_qkv[base + 256] = k;
                *(float2*)&g_qkv[base + 512] = v;
            }
}

// ---------------------------------------------------------------------------
// Kernel 2: attention (fp32 FFMA — known good).
// ---------------------------------------------------------------------------
#define SS_STRIDE 132

__global__ __launch_bounds__(512) void attn_kernel()
{
    float* smf = (float*)smraw;
    float* sq  = smf;
    float* skT = sq  + SEQ*EDIM;
    float* sv  = skT + EDIM*SEQ;
    float* ss  = sv  + SEQ*EDIM;

    const int bid  = blockIdx.x;
    const int nseq = bid >> 3;
    const int h    = bid & 7;
    const int t0   = nseq * SEQ;
    const int tid  = threadIdx.x;

    #pragma unroll
    for (int u = 0; u < 2; ++u) {
        const int idx = tid*2 + u;
        const int s   = idx >> 3;
        const int c4  = (idx & 7) << 2;
        const size_t gbase = (size_t)(t0 + s)*768 + h*EDIM + c4;
        float4 q4 = *(const float4*)&g_qkv[gbase];
        *(float4*)&sq[s*EDIM + c4] = q4;
        float4 k4 = *(const float4*)&g_qkv[gbase + 256];
        skT[(c4+0)*SEQ + s] = k4.x; skT[(c4+1)*SEQ + s] = k4.y;
        skT[(c4+2)*SEQ + s] = k4.z; skT[(c4+3)*SEQ + s] = k4.w;
        float4 v4 = *(const float4*)&g_qkv[gbase + 512];
        *(float4*)&sv[s*EDIM + c4] = v4;
    }
    __syncthreads();

    {
        const int i0 = (tid >> 4) * 4;
        const int j0 = (tid & 15) * 8;
        float acc[4][8] = {};
        #pragma unroll 4
        for (int c = 0; c < EDIM; ++c) {
            float qv[4];
            #pragma unroll
            for (int i = 0; i < 4; ++i) qv[i] = sq[(i0+i)*EDIM + c];
            float kv[8];
            *(float4*)(kv  ) = *(const float4*)&skT[c*SEQ + j0];
            *(float4*)(kv+4) = *(const float4*)&skT[c*SEQ + j0 + 4];
            #pragma unroll
            for (int i = 0; i < 4; ++i)
                #pragma unroll
                for (int j = 0; j < 8; ++j)
                    acc[i][j] += qv[i]*kv[j];
        }
        const float scl = 0.17677669529663688f;
        #pragma unroll
        for (int i = 0; i < 4; ++i) {
            float t0_[4], t1_[4];
            #pragma unroll
            for (int j = 0; j < 4; ++j) { t0_[j] = acc[i][j]*scl; t1_[j] = acc[i][j+4]*scl; }
            *(float4*)&ss[(i0+i)*SS_STRIDE + j0    ] = *(float4*)t0_;
            *(float4*)&ss[(i0+i)*SS_STRIDE + j0 + 4] = *(float4*)t1_;
        }
    }
    __syncthreads();

    {
        const int warp = tid >> 5, lane = tid & 31;
        for (int r = warp; r < SEQ; r += 16) {
            float* row = ss + r*SS_STRIDE;
            float v0 = row[lane], v1 = row[lane+32], v2 = row[lane+64], v3 = row[lane+96];
            float mx = fmaxf(fmaxf(v0, v1), fmaxf(v2, v3));
            #pragma unroll
            for (int o = 16; o > 0; o >>= 1) mx = fmaxf(mx, __shfl_xor_sync(0xffffffffu, mx, o));
            float e0 = __expf(v0 - mx), e1 = __expf(v1 - mx), e2 = __expf(v2 - mx), e3 = __expf(v3 - mx);
            float sum = e0 + e1 + e2 + e3;
            #pragma unroll
            for (int o = 16; o > 0; o >>= 1) sum += __shfl_xor_sync(0xffffffffu, sum, o);
            const float inv = 1.0f / sum;
            row[lane]    = e0*inv; row[lane+32] = e1*inv;
            row[lane+64] = e2*inv; row[lane+96] = e3*inv;
        }
    }
    __syncthreads();

    {
        const int i  = tid >> 2;
        const int c0 = (tid & 3) * 8;
        float acc[8] = {};
        #pragma unroll 4
        for (int j = 0; j < SEQ; ++j) {
            const float s = ss[i*SS_STRIDE + j];
            float vv[8];
            *(float4*)(vv  ) = *(const float4*)&sv[j*EDIM + c0];
            *(float4*)(vv+4) = *(const float4*)&sv[j*EDIM + c0 + 4];
            #pragma unroll
            for (int c = 0; c < 8; ++c) acc[c] += s*vv[c];
        }
        const size_t obase = (size_t)(t0 + i)*CCH + h*EDIM + c0;
        *(float4*)&g_att[obase    ] = *(float4*)(acc);
        *(float4*)&g_att[obase + 4] = *(float4*)(acc + 4);
    }
}

// ---------------------------------------------------------------------------
// Kernel 3: out = g_att @ Wout^T via mma.sync fp16 3-term split. CTA 128x64.
// ---------------------------------------------------------------------------
#define OAHI 0
#define OALO 10240
#define OBHI 20480
#define OBLO 25600
#define OUT_SMEM 30720

__global__ __launch_bounds__(256, 1) void out_kernel(
    const float* __restrict__ Wout, float* __restrict__ out)
{
    const int tid = threadIdx.x;
    const int wid = tid >> 5, lane = tid & 31;
    const int n0 = blockIdx.x * 64;
    const int m0 = blockIdx.y * 128;
    const uint32_t sbase = smem_u32(smraw);

    float4 ra[4], rb[2];
    auto ldg = [&](int k0) {
        #pragma unroll
        for (int u = 0; u < 4; ++u) {
            int idx = tid + u*256, r = idx >> 3, kq = idx & 7;
            ra[u] = *(const float4*)&g_att[(size_t)(m0 + r)*CCH + k0 + kq*4];
        }
        #pragma unroll
        for (int u = 0; u < 2; ++u) {
            int idx = tid + u*256, r = idx >> 3, kq = idx & 7;
            rb[u] = *(const float4*)&Wout[(size_t)(n0 + r)*CCH + k0 + kq*4];
        }
    };
    auto sts = [&]() {
        #pragma unroll
        for (int u = 0; u < 4; ++u) {
            int idx = tid + u*256, r = idx >> 3, kq = idx & 7;
            uint32_t off = (uint32_t)(r*RSTR + kq*8);
            H4 h = splitf4(ra[u]);
            *(uint2*)(smraw + OAHI + off) = h.hi;
            *(uint2*)(smraw + OALO + off) = h.lo;
        }
        #pragma unroll
        for (int u = 0; u < 2; ++u) {
            int idx = tid + u*256, r = idx >> 3, kq = idx & 7;
            uint32_t off = (uint32_t)(r*RSTR + kq*8);
            H4 h = splitf4(rb[u]);
            *(uint2*)(smraw + OBHI + off) = h.hi;
            *(uint2*)(smraw + OBLO + off) = h.lo;
        }
    };

    float acc[2][4][4] = {};
    const int wm = (wid >> 1) * 32;
    const int wn = (wid & 1) * 32;

    ldg(0);
    #pragma unroll 1
    for (int c = 0; c < 8; ++c) {
        sts();
        __syncthreads();
        if (c < 7) ldg((c + 1) * 32);

        #pragma unroll
        for (int kb = 0; kb < 2; ++kb) {
            uint32_t ah[2][4], al[2][4];
            #pragma unroll
            for (int mi = 0; mi < 2; ++mi) {
                ldsm4(ah[mi], fragA(sbase + OAHI, wm + mi*16, kb, lane));
                ldsm4(al[mi], fragA(sbase + OALO, wm + mi*16, kb, lane));
            }
            uint32_t bh0[4], bh1[4], bl0[4], bl1[4];
            ldsm4(bh0, fragA(sbase + OBHI, wn,      kb, lane));
            ldsm4(bh1, fragA(sbase + OBHI, wn + 16, kb, lane));
            ldsm4(bl0, fragA(sbase + OBLO, wn,      kb, lane));
            ldsm4(bl1, fragA(sbase + OBLO, wn + 16, kb, lane));
            #pragma unroll
            for (int mi = 0; mi < 2; ++mi)
                #pragma unroll
                for (int ni = 0; ni < 4; ++ni) {
                    const uint32_t* bh = (ni < 2) ? bh0 : bh1;
                    const uint32_t* bl = (ni < 2) ? bl0 : bl1;
                    int j = ni & 1;
                    mmaf16(acc[mi][ni], ah[mi], bh[j], bh[j+2]);
                    mmaf16(acc[mi][ni], al[mi], bh[j], bh[j+2]);
                    mmaf16(acc[mi][ni], ah[mi], bl[j], bl[j+2]);
                }
        }
        __syncthreads();
    }

    const int g = lane >> 2, tg = lane & 3;
    #pragma unroll
    for (int mi = 0; mi < 2; ++mi)
        #pragma unroll
        for (int ni = 0; ni < 4; ++ni)
            #pragma unroll
            for (int h2 = 0; h2 < 2; ++h2) {
                const int row = m0 + wm + mi*16 + g + h2*8;
                const int col = n0 + wn + ni*8 + tg*2;
                const int i0 = h2*2;
                *(float2*)&out[(size_t)row*CCH + col] =
                    make_float2(acc[mi][ni][i0], acc[mi][ni][i0+1]);
            }
}

// ---------------------------------------------------------------------------
extern "C" void kernel_launch(void* const* d_in, const int* in_sizes, int n_in,
                              void* d_out, int out_size)
{
    (void)in_sizes; (void)n_in; (void)out_size;
    const float* X      = (const float*)d_in[0];
    const float* CTX    = (const float*)d_in[1];
    const float* Wq     = (const float*)d_in[2];
    const float* Wkv    = (const float*)d_in[3];
    const float* Wout   = (const float*)d_in[4];
    const float* Wscale = (const float*)d_in[5];
    const float* Wshift = (const float*)d_in[6];
    float* out = (float*)d_out;

    const int attn_smem = (3*SEQ*EDIM + SEQ*SS_STRIDE) * (int)sizeof(float);  // 116736
    cudaFuncSetAttribute(proj_kernel, cudaFuncAttributeMaxDynamicSharedMemorySize, PROJ_SMEM);
    cudaFuncSetAttribute(attn_kernel, cudaFuncAttributeMaxDynamicSharedMemorySize, attn_smem);
    cudaFuncSetAttribute(out_kernel,  cudaFuncAttributeMaxDynamicSharedMemorySize, OUT_SMEM);

    proj_kernel<<<dim3(8, 1024), 256, PROJ_SMEM>>>(X, CTX, Wq, Wkv, Wscale, Wshift);
    attn_kernel<<<NSEQ*NHEADS, 512, attn_smem>>>();
    out_kernel<<<dim3(4, 1024), 256, OUT_SMEM>>>(Wout, out);
}

// round 7
// speedup vs baseline: 2.0785x; 1.1044x over previous
#include <cuda_runtime.h>
#include <cuda_fp16.h>
#include <cstdint>

#define TOK   131072
#define CCH   256
#define SEQ   128
#define NSEQ  1024
#define NHEADS 8
#define EDIM  32

// fp16 hi/lo global buffers (split precision: x = hi + lo)
__device__ __half g_xh[(size_t)TOK * 256], g_xl[(size_t)TOK * 256];
__device__ __half g_ch[(size_t)TOK * 256], g_cl[(size_t)TOK * 256];
__device__ __half g_wh[6 * 65536], g_wl[6 * 65536];   // Wq, Wk, Wv, Wscale, Wshift, Wout
__device__ __half g_qh[(size_t)TOK * 768], g_ql[(size_t)TOK * 768];  // q|k|v post scale/shift
__device__ __half g_oh[(size_t)TOK * 256], g_ol[(size_t)TOK * 256];  // attention out

extern __shared__ __align__(16) char smraw[];

// ---------------- helpers ----------------
__device__ __forceinline__ uint32_t smem_u32(const void* p) {
    uint32_t a;
    asm("{ .reg .u64 t; cvta.to.shared.u64 t, %1; cvt.u32.u64 %0, t; }" : "=r"(a) : "l"(p));
    return a;
}
__device__ __forceinline__ void ldsm4(uint32_t* r, uint32_t a) {
    asm volatile("ldmatrix.sync.aligned.m8n8.x4.shared.b16 {%0,%1,%2,%3}, [%4];"
        : "=r"(r[0]), "=r"(r[1]), "=r"(r[2]), "=r"(r[3]) : "r"(a));
}
__device__ __forceinline__ void ldsm4t(uint32_t* r, uint32_t a) {
    asm volatile("ldmatrix.sync.aligned.m8n8.x4.trans.shared.b16 {%0,%1,%2,%3}, [%4];"
        : "=r"(r[0]), "=r"(r[1]), "=r"(r[2]), "=r"(r[3]) : "r"(a));
}
__device__ __forceinline__ void mmaf16(float* d, const uint32_t* a, uint32_t b0, uint32_t b1) {
    asm volatile("mma.sync.aligned.m16n8k16.row.col.f32.f16.f16.f32 "
        "{%0,%1,%2,%3}, {%4,%5,%6,%7}, {%8,%9}, {%0,%1,%2,%3};"
        : "+f"(d[0]), "+f"(d[1]), "+f"(d[2]), "+f"(d[3])
        : "r"(a[0]), "r"(a[1]), "r"(a[2]), "r"(a[3]), "r"(b0), "r"(b1));
}
#define CP16(s, g) asm volatile("cp.async.cg.shared.global [%0], [%1], 16;" :: "r"(s), "l"(g))
#define CPCOMMIT() asm volatile("cp.async.commit_group;")
#define CPWAIT0()  asm volatile("cp.async.wait_group 0;")

struct H4 { uint2 hi, lo; };
__device__ __forceinline__ H4 splitf4(float4 v) {
    __half2 h0 = __floats2half2_rn(v.x, v.y);
    __half2 h1 = __floats2half2_rn(v.z, v.w);
    float2 f0 = __half22float2(h0), f1 = __half22float2(h1);
    __half2 l0 = __floats2half2_rn(v.x - f0.x, v.y - f0.y);
    __half2 l1 = __floats2half2_rn(v.z - f1.x, v.w - f1.y);
    H4 r;
    r.hi.x = *(uint32_t*)&h0; r.hi.y = *(uint32_t*)&h1;
    r.lo.x = *(uint32_t*)&l0; r.lo.y = *(uint32_t*)&l1;
    return r;
}
// hi/lo half2 from two floats
__device__ __forceinline__ void split2(float a, float b, uint32_t& hi, uint32_t& lo) {
    __half2 h = __floats2half2_rn(a, b);
    float2 f = __half22float2(h);
    __half2 l = __floats2half2_rn(a - f.x, b - f.y);
    hi = *(uint32_t*)&h; lo = *(uint32_t*)&l;
}

#define RSTR 80   // 32 halves (64B) padded to 80B -> conflict-free ldmatrix
__device__ __forceinline__ uint32_t fragA(uint32_t matbase, int row0, int kb, int lane) {
    return matbase + (uint32_t)(row0 + (lane & 15)) * RSTR
                   + (uint32_t)(kb * 32 + ((lane >> 4) << 4));
}

// ---------------------------------------------------------------------------
// Kernel 0: fp32 -> fp16 hi/lo convert (memory bound)
// ---------------------------------------------------------------------------
__global__ __launch_bounds__(256) void conv_kernel(
    const float4* __restrict__ s, uint2* __restrict__ dh, uint2* __restrict__ dl, int n)
{
    for (int i = blockIdx.x * blockDim.x + threadIdx.x; i < n; i += gridDim.x * blockDim.x) {
        H4 h = splitf4(s[i]);
        dh[i] = h.hi; dl[i] = h.lo;
    }
}

// ---------------------------------------------------------------------------
// Kernel 1: fused projection. CTA 128 tokens x 32 channels, 5 outputs,
// cp.async double-buffered fp16 tiles, fused scale*x+shift epilogue.
// buffer layout: XH 0, XL 10240, CH 20480, CL 30720, W(t,hl) 40960+(t*2+hl)*2560
// ---------------------------------------------------------------------------
#define PJ_BUF 66560
#define PROJ_SMEM (2*PJ_BUF)

__global__ __launch_bounds__(256, 1) void proj_kernel()
{
    const int tid = threadIdx.x;
    const int wid = tid >> 5, lane = tid & 31;
    const int n0 = blockIdx.x * 32;
    const int m0 = blockIdx.y * 128;
    const uint32_t sbase = smem_u32(smraw);

    auto issue = [&](int c, int b) {
        const int k0 = c * 32;
        const uint32_t sb = sbase + b * PJ_BUF;
        #pragma unroll
        for (int u = 0; u < 2; ++u) {
            int task = tid + u*256, row = task >> 2, seg = task & 3;
            uint32_t so = (uint32_t)(row*RSTR + seg*16);
            size_t gi = (size_t)(m0 + row)*CCH + k0 + seg*8;
            CP16(sb + so,         g_xh + gi);
            CP16(sb + 10240 + so, g_xl + gi);
            CP16(sb + 20480 + so, g_ch + gi);
            CP16(sb + 30720 + so, g_cl + gi);
        }
        #pragma unroll
        for (int i = 0; i < 5; ++i) {
            int task = tid + i*256;             // 0..1279
            int tile = task >> 7;               // 0..9
            int r = (task & 127) >> 2, seg = task & 3;
            int t = tile >> 1, hl = tile & 1;
            uint32_t so = (uint32_t)(40960 + tile*2560 + r*RSTR + seg*16);
            const __half* src = (hl ? g_wl : g_wh) + (size_t)t*65536 + (size_t)(n0 + r)*CCH + k0 + seg*8;
            CP16(sb + so, src);
        }
    };

    float acc[5][2][2][4] = {};
    const int wm = (wid >> 1) * 32;
    const int wn = (wid & 1) * 16;

    auto compute = [&](uint32_t sb) {
        #pragma unroll
        for (int kb = 0; kb < 2; ++kb) {
            uint32_t axh[2][4], axl[2][4], ach[2][4], acl[2][4];
            #pragma unroll
            for (int mi = 0; mi < 2; ++mi) {
                ldsm4(axh[mi], fragA(sb,         wm + mi*16, kb, lane));
                ldsm4(axl[mi], fragA(sb + 10240, wm + mi*16, kb, lane));
                ldsm4(ach[mi], fragA(sb + 20480, wm + mi*16, kb, lane));
                ldsm4(acl[mi], fragA(sb + 30720, wm + mi*16, kb, lane));
            }
            #pragma unroll
            for (int t = 0; t < 5; ++t) {
                uint32_t bh[4], bl[4];
                ldsm4(bh, fragA(sb + 40960 + (t*2+0)*2560, wn, kb, lane));
                ldsm4(bl, fragA(sb + 40960 + (t*2+1)*2560, wn, kb, lane));
                const uint32_t (*Ah)[4] = (t < 3) ? axh : ach;
                const uint32_t (*Al)[4] = (t < 3) ? axl : acl;
                #pragma unroll
                for (int mi = 0; mi < 2; ++mi)
                    #pragma unroll
                    for (int ni = 0; ni < 2; ++ni) {
                        mmaf16(acc[t][mi][ni], Ah[mi], bh[ni], bh[ni+2]);
                        mmaf16(acc[t][mi][ni], Al[mi], bh[ni], bh[ni+2]);
                        mmaf16(acc[t][mi][ni], Ah[mi], bl[ni], bl[ni+2]);
                    }
            }
        }
    };

    issue(0, 0); CPCOMMIT();
    CPWAIT0(); __syncthreads();
    #pragma unroll 1
    for (int c = 0; c < 8; ++c) {
        if (c < 7) { issue(c + 1, (c + 1) & 1); CPCOMMIT(); }
        compute(sbase + (c & 1) * PJ_BUF);
        if (c < 7) { CPWAIT0(); __syncthreads(); }
    }

    // Epilogue: fused scale*x+shift, emit q/k/v as fp16 hi/lo
    const int g = lane >> 2, tg = lane & 3;
    #pragma unroll
    for (int mi = 0; mi < 2; ++mi)
        #pragma unroll
        for (int ni = 0; ni < 2; ++ni)
            #pragma unroll
            for (int h2 = 0; h2 < 2; ++h2) {
                const int row = m0 + wm + mi*16 + g + h2*8;
                const int col = n0 + wn + ni*8 + tg*2;
                const int i0 = h2*2;
                float sc0 = acc[3][mi][ni][i0],   sc1 = acc[3][mi][ni][i0+1];
                float sh0 = acc[4][mi][ni][i0],   sh1 = acc[4][mi][ni][i0+1];
                float q0 = fmaf(sc0, acc[0][mi][ni][i0], sh0), q1 = fmaf(sc1, acc[0][mi][ni][i0+1], sh1);
                float k0 = fmaf(sc0, acc[1][mi][ni][i0], sh0), k1 = fmaf(sc1, acc[1][mi][ni][i0+1], sh1);
                float v0 = fmaf(sc0, acc[2][mi][ni][i0], sh0), v1 = fmaf(sc1, acc[2][mi][ni][i0+1], sh1);
                size_t base = (size_t)row*768 + col;
                uint32_t hi, lo;
                split2(q0, q1, hi, lo);
                *(uint32_t*)&g_qh[base] = hi;        *(uint32_t*)&g_ql[base] = lo;
                split2(k0, k1, hi, lo);
                *(uint32_t*)&g_qh[base + 256] = hi;  *(uint32_t*)&g_ql[base + 256] = lo;
                split2(v0, v1, hi, lo);
                *(uint32_t*)&g_qh[base + 512] = hi;  *(uint32_t*)&g_ql[base + 512] = lo;
            }
}

// ---------------------------------------------------------------------------
// Kernel 2: attention via mma.sync split-fp16. One CTA per (seq, head),
// 256 threads (8 warps). QK^T 3-term, softmax fp32, SV 3-term with
// ldmatrix.trans on V.
// smem: QH 0, QL 10240, KH 20480, KL 30720, VH 40960, VL 51200,
//       S fp32 61440 (128x132), SH 129024 (128x272B), SL 163840 -> 198656
// ---------------------------------------------------------------------------
#define A_S   61440
#define A_SH  129024
#define A_SL  163840
#define SSTR  272
#define ATTN_SMEM 198656

__global__ __launch_bounds__(256, 1) void attn_kernel()
{
    const int bid  = blockIdx.x;
    const int nseq = bid >> 3;
    const int h    = bid & 7;
    const int t0   = nseq * SEQ;
    const int tid  = threadIdx.x;
    const int wid  = tid >> 5, lane = tid & 31;
    const uint32_t sbase = smem_u32(smraw);
    float* ss = (float*)(smraw + A_S);

    // Load Q,K,V hi/lo tiles: 6 tensors x 128 rows x 4 segs
    #pragma unroll
    for (int i = 0; i < 12; ++i) {
        int task = tid + i*256;
        int tensor = task >> 9;            // 0..5
        int within = task & 511;
        int row = within >> 2, seg = within & 3;
        const __half* src = ((tensor & 1) ? g_ql : g_qh)
            + (size_t)(t0 + row)*768 + (tensor >> 1)*256 + h*EDIM + seg*8;
        *(uint4*)(smraw + tensor*10240 + row*RSTR + seg*16) = *(const uint4*)src;
    }
    __syncthreads();

    // --- S = Q K^T / sqrt(32): warp grid 4x2 (wm 32, wn 64)
    {
        const int wm = (wid >> 1) * 32;
        const int wn = (wid & 1) * 64;
        float acc[2][8][4] = {};
        #pragma unroll
        for (int kb = 0; kb < 2; ++kb) {
            uint32_t aqh[2][4], aql[2][4];
            #pragma unroll
            for (int mi = 0; mi < 2; ++mi) {
                ldsm4(aqh[mi], fragA(sbase,         wm + mi*16, kb, lane));
                ldsm4(aql[mi], fragA(sbase + 10240, wm + mi*16, kb, lane));
            }
            #pragma unroll
            for (int nb = 0; nb < 4; ++nb) {
                uint32_t bkh[4], bkl[4];
                ldsm4(bkh, fragA(sbase + 20480, wn + nb*16, kb, lane));
                ldsm4(bkl, fragA(sbase + 30720, wn + nb*16, kb, lane));
                #pragma unroll
                for (int mi = 0; mi < 2; ++mi)
                    #pragma unroll
                    for (int j = 0; j < 2; ++j) {
                        float* d = acc[mi][nb*2 + j];
                        mmaf16(d, aqh[mi], bkh[j], bkh[j+2]);
                        mmaf16(d, aql[mi], bkh[j], bkh[j+2]);
                        mmaf16(d, aqh[mi], bkl[j], bkl[j+2]);
                    }
            }
        }
        const float scl = 0.17677669529663688f;  // 1/sqrt(32)
        const int g = lane >> 2, tg = lane & 3;
        #pragma unroll
        for (int mi = 0; mi < 2; ++mi)
            #pragma unroll
            for (int ni = 0; ni < 8; ++ni)
                #pragma unroll
                for (int h2 = 0; h2 < 2; ++h2) {
                    int row = wm + mi*16 + g + h2*8;
                    int col = wn + ni*8 + tg*2;
                    *(float2*)&ss[row*132 + col] =
                        make_float2(acc[mi][ni][h2*2]*scl, acc[mi][ni][h2*2+1]*scl);
                }
    }
    __syncthreads();

    // --- softmax rows, write probabilities as fp16 hi/lo
    for (int r = wid; r < SEQ; r += 8) {
        float* row = ss + r*132;
        float v0 = row[lane], v1 = row[lane+32], v2 = row[lane+64], v3 = row[lane+96];
        float mx = fmaxf(fmaxf(v0, v1), fmaxf(v2, v3));
        #pragma unroll
        for (int o = 16; o > 0; o >>= 1) mx = fmaxf(mx, __shfl_xor_sync(0xffffffffu, mx, o));
        float e0 = __expf(v0 - mx), e1 = __expf(v1 - mx), e2 = __expf(v2 - mx), e3 = __expf(v3 - mx);
        float sum = e0 + e1 + e2 + e3;
        #pragma unroll
        for (int o = 16; o > 0; o >>= 1) sum += __shfl_xor_sync(0xffffffffu, sum, o);
        const float inv = 1.0f / sum;
        float p[4] = { e0*inv, e1*inv, e2*inv, e3*inv };
        #pragma unroll
        for (int j = 0; j < 4; ++j) {
            int col = lane + j*32;
            __half hp = __float2half_rn(p[j]);
            __half lp = __float2half_rn(p[j] - __half2float(hp));
            *(__half*)(smraw + A_SH + r*SSTR + col*2) = hp;
            *(__half*)(smraw + A_SL + r*SSTR + col*2) = lp;
        }
    }
    __syncthreads();

    // --- O = S V: warp tile 16 rows x 32 cols, K=128
    {
        float acc[4][4] = {};
        const int wm2 = wid * 16;
        #pragma unroll 2
        for (int kk = 0; kk < 8; ++kk) {
            uint32_t ash[4], asl[4];
            uint32_t aaddr = sbase + A_SH + (uint32_t)(wm2 + (lane & 15))*SSTR
                           + (uint32_t)(kk*32 + ((lane >> 4) << 4));
            ldsm4(ash, aaddr);
            ldsm4(asl, aaddr + (A_SL - A_SH));
            uint32_t bh[2][4], bl[2][4];
            uint32_t vrow = (uint32_t)(kk*16 + (lane & 15))*RSTR + (uint32_t)((lane >> 4) << 4);
            ldsm4t(bh[0], sbase + 40960 + vrow);
            ldsm4t(bh[1], sbase + 40960 + vrow + 32);
            ldsm4t(bl[0], sbase + 51200 + vrow);
            ldsm4t(bl[1], sbase + 51200 + vrow + 32);
            #pragma unroll
            for (int nb = 0; nb < 2; ++nb)
                #pragma unroll
                for (int j = 0; j < 2; ++j) {
                    float* d = acc[nb*2 + j];
                    mmaf16(d, ash, bh[nb][j*2], bh[nb][j*2+1]);
                    mmaf16(d, asl, bh[nb][j*2], bh[nb][j*2+1]);
                    mmaf16(d, ash, bl[nb][j*2], bl[nb][j*2+1]);
                }
        }
        const int g = lane >> 2, tg = lane & 3;
        #pragma unroll
        for (int ni = 0; ni < 4; ++ni)
            #pragma unroll
            for (int h2 = 0; h2 < 2; ++h2) {
                int row = t0 + wm2 + g + h2*8;
                int col = h*EDIM + ni*8 + tg*2;
                uint32_t hi, lo;
                split2(acc[ni][h2*2], acc[ni][h2*2+1], hi, lo);
                *(uint32_t*)&g_oh[(size_t)row*CCH + col] = hi;
                *(uint32_t*)&g_ol[(size_t)row*CCH + col] = lo;
            }
    }
}

// ---------------------------------------------------------------------------
// Kernel 3: out = O @ Wout^T. CTA 128x64, cp.async double-buffered.
// buffer: AH 0 (128x80), AL 10240, BH 20480 (64x80), BL 25600 -> 30720
// ---------------------------------------------------------------------------
#define OU_BUF 30720
#define OUT_SMEM (2*OU_BUF)

__global__ __launch_bounds__(256, 1) void out_kernel(float* __restrict__ out)
{
    const int tid = threadIdx.x;
    const int wid = tid >> 5, lane = tid & 31;
    const int n0 = blockIdx.x * 64;
    const int m0 = blockIdx.y * 128;
    const uint32_t sbase = smem_u32(smraw);

    auto issue = [&](int c, int b) {
        const int k0 = c * 32;
        const uint32_t sb = sbase + b * OU_BUF;
        #pragma unroll
        for (int i = 0; i < 4; ++i) {
            int task = tid + i*256;
            int tensor = task >> 9;            // 0..1
            int within = task & 511;
            int row = within >> 2, seg = within & 3;
            const __half* src = (tensor ? g_ol : g_oh) + (size_t)(m0 + row)*CCH + k0 + seg*8;
            CP16(sb + tensor*10240 + row*RSTR + seg*16, src);
        }
        #pragma unroll
        for (int i = 0; i < 2; ++i) {
            int task = tid + i*256;
            int tensor = task >> 8;            // 0..1
            int within = task & 255;
            int row = within >> 2, seg = within & 3;
            const __half* src = (tensor ? g_wl : g_wh) + (size_t)5*65536 + (size_t)(n0 + row)*CCH + k0 + seg*8;
            CP16(sb + 20480 + tensor*5120 + row*RSTR + seg*16, src);
        }
    };

    float acc[2][4][4] = {};
    const int wm = (wid >> 1) * 32;
    const int wn = (wid & 1) * 32;

    auto compute = [&](uint32_t sb) {
        #pragma unroll
        for (int kb = 0; kb < 2; ++kb) {
            uint32_t ah[2][4], al[2][4];
            #pragma unroll
            for (int mi = 0; mi < 2; ++mi) {
                ldsm4(ah[mi], fragA(sb,         wm + mi*16, kb, lane));
                ldsm4(al[mi], fragA(sb + 10240, wm + mi*16, kb, lane));
            }
            uint32_t bh0[4], bh1[4], bl0[4], bl1[4];
            ldsm4(bh0, fragA(sb + 20480, wn,      kb, lane));
            ldsm4(bh1, fragA(sb + 20480, wn + 16, kb, lane));
            ldsm4(bl0, fragA(sb + 25600, wn,      kb, lane));
            ldsm4(bl1, fragA(sb + 25600, wn + 16, kb, lane));
            #pragma unroll
            for (int mi = 0; mi < 2; ++mi)
                #pragma unroll
                for (int ni = 0; ni < 4; ++ni) {
                    const uint32_t* bh = (ni < 2) ? bh0 : bh1;
                    const uint32_t* bl = (ni < 2) ? bl0 : bl1;
                    int j = ni & 1;
                    mmaf16(acc[mi][ni], ah[mi], bh[j], bh[j+2]);
                    mmaf16(acc[mi][ni], al[mi], bh[j], bh[j+2]);
                    mmaf16(acc[mi][ni], ah[mi], bl[j], bl[j+2]);
                }
        }
    };

    issue(0, 0); CPCOMMIT();
    CPWAIT0(); __syncthreads();
    #pragma unroll 1
    for (int c = 0; c < 8; ++c) {
        if (c < 7) { issue(c + 1, (c + 1) & 1); CPCOMMIT(); }
        compute(sbase + (c & 1) * OU_BUF);
        if (c < 7) { CPWAIT0(); __syncthreads(); }
    }

    const int g = lane >> 2, tg = lane & 3;
    #pragma unroll
    for (int mi = 0; mi < 2; ++mi)
        #pragma unroll
        for (int ni = 0; ni < 4; ++ni)
            #pragma unroll
            for (int h2 = 0; h2 < 2; ++h2) {
                const int row = m0 + wm + mi*16 + g + h2*8;
                const int col = n0 + wn + ni*8 + tg*2;
                *(float2*)&out[(size_t)row*CCH + col] =
                    make_float2(acc[mi][ni][h2*2], acc[mi][ni][h2*2+1]);
            }
}

// ---------------------------------------------------------------------------
extern "C" void kernel_launch(void* const* d_in, const int* in_sizes, int n_in,
                              void* d_out, int out_size)
{
    (void)in_sizes; (void)n_in; (void)out_size;
    const float* X      = (const float*)d_in[0];
    const float* CTX    = (const float*)d_in[1];
    const float* Wq     = (const float*)d_in[2];
    const float* Wkv    = (const float*)d_in[3];
    const float* Wout   = (const float*)d_in[4];
    const float* Wscale = (const float*)d_in[5];
    const float* Wshift = (const float*)d_in[6];
    float* out = (float*)d_out;

    // device-symbol addresses (host side)
    __half *xh, *xl, *ch, *cl, *wh, *wl;
    cudaGetSymbolAddress((void**)&xh, g_xh);
    cudaGetSymbolAddress((void**)&xl, g_xl);
    cudaGetSymbolAddress((void**)&ch, g_ch);
    cudaGetSymbolAddress((void**)&cl, g_cl);
    cudaGetSymbolAddress((void**)&wh, g_wh);
    cudaGetSymbolAddress((void**)&wl, g_wl);

    cudaFuncSetAttribute(proj_kernel, cudaFuncAttributeMaxDynamicSharedMemorySize, PROJ_SMEM);
    cudaFuncSetAttribute(attn_kernel, cudaFuncAttributeMaxDynamicSharedMemorySize, ATTN_SMEM);
    cudaFuncSetAttribute(out_kernel,  cudaFuncAttributeMaxDynamicSharedMemorySize, OUT_SMEM);

    // convert pass
    conv_kernel<<<4096, 256>>>((const float4*)X,   (uint2*)xh, (uint2*)xl, TOK*64);
    conv_kernel<<<4096, 256>>>((const float4*)CTX, (uint2*)ch, (uint2*)cl, TOK*64);
    conv_kernel<<<64, 256>>>((const float4*)Wq,     (uint2*)(wh + 0*65536),      (uint2*)(wl + 0*65536),      16384);
    conv_kernel<<<128, 256>>>((const float4*)Wkv,   (uint2*)(wh + 1*65536),      (uint2*)(wl + 1*65536),      32768);
    conv_kernel<<<64, 256>>>((const float4*)Wscale, (uint2*)(wh + 3*65536),      (uint2*)(wl + 3*65536),      16384);
    conv_kernel<<<64, 256>>>((const float4*)Wshift, (uint2*)(wh + 4*65536),      (uint2*)(wl + 4*65536),      16384);
    conv_kernel<<<64, 256>>>((const float4*)Wout,   (uint2*)(wh + 5*65536),      (uint2*)(wl + 5*65536),      16384);

    proj_kernel<<<dim3(8, 1024), 256, PROJ_SMEM>>>();
    attn_kernel<<<NSEQ*NHEADS, 256, ATTN_SMEM>>>();
    out_kernel<<<dim3(4, 1024), 256, OUT_SMEM>>>(out);
}

// round 9
// speedup vs baseline: 2.2513x; 1.0832x over previous
#include <cuda_runtime.h>
#include <cuda_fp16.h>
#include <cstdint>

#define TOK   131072
#define CCH   256
#define SEQ   128
#define NSEQ  1024
#define NHEADS 8
#define EDIM  32

// fp16 hi/lo global buffers (split precision: x = hi + lo)
__device__ __half g_xh[(size_t)TOK * 256], g_xl[(size_t)TOK * 256];
__device__ __half g_ch[(size_t)TOK * 256], g_cl[(size_t)TOK * 256];
__device__ __half g_wh[6 * 65536], g_wl[6 * 65536];   // Wq, Wk, Wv, Wscale, Wshift, Wout
__device__ __half g_qh[(size_t)TOK * 768], g_ql[(size_t)TOK * 768];  // q|k|v post scale/shift
__device__ __half g_oh[(size_t)TOK * 256], g_ol[(size_t)TOK * 256];  // attention out

extern __shared__ __align__(16) char smraw[];

// ---------------- helpers ----------------
__device__ __forceinline__ uint32_t smem_u32(const void* p) {
    uint32_t a;
    asm("{ .reg .u64 t; cvta.to.shared.u64 t, %1; cvt.u32.u64 %0, t; }" : "=r"(a) : "l"(p));
    return a;
}
__device__ __forceinline__ void ldsm4(uint32_t* r, uint32_t a) {
    asm volatile("ldmatrix.sync.aligned.m8n8.x4.shared.b16 {%0,%1,%2,%3}, [%4];"
        : "=r"(r[0]), "=r"(r[1]), "=r"(r[2]), "=r"(r[3]) : "r"(a));
}
__device__ __forceinline__ void ldsm4t(uint32_t* r, uint32_t a) {
    asm volatile("ldmatrix.sync.aligned.m8n8.x4.trans.shared.b16 {%0,%1,%2,%3}, [%4];"
        : "=r"(r[0]), "=r"(r[1]), "=r"(r[2]), "=r"(r[3]) : "r"(a));
}
__device__ __forceinline__ void mmaf16(float* d, const uint32_t* a, uint32_t b0, uint32_t b1) {
    asm volatile("mma.sync.aligned.m16n8k16.row.col.f32.f16.f16.f32 "
        "{%0,%1,%2,%3}, {%4,%5,%6,%7}, {%8,%9}, {%0,%1,%2,%3};"
        : "+f"(d[0]), "+f"(d[1]), "+f"(d[2]), "+f"(d[3])
        : "r"(a[0]), "r"(a[1]), "r"(a[2]), "r"(a[3]), "r"(b0), "r"(b1));
}
#define CP16(s, g) asm volatile("cp.async.cg.shared.global [%0], [%1], 16;" :: "r"(s), "l"(g))
#define CPCOMMIT() asm volatile("cp.async.commit_group;")
#define CPWAIT0()  asm volatile("cp.async.wait_group 0;")

struct H4 { uint2 hi, lo; };
__device__ __forceinline__ H4 splitf4(float4 v) {
    __half2 h0 = __floats2half2_rn(v.x, v.y);
    __half2 h1 = __floats2half2_rn(v.z, v.w);
    float2 f0 = __half22float2(h0), f1 = __half22float2(h1);
    __half2 l0 = __floats2half2_rn(v.x - f0.x, v.y - f0.y);
    __half2 l1 = __floats2half2_rn(v.z - f1.x, v.w - f1.y);
    H4 r;
    r.hi.x = *(uint32_t*)&h0; r.hi.y = *(uint32_t*)&h1;
    r.lo.x = *(uint32_t*)&l0; r.lo.y = *(uint32_t*)&l1;
    return r;
}
__device__ __forceinline__ void split2(float a, float b, uint32_t& hi, uint32_t& lo) {
    __half2 h = __floats2half2_rn(a, b);
    float2 f = __half22float2(h);
    __half2 l = __floats2half2_rn(a - f.x, b - f.y);
    hi = *(uint32_t*)&h; lo = *(uint32_t*)&l;
}

#define RSTR 80   // 32 halves (64B) padded to 80B -> conflict-free ldmatrix
__device__ __forceinline__ uint32_t fragA(uint32_t matbase, int row0, int kb, int lane) {
    return matbase + (uint32_t)(row0 + (lane & 15)) * RSTR
                   + (uint32_t)(kb * 32 + ((lane >> 4) << 4));
}

// ---------------------------------------------------------------------------
// Kernel 0: fp32 -> fp16 hi/lo convert (memory bound)
// ---------------------------------------------------------------------------
__global__ __launch_bounds__(256) void conv_kernel(
    const float4* __restrict__ s, uint2* __restrict__ dh, uint2* __restrict__ dl, int n)
{
    for (int i = blockIdx.x * blockDim.x + threadIdx.x; i < n; i += gridDim.x * blockDim.x) {
        H4 h = splitf4(s[i]);
        dh[i] = h.hi; dl[i] = h.lo;
    }
}

// ---------------------------------------------------------------------------
// Kernel 1: fused projection. CTA 128 tokens x 32 channels, 512 threads
// (16 warps: 8 in M x 2 in N, warp tile 16x16), cp.async double-buffered.
// buffer layout: XH 0, XL 10240, CH 20480, CL 30720, W(t,hl) 40960+(t*2+hl)*2560
// ---------------------------------------------------------------------------
#define PJ_BUF 66560
#define PROJ_SMEM (2*PJ_BUF)

__global__ __launch_bounds__(512, 1) void proj_kernel()
{
    const int tid = threadIdx.x;
    const int wid = tid >> 5, lane = tid & 31;
    const int n0 = blockIdx.x * 32;
    const int m0 = blockIdx.y * 128;
    const uint32_t sbase = smem_u32(smraw);

    auto issue = [&](int c, int b) {
        const int k0 = c * 32;
        const uint32_t sb = sbase + b * PJ_BUF;
        {   // X/CTX hi+lo: 512 tasks, one per thread per tensor
            int row = tid >> 2, seg = tid & 3;
            uint32_t so = (uint32_t)(row*RSTR + seg*16);
            size_t gi = (size_t)(m0 + row)*CCH + k0 + seg*8;
            CP16(sb + so,         g_xh + gi);
            CP16(sb + 10240 + so, g_xl + gi);
            CP16(sb + 20480 + so, g_ch + gi);
            CP16(sb + 30720 + so, g_cl + gi);
        }
        #pragma unroll
        for (int i = 0; i < 3; ++i) {       // weights: 1280 tasks
            int task = tid + i*512;
            if (task < 1280) {
                int tile = task >> 7;       // 0..9
                int r = (task & 127) >> 2, seg = task & 3;
                int t = tile >> 1, hl = tile & 1;
                uint32_t so = (uint32_t)(40960 + tile*2560 + r*RSTR + seg*16);
                const __half* src = (hl ? g_wl : g_wh) + (size_t)t*65536 + (size_t)(n0 + r)*CCH + k0 + seg*8;
                CP16(sb + so, src);
            }
        }
    };

    float acc[5][2][4] = {};
    const int wm = (wid >> 1) * 16;
    const int wn = (wid & 1) * 16;

    auto compute = [&](uint32_t sb) {
        #pragma unroll
        for (int kb = 0; kb < 2; ++kb) {
            uint32_t axh[4], axl[4], ach[4], acl[4];
            ldsm4(axh, fragA(sb,         wm, kb, lane));
            ldsm4(axl, fragA(sb + 10240, wm, kb, lane));
            ldsm4(ach, fragA(sb + 20480, wm, kb, lane));
            ldsm4(acl, fragA(sb + 30720, wm, kb, lane));
            #pragma unroll
            for (int t = 0; t < 5; ++t) {
                uint32_t bh[4], bl[4];
                ldsm4(bh, fragA(sb + 40960 + (t*2+0)*2560, wn, kb, lane));
                ldsm4(bl, fragA(sb + 40960 + (t*2+1)*2560, wn, kb, lane));
                const uint32_t* Ah = (t < 3) ? axh : ach;
                const uint32_t* Al = (t < 3) ? axl : acl;
                #pragma unroll
                for (int ni = 0; ni < 2; ++ni) {
                    mmaf16(acc[t][ni], Ah, bh[ni], bh[ni+2]);
                    mmaf16(acc[t][ni], Al, bh[ni], bh[ni+2]);
                    mmaf16(acc[t][ni], Ah, bl[ni], bl[ni+2]);
                }
            }
        }
    };

    issue(0, 0); CPCOMMIT();
    CPWAIT0(); __syncthreads();
    #pragma unroll 1
    for (int c = 0; c < 8; ++c) {
        if (c < 7) { issue(c + 1, (c + 1) & 1); CPCOMMIT(); }
        compute(sbase + (c & 1) * PJ_BUF);
        if (c < 7) { CPWAIT0(); __syncthreads(); }
    }

    // Epilogue: fused scale*x+shift, emit q/k/v as fp16 hi/lo
    const int g = lane >> 2, tg = lane & 3;
    #pragma unroll
    for (int ni = 0; ni < 2; ++ni)
        #pragma unroll
        for (int h2 = 0; h2 < 2; ++h2) {
            const int row = m0 + wm + g + h2*8;
            const int col = n0 + wn + ni*8 + tg*2;
            const int i0 = h2*2;
            float sc0 = acc[3][ni][i0],   sc1 = acc[3][ni][i0+1];
            float sh0 = acc[4][ni][i0],   sh1 = acc[4][ni][i0+1];
            float q0 = fmaf(sc0, acc[0][ni][i0], sh0), q1 = fmaf(sc1, acc[0][ni][i0+1], sh1);
            float k0 = fmaf(sc0, acc[1][ni][i0], sh0), k1 = fmaf(sc1, acc[1][ni][i0+1], sh1);
            float v0 = fmaf(sc0, acc[2][ni][i0], sh0), v1 = fmaf(sc1, acc[2][ni][i0+1], sh1);
            size_t base = (size_t)row*768 + col;
            uint32_t hi, lo;
            split2(q0, q1, hi, lo);
            *(uint32_t*)&g_qh[base] = hi;        *(uint32_t*)&g_ql[base] = lo;
            split2(k0, k1, hi, lo);
            *(uint32_t*)&g_qh[base + 256] = hi;  *(uint32_t*)&g_ql[base + 256] = lo;
            split2(v0, v1, hi, lo);
            *(uint32_t*)&g_qh[base + 512] = hi;  *(uint32_t*)&g_ql[base + 512] = lo;
        }
}

// ---------------------------------------------------------------------------
// Kernel 2: attention, 512 threads (16 warps). QK^T warp grid 4x4 (32x32),
// softmax fp32, SV warp grid 8x2 (16x16) with ldmatrix.trans on V.
// smem: QH 0, QL 10240, KH 20480, KL 30720, VH 40960, VL 51200,
//       S fp32 61440 (128x132), SH 129024 (128x272B), SL 163840 -> 198656
// ---------------------------------------------------------------------------
#define A_S   61440
#define A_SH  129024
#define A_SL  163840
#define SSTR  272
#define ATTN_SMEM 198656

__global__ __launch_bounds__(512, 1) void attn_kernel()
{
    const int bid  = blockIdx.x;
    const int nseq = bid >> 3;
    const int h    = bid & 7;
    const int t0   = nseq * SEQ;
    const int tid  = threadIdx.x;
    const int wid  = tid >> 5, lane = tid & 31;
    const uint32_t sbase = smem_u32(smraw);
    float* ss = (float*)(smraw + A_S);

    // Load Q,K,V hi/lo tiles: 6 tensors x 128 rows x 4 segs = 3072 uint4
    #pragma unroll
    for (int i = 0; i < 6; ++i) {
        int task = tid + i*512;
        int tensor = task >> 9;            // 0..5
        int within = task & 511;
        int row = within >> 2, seg = within & 3;
        const __half* src = ((tensor & 1) ? g_ql : g_qh)
            + (size_t)(t0 + row)*768 + (tensor >> 1)*256 + h*EDIM + seg*8;
        *(uint4*)(smraw + tensor*10240 + row*RSTR + seg*16) = *(const uint4*)src;
    }
    __syncthreads();

    // --- S = Q K^T / sqrt(32): warp grid 4m x 4n (tile 32x32)
    {
        const int wm = (wid >> 2) * 32;
        const int wn = (wid & 3) * 32;
        float acc[2][4][4] = {};
        #pragma unroll
        for (int kb = 0; kb < 2; ++kb) {
            uint32_t aqh[2][4], aql[2][4];
            #pragma unroll
            for (int mi = 0; mi < 2; ++mi) {
                ldsm4(aqh[mi], fragA(sbase,         wm + mi*16, kb, lane));
                ldsm4(aql[mi], fragA(sbase + 10240, wm + mi*16, kb, lane));
            }
            #pragma unroll
            for (int nb = 0; nb < 2; ++nb) {
                uint32_t bkh[4], bkl[4];
                ldsm4(bkh, fragA(sbase + 20480, wn + nb*16, kb, lane));
                ldsm4(bkl, fragA(sbase + 30720, wn + nb*16, kb, lane));
                #pragma unroll
                for (int mi = 0; mi < 2; ++mi)
                    #pragma unroll
                    for (int j = 0; j < 2; ++j) {
                        float* d = acc[mi][nb*2 + j];
                        mmaf16(d, aqh[mi], bkh[j], bkh[j+2]);
                        mmaf16(d, aql[mi], bkh[j], bkh[j+2]);
                        mmaf16(d, aqh[mi], bkl[j], bkl[j+2]);
                    }
            }
        }
        const float scl = 0.17677669529663688f;  // 1/sqrt(32)
        const int g = lane >> 2, tg = lane & 3;
        #pragma unroll
        for (int mi = 0; mi < 2; ++mi)
            #pragma unroll
            for (int ni = 0; ni < 4; ++ni)
                #pragma unroll
                for (int h2 = 0; h2 < 2; ++h2) {
                    int row = wm + mi*16 + g + h2*8;
                    int col = wn + ni*8 + tg*2;
                    *(float2*)&ss[row*132 + col] =
                        make_float2(acc[mi][ni][h2*2]*scl, acc[mi][ni][h2*2+1]*scl);
                }
    }
    __syncthreads();

    // --- softmax rows, write probabilities as fp16 hi/lo
    for (int r = wid; r < SEQ; r += 16) {
        float* row = ss + r*132;
        float v0 = row[lane], v1 = row[lane+32], v2 = row[lane+64], v3 = row[lane+96];
        float mx = fmaxf(fmaxf(v0, v1), fmaxf(v2, v3));
        #pragma unroll
        for (int o = 16; o > 0; o >>= 1) mx = fmaxf(mx, __shfl_xor_sync(0xffffffffu, mx, o));
        float e0 = __expf(v0 - mx), e1 = __expf(v1 - mx), e2 = __expf(v2 - mx), e3 = __expf(v3 - mx);
        float sum = e0 + e1 + e2 + e3;
        #pragma unroll
        for (int o = 16; o > 0; o >>= 1) sum += __shfl_xor_sync(0xffffffffu, sum, o);
        const float inv = 1.0f / sum;
        float p[4] = { e0*inv, e1*inv, e2*inv, e3*inv };
        #pragma unroll
        for (int j = 0; j < 4; ++j) {
            int col = lane + j*32;
            __half hp = __float2half_rn(p[j]);
            __half lp = __float2half_rn(p[j] - __half2float(hp));
            *(__half*)(smraw + A_SH + r*SSTR + col*2) = hp;
            *(__half*)(smraw + A_SL + r*SSTR + col*2) = lp;
        }
    }
    __syncthreads();

    // --- O = S V: warp grid 8m x 2n (tile 16x16), K=128
    {
        float acc[2][4] = {};
        const int wm2 = (wid >> 1) * 16;
        const int wnv = (wid & 1) * 16;
        #pragma unroll 2
        for (int kk = 0; kk < 8; ++kk) {
            uint32_t ash[4], asl[4];
            uint32_t aaddr = sbase + A_SH + (uint32_t)(wm2 + (lane & 15))*SSTR
                           + (uint32_t)(kk*32 + ((lane >> 4) << 4));
            ldsm4(ash, aaddr);
            ldsm4(asl, aaddr + (A_SL - A_SH));
            uint32_t bh[4], bl[4];
            uint32_t vrow = (uint32_t)(kk*16 + (lane & 15))*RSTR
                          + (uint32_t)((lane >> 4) << 4) + (uint32_t)wnv*2;
            ldsm4t(bh, sbase + 40960 + vrow);
            ldsm4t(bl, sbase + 51200 + vrow);
            #pragma unroll
            for (int j = 0; j < 2; ++j) {
                float* d = acc[j];
                mmaf16(d, ash, bh[j*2], bh[j*2+1]);
                mmaf16(d, asl, bh[j*2], bh[j*2+1]);
                mmaf16(d, ash, bl[j*2], bl[j*2+1]);
            }
        }
        const int g = lane >> 2, tg = lane & 3;
        #pragma unroll
        for (int j = 0; j < 2; ++j)
            #pragma unroll
            for (int h2 = 0; h2 < 2; ++h2) {
                int row = t0 + wm2 + g + h2*8;
                int col = h*EDIM + wnv + j*8 + tg*2;
                uint32_t hi, lo;
                split2(acc[j][h2*2], acc[j][h2*2+1], hi, lo);
                *(uint32_t*)&g_oh[(size_t)row*CCH + col] = hi;
                *(uint32_t*)&g_ol[(size_t)row*CCH + col] = lo;
            }
    }
}

// ---------------------------------------------------------------------------
// Kernel 3: out = O @ Wout^T. CTA 128x64, 512 threads (8m x 2n warps,
// warp tile 16x32), cp.async double-buffered.
// buffer: AH 0 (128x80), AL 10240, BH 20480 (64x80), BL 25600 -> 30720
// ---------------------------------------------------------------------------
#define OU_BUF 30720
#define OUT_SMEM (2*OU_BUF)

__global__ __launch_bounds__(512, 1) void out_kernel(float* __restrict__ out)
{
    const int tid = threadIdx.x;
    const int wid = tid >> 5, lane = tid & 31;
    const int n0 = blockIdx.x * 64;
    const int m0 = blockIdx.y * 128;
    const uint32_t sbase = smem_u32(smraw);

    auto issue = [&](int c, int b) {
        const int k0 = c * 32;
        const uint32_t sb = sbase + b * OU_BUF;
        #pragma unroll
        for (int i = 0; i < 2; ++i) {           // A: 1024 tasks
            int task = tid + i*512;
            int tensor = task >> 9;
            int within = task & 511;
            int row = within >> 2, seg = within & 3;
            const __half* src = (tensor ? g_ol : g_oh) + (size_t)(m0 + row)*CCH + k0 + seg*8;
            CP16(sb + tensor*10240 + row*RSTR + seg*16, src);
        }
        if (tid < 512) {                        // B: 512 tasks
            int tensor = tid >> 8;
            int within = tid & 255;
            int row = within >> 2, seg = within & 3;
            const __half* src = (tensor ? g_wl : g_wh) + (size_t)5*65536 + (size_t)(n0 + row)*CCH + k0 + seg*8;
            CP16(sb + 20480 + tensor*5120 + row*RSTR + seg*16, src);
        }
    };

    float acc[4][4] = {};
    const int wm = (wid >> 1) * 16;
    const int wn = (wid & 1) * 32;

    auto compute = [&](uint32_t sb) {
        #pragma unroll
        for (int kb = 0; kb < 2; ++kb) {
            uint32_t ah[4], al[4];
            ldsm4(ah, fragA(sb,         wm, kb, lane));
            ldsm4(al, fragA(sb + 10240, wm, kb, lane));
            uint32_t bh0[4], bh1[4], bl0[4], bl1[4];
            ldsm4(bh0, fragA(sb + 20480, wn,      kb, lane));
            ldsm4(bh1, fragA(sb + 20480, wn + 16, kb, lane));
            ldsm4(bl0, fragA(sb + 25600, wn,      kb, lane));
            ldsm4(bl1, fragA(sb + 25600, wn + 16, kb, lane));
            #pragma unroll
            for (int ni = 0; ni < 4; ++ni) {
                const uint32_t* bh = (ni < 2) ? bh0 : bh1;
                const uint32_t* bl = (ni < 2) ? bl0 : bl1;
                int j = ni & 1;
                mmaf16(acc[ni], ah, bh[j], bh[j+2]);
                mmaf16(acc[ni], al, bh[j], bh[j+2]);
                mmaf16(acc[ni], ah, bl[j], bl[j+2]);
            }
        }
    };

    issue(0, 0); CPCOMMIT();
    CPWAIT0(); __syncthreads();
    #pragma unroll 1
    for (int c = 0; c < 8; ++c) {
        if (c < 7) { issue(c + 1, (c + 1) & 1); CPCOMMIT(); }
        compute(sbase + (c & 1) * OU_BUF);
        if (c < 7) { CPWAIT0(); __syncthreads(); }
    }

    const int g = lane >> 2, tg = lane & 3;
    #pragma unroll
    for (int ni = 0; ni < 4; ++ni)
        #pragma unroll
        for (int h2 = 0; h2 < 2; ++h2) {
            const int row = m0 + wm + g + h2*8;
            const int col = n0 + wn + ni*8 + tg*2;
            *(float2*)&out[(size_t)row*CCH + col] =
                make_float2(acc[ni][h2*2], acc[ni][h2*2+1]);
        }
}

// ---------------------------------------------------------------------------
extern "C" void kernel_launch(void* const* d_in, const int* in_sizes, int n_in,
                              void* d_out, int out_size)
{
    (void)in_sizes; (void)n_in; (void)out_size;
    const float* X      = (const float*)d_in[0];
    const float* CTX    = (const float*)d_in[1];
    const float* Wq     = (const float*)d_in[2];
    const float* Wkv    = (const float*)d_in[3];
    const float* Wout   = (const float*)d_in[4];
    const float* Wscale = (const float*)d_in[5];
    const float* Wshift = (const float*)d_in[6];
    float* out = (float*)d_out;

    __half *xh, *xl, *ch, *cl, *wh, *wl;
    cudaGetSymbolAddress((void**)&xh, g_xh);
    cudaGetSymbolAddress((void**)&xl, g_xl);
    cudaGetSymbolAddress((void**)&ch, g_ch);
    cudaGetSymbolAddress((void**)&cl, g_cl);
    cudaGetSymbolAddress((void**)&wh, g_wh);
    cudaGetSymbolAddress((void**)&wl, g_wl);

    cudaFuncSetAttribute(proj_kernel, cudaFuncAttributeMaxDynamicSharedMemorySize, PROJ_SMEM);
    cudaFuncSetAttribute(attn_kernel, cudaFuncAttributeMaxDynamicSharedMemorySize, ATTN_SMEM);
    cudaFuncSetAttribute(out_kernel,  cudaFuncAttributeMaxDynamicSharedMemorySize, OUT_SMEM);

    conv_kernel<<<4096, 256>>>((const float4*)X,   (uint2*)xh, (uint2*)xl, TOK*64);
    conv_kernel<<<4096, 256>>>((const float4*)CTX, (uint2*)ch, (uint2*)cl, TOK*64);
    conv_kernel<<<64, 256>>>((const float4*)Wq,     (uint2*)(wh + 0*65536), (uint2*)(wl + 0*65536), 16384);
    conv_kernel<<<128, 256>>>((const float4*)Wkv,   (uint2*)(wh + 1*65536), (uint2*)(wl + 1*65536), 32768);
    conv_kernel<<<64, 256>>>((const float4*)Wscale, (uint2*)(wh + 3*65536), (uint2*)(wl + 3*65536), 16384);
    conv_kernel<<<64, 256>>>((const float4*)Wshift, (uint2*)(wh + 4*65536), (uint2*)(wl + 4*65536), 16384);
    conv_kernel<<<64, 256>>>((const float4*)Wout,   (uint2*)(wh + 5*65536), (uint2*)(wl + 5*65536), 16384);

    proj_kernel<<<dim3(8, 1024), 512, PROJ_SMEM>>>();
    attn_kernel<<<NSEQ*NHEADS, 512, ATTN_SMEM>>>();
    out_kernel<<<dim3(4, 1024), 512, OUT_SMEM>>>(out);
}

// round 11
// speedup vs baseline: 2.2534x; 1.0009x over previous
#include <cuda_runtime.h>
#include <cuda_fp16.h>
#include <cstdint>

#define TOK   131072
#define CCH   256
#define SEQ   128
#define NSEQ  1024
#define NHEADS 8
#define EDIM  32

// fp16 hi/lo global buffers (split precision: x = hi + lo)
__device__ __half g_xh[(size_t)TOK * 256], g_xl[(size_t)TOK * 256];
__device__ __half g_ch[(size_t)TOK * 256], g_cl[(size_t)TOK * 256];
__device__ __half g_wh[6 * 65536], g_wl[6 * 65536];   // Wq, Wk, Wv, Wscale, Wshift, Wout
__device__ __half g_qh[(size_t)TOK * 768], g_ql[(size_t)TOK * 768];  // q|k|v post scale/shift
__device__ __half g_oh[(size_t)TOK * 256], g_ol[(size_t)TOK * 256];  // attention out
__device__ float  g_scale[(size_t)TOK * 256], g_shift[(size_t)TOK * 256];

extern __shared__ __align__(16) char smraw[];

// ---------------- helpers ----------------
__device__ __forceinline__ uint32_t smem_u32(const void* p) {
    uint32_t a;
    asm("{ .reg .u64 t; cvta.to.shared.u64 t, %1; cvt.u32.u64 %0, t; }" : "=r"(a) : "l"(p));
    return a;
}
__device__ __forceinline__ void ldsm4(uint32_t* r, uint32_t a) {
    asm volatile("ldmatrix.sync.aligned.m8n8.x4.shared.b16 {%0,%1,%2,%3}, [%4];"
        : "=r"(r[0]), "=r"(r[1]), "=r"(r[2]), "=r"(r[3]) : "r"(a));
}
__device__ __forceinline__ void ldsm4t(uint32_t* r, uint32_t a) {
    asm volatile("ldmatrix.sync.aligned.m8n8.x4.trans.shared.b16 {%0,%1,%2,%3}, [%4];"
        : "=r"(r[0]), "=r"(r[1]), "=r"(r[2]), "=r"(r[3]) : "r"(a));
}
__device__ __forceinline__ void mmaf16(float* d, const uint32_t* a, uint32_t b0, uint32_t b1) {
    asm volatile("mma.sync.aligned.m16n8k16.row.col.f32.f16.f16.f32 "
        "{%0,%1,%2,%3}, {%4,%5,%6,%7}, {%8,%9}, {%0,%1,%2,%3};"
        : "+f"(d[0]), "+f"(d[1]), "+f"(d[2]), "+f"(d[3])
        : "r"(a[0]), "r"(a[1]), "r"(a[2]), "r"(a[3]), "r"(b0), "r"(b1));
}
#define CP16(s, g) asm volatile("cp.async.cg.shared.global [%0], [%1], 16;" :: "r"(s), "l"(g))
#define CPCOMMIT() asm volatile("cp.async.commit_group;")
#define CPWAIT0()  asm volatile("cp.async.wait_group 0;")

struct H4 { uint2 hi, lo; };
__device__ __forceinline__ H4 splitf4(float4 v) {
    __half2 h0 = __floats2half2_rn(v.x, v.y);
    __half2 h1 = __floats2half2_rn(v.z, v.w);
    float2 f0 = __half22float2(h0), f1 = __half22float2(h1);
    __half2 l0 = __floats2half2_rn(v.x - f0.x, v.y - f0.y);
    __half2 l1 = __floats2half2_rn(v.z - f1.x, v.w - f1.y);
    H4 r;
    r.hi.x = *(uint32_t*)&h0; r.hi.y = *(uint32_t*)&h1;
    r.lo.x = *(uint32_t*)&l0; r.lo.y = *(uint32_t*)&l1;
    return r;
}
__device__ __forceinline__ void split2(float a, float b, uint32_t& hi, uint32_t& lo) {
    __half2 h = __floats2half2_rn(a, b);
    float2 f = __half22float2(h);
    __half2 l = __floats2half2_rn(a - f.x, b - f.y);
    hi = *(uint32_t*)&h; lo = *(uint32_t*)&l;
}

#define RSTR 80   // 32 halves (64B) padded to 80B -> conflict-free ldmatrix
__device__ __forceinline__ uint32_t fragA(uint32_t matbase, int row0, int kb, int lane) {
    return matbase + (uint32_t)(row0 + (lane & 15)) * RSTR
                   + (uint32_t)(kb * 32 + ((lane >> 4) << 4));
}

// ---------------------------------------------------------------------------
// Kernel 0: fp32 -> fp16 hi/lo convert (memory bound)
// ---------------------------------------------------------------------------
__global__ __launch_bounds__(256) void conv_kernel(
    const float4* __restrict__ s, uint2* __restrict__ dh, uint2* __restrict__ dl, int n)
{
    for (int i = blockIdx.x * blockDim.x + threadIdx.x; i < n; i += gridDim.x * blockDim.x) {
        H4 h = splitf4(s[i]);
        dh[i] = h.hi; dl[i] = h.lo;
    }
}

// ---------------------------------------------------------------------------
// Kernel 1a: scale/shift = CTX @ {Wscale,Wshift}^T -> fp32 g_scale/g_shift.
// CTA 128 x 64, 512 threads, 16 warps (4m x 4n), warp tile 32x16 x 2 tensors.
// buffer: CH 0, CL 10240, W(t,hl) 20480 + (t*2+hl)*5120  -> 40960/buf
// ---------------------------------------------------------------------------
#define SS_BUF 40960
#define SS_SMEM (2*SS_BUF)

__global__ __launch_bounds__(512, 1) void ss_kernel()
{
    const int tid = threadIdx.x;
    const int wid = tid >> 5, lane = tid & 31;
    const int n0 = blockIdx.x * 64;
    const int m0 = blockIdx.y * 128;
    const uint32_t sbase = smem_u32(smraw);

    auto issue = [&](int c, int b) {
        const int k0 = c * 32;
        const uint32_t sb = sbase + b * SS_BUF;
        {   // A: CTX hi/lo, 512 tasks each
            int row = tid >> 2, seg = tid & 3;
            uint32_t so = (uint32_t)(row*RSTR + seg*16);
            size_t gi = (size_t)(m0 + row)*CCH + k0 + seg*8;
            CP16(sb + so,         g_ch + gi);
            CP16(sb + 10240 + so, g_cl + gi);
        }
        #pragma unroll
        for (int i = 0; i < 2; ++i) {   // B: 4 tiles x 64 rows x 4 segs = 1024 tasks
            int task = tid + i*512;
            int tile = task >> 8;       // 0..3
            int r = (task & 255) >> 2, seg = task & 3;
            int t = tile >> 1, hl = tile & 1;
            const __half* src = (hl ? g_wl : g_wh) + (size_t)(3 + t)*65536
                              + (size_t)(n0 + r)*CCH + k0 + seg*8;
            CP16(sb + 20480 + tile*5120 + r*RSTR + seg*16, src);
        }
    };

    float acc[2][2][2][4] = {};   // [tensor][mi][ni][4]
    const int wm = (wid >> 2) * 32;
    const int wn = (wid & 3) * 16;

    auto compute = [&](uint32_t sb) {
        #pragma unroll
        for (int kb = 0; kb < 2; ++kb) {
            uint32_t ah[2][4], al[2][4];
            #pragma unroll
            for (int mi = 0; mi < 2; ++mi) {
                ldsm4(ah[mi], fragA(sb,         wm + mi*16, kb, lane));
                ldsm4(al[mi], fragA(sb + 10240, wm + mi*16, kb, lane));
            }
            #pragma unroll
            for (int t = 0; t < 2; ++t) {
                uint32_t bh[4], bl[4];
                ldsm4(bh, fragA(sb + 20480 + (t*2+0)*5120, wn, kb, lane));
                ldsm4(bl, fragA(sb + 20480 + (t*2+1)*5120, wn, kb, lane));
                #pragma unroll
                for (int mi = 0; mi < 2; ++mi)
                    #pragma unroll
                    for (int ni = 0; ni < 2; ++ni) {
                        float* d = acc[t][mi][ni];
                        mmaf16(d, ah[mi], bh[ni], bh[ni+2]);
                        mmaf16(d, al[mi], bh[ni], bh[ni+2]);
                        mmaf16(d, ah[mi], bl[ni], bl[ni+2]);
                    }
            }
        }
    };

    issue(0, 0); CPCOMMIT();
    CPWAIT0(); __syncthreads();
    #pragma unroll 1
    for (int c = 0; c < 8; ++c) {
        if (c < 7) { issue(c + 1, (c + 1) & 1); CPCOMMIT(); }
        compute(sbase + (c & 1) * SS_BUF);
        if (c < 7) { CPWAIT0(); __syncthreads(); }
    }

    const int g = lane >> 2, tg = lane & 3;
    #pragma unroll
    for (int mi = 0; mi < 2; ++mi)
        #pragma unroll
        for (int ni = 0; ni < 2; ++ni)
            #pragma unroll
            for (int h2 = 0; h2 < 2; ++h2) {
                const int row = m0 + wm + mi*16 + g + h2*8;
                const int col = n0 + wn + ni*8 + tg*2;
                *(float2*)&g_scale[(size_t)row*CCH + col] =
                    make_float2(acc[0][mi][ni][h2*2], acc[0][mi][ni][h2*2+1]);
                *(float2*)&g_shift[(size_t)row*CCH + col] =
                    make_float2(acc[1][mi][ni][h2*2], acc[1][mi][ni][h2*2+1]);
            }
}

// ---------------------------------------------------------------------------
// Kernel 1b: q,k,v = X @ {Wq,Wk,Wv}^T, fused with scale*x+shift (from fp32
// g_scale/g_shift). CTA 128 x 64, 512 threads, 16 warps (4m x 4n), warp 32x16.
// buffer: XH 0, XL 10240, W(t,hl) 20480 + (t*2+hl)*5120 -> 51200/buf
// ---------------------------------------------------------------------------
#define QK_BUF 51200
#define QKV_SMEM (2*QK_BUF)

__global__ __launch_bounds__(512, 1) void qkv_kernel()
{
    const int tid = threadIdx.x;
    const int wid = tid >> 5, lane = tid & 31;
    const int n0 = blockIdx.x * 64;
    const int m0 = blockIdx.y * 128;
    const uint32_t sbase = smem_u32(smraw);

    auto issue = [&](int c, int b) {
        const int k0 = c * 32;
        const uint32_t sb = sbase + b * QK_BUF;
        {
            int row = tid >> 2, seg = tid & 3;
            uint32_t so = (uint32_t)(row*RSTR + seg*16);
            size_t gi = (size_t)(m0 + row)*CCH + k0 + seg*8;
            CP16(sb + so,         g_xh + gi);
            CP16(sb + 10240 + so, g_xl + gi);
        }
        #pragma unroll
        for (int i = 0; i < 3; ++i) {   // B: 6 tiles x 64 rows x 4 segs = 1536 tasks
            int task = tid + i*512;
            int tile = task >> 8;       // 0..5
            int r = (task & 255) >> 2, seg = task & 3;
            int t = tile >> 1, hl = tile & 1;
            const __half* src = (hl ? g_wl : g_wh) + (size_t)t*65536
                              + (size_t)(n0 + r)*CCH + k0 + seg*8;
            CP16(sb + 20480 + tile*5120 + r*RSTR + seg*16, src);
        }
    };

    float acc[3][2][2][4] = {};
    const int wm = (wid >> 2) * 32;
    const int wn = (wid & 3) * 16;

    auto compute = [&](uint32_t sb) {
        #pragma unroll
        for (int kb = 0; kb < 2; ++kb) {
            uint32_t ah[2][4], al[2][4];
            #pragma unroll
            for (int mi = 0; mi < 2; ++mi) {
                ldsm4(ah[mi], fragA(sb,         wm + mi*16, kb, lane));
                ldsm4(al[mi], fragA(sb + 10240, wm + mi*16, kb, lane));
            }
            #pragma unroll
            for (int t = 0; t < 3; ++t) {
                uint32_t bh[4], bl[4];
                ldsm4(bh, fragA(sb + 20480 + (t*2+0)*5120, wn, kb, lane));
                ldsm4(bl, fragA(sb + 20480 + (t*2+1)*5120, wn, kb, lane));
                #pragma unroll
                for (int mi = 0; mi < 2; ++mi)
                    #pragma unroll
                    for (int ni = 0; ni < 2; ++ni) {
                        float* d = acc[t][mi][ni];
                        mmaf16(d, ah[mi], bh[ni], bh[ni+2]);
                        mmaf16(d, al[mi], bh[ni], bh[ni+2]);
                        mmaf16(d, ah[mi], bl[ni], bl[ni+2]);
                    }
            }
        }
    };

    issue(0, 0); CPCOMMIT();
    CPWAIT0(); __syncthreads();
    #pragma unroll 1
    for (int c = 0; c < 8; ++c) {
        if (c < 7) { issue(c + 1, (c + 1) & 1); CPCOMMIT(); }
        compute(sbase + (c & 1) * QK_BUF);
        if (c < 7) { CPWAIT0(); __syncthreads(); }
    }

    // Epilogue: fused scale*x+shift (fp32 from global), emit q/k/v as fp16 hi/lo
    const int g = lane >> 2, tg = lane & 3;
    #pragma unroll
    for (int mi = 0; mi < 2; ++mi)
        #pragma unroll
        for (int ni = 0; ni < 2; ++ni)
            #pragma unroll
            for (int h2 = 0; h2 < 2; ++h2) {
                const int row = m0 + wm + mi*16 + g + h2*8;
                const int col = n0 + wn + ni*8 + tg*2;
                const int i0 = h2*2;
                float2 sc = *(const float2*)&g_scale[(size_t)row*CCH + col];
                float2 sh = *(const float2*)&g_shift[(size_t)row*CCH + col];
                float q0 = fmaf(sc.x, acc[0][mi][ni][i0], sh.x), q1 = fmaf(sc.y, acc[0][mi][ni][i0+1], sh.y);
                float k0 = fmaf(sc.x, acc[1][mi][ni][i0], sh.x), k1 = fmaf(sc.y, acc[1][mi][ni][i0+1], sh.y);
                float v0 = fmaf(sc.x, acc[2][mi][ni][i0], sh.x), v1 = fmaf(sc.y, acc[2][mi][ni][i0+1], sh.y);
                size_t base = (size_t)row*768 + col;
                uint32_t hi, lo;
                split2(q0, q1, hi, lo);
                *(uint32_t*)&g_qh[base] = hi;        *(uint32_t*)&g_ql[base] = lo;
                split2(k0, k1, hi, lo);
                *(uint32_t*)&g_qh[base + 256] = hi;  *(uint32_t*)&g_ql[base + 256] = lo;
                split2(v0, v1, hi, lo);
                *(uint32_t*)&g_qh[base + 512] = hi;  *(uint32_t*)&g_ql[base + 512] = lo;
            }
}

// ---------------------------------------------------------------------------
// Kernel 2: attention, 512 threads (16 warps) — unchanged from R9 (known good).
// ---------------------------------------------------------------------------
#define A_S   61440
#define A_SH  129024
#define A_SL  163840
#define SSTR  272
#define ATTN_SMEM 198656

__global__ __launch_bounds__(512, 1) void attn_kernel()
{
    const int bid  = blockIdx.x;
    const int nseq = bid >> 3;
    const int h    = bid & 7;
    const int t0   = nseq * SEQ;
    const int tid  = threadIdx.x;
    const int wid  = tid >> 5, lane = tid & 31;
    const uint32_t sbase = smem_u32(smraw);
    float* ss = (float*)(smraw + A_S);

    #pragma unroll
    for (int i = 0; i < 6; ++i) {
        int task = tid + i*512;
        int tensor = task >> 9;
        int within = task & 511;
        int row = within >> 2, seg = within & 3;
        const __half* src = ((tensor & 1) ? g_ql : g_qh)
            + (size_t)(t0 + row)*768 + (tensor >> 1)*256 + h*EDIM + seg*8;
        *(uint4*)(smraw + tensor*10240 + row*RSTR + seg*16) = *(const uint4*)src;
    }
    __syncthreads();

    {
        const int wm = (wid >> 2) * 32;
        const int wn = (wid & 3) * 32;
        float acc[2][4][4] = {};
        #pragma unroll
        for (int kb = 0; kb < 2; ++kb) {
            uint32_t aqh[2][4], aql[2][4];
            #pragma unroll
            for (int mi = 0; mi < 2; ++mi) {
                ldsm4(aqh[mi], fragA(sbase,         wm + mi*16, kb, lane));
                ldsm4(aql[mi], fragA(sbase + 10240, wm + mi*16, kb, lane));
            }
            #pragma unroll
            for (int nb = 0; nb < 2; ++nb) {
                uint32_t bkh[4], bkl[4];
                ldsm4(bkh, fragA(sbase + 20480, wn + nb*16, kb, lane));
                ldsm4(bkl, fragA(sbase + 30720, wn + nb*16, kb, lane));
                #pragma unroll
                for (int mi = 0; mi < 2; ++mi)
                    #pragma unroll
                    for (int j = 0; j < 2; ++j) {
                        float* d = acc[mi][nb*2 + j];
                        mmaf16(d, aqh[mi], bkh[j], bkh[j+2]);
                        mmaf16(d, aql[mi], bkh[j], bkh[j+2]);
                        mmaf16(d, aqh[mi], bkl[j], bkl[j+2]);
                    }
            }
        }
        const float scl = 0.17677669529663688f;
        const int g = lane >> 2, tg = lane & 3;
        #pragma unroll
        for (int mi = 0; mi < 2; ++mi)
            #pragma unroll
            for (int ni = 0; ni < 4; ++ni)
                #pragma unroll
                for (int h2 = 0; h2 < 2; ++h2) {
                    int row = wm + mi*16 + g + h2*8;
                    int col = wn + ni*8 + tg*2;
                    *(float2*)&ss[row*132 + col] =
                        make_float2(acc[mi][ni][h2*2]*scl, acc[mi][ni][h2*2+1]*scl);
                }
    }
    __syncthreads();

    for (int r = wid; r < SEQ; r += 16) {
        float* row = ss + r*132;
        float v0 = row[lane], v1 = row[lane+32], v2 = row[lane+64], v3 = row[lane+96];
        float mx = fmaxf(fmaxf(v0, v1), fmaxf(v2, v3));
        #pragma unroll
        for (int o = 16; o > 0; o >>= 1) mx = fmaxf(mx, __shfl_xor_sync(0xffffffffu, mx, o));
        float e0 = __expf(v0 - mx), e1 = __expf(v1 - mx), e2 = __expf(v2 - mx), e3 = __expf(v3 - mx);
        float sum = e0 + e1 + e2 + e3;
        #pragma unroll
        for (int o = 16; o > 0; o >>= 1) sum += __shfl_xor_sync(0xffffffffu, sum, o);
        const float inv = 1.0f / sum;
        float p[4] = { e0*inv, e1*inv, e2*inv, e3*inv };
        #pragma unroll
        for (int j = 0; j < 4; ++j) {
            int col = lane + j*32;
            __half hp = __float2half_rn(p[j]);
            __half lp = __float2half_rn(p[j] - __half2float(hp));
            *(__half*)(smraw + A_SH + r*SSTR + col*2) = hp;
            *(__half*)(smraw + A_SL + r*SSTR + col*2) = lp;
        }
    }
    __syncthreads();

    {
        float acc[2][4] = {};
        const int wm2 = (wid >> 1) * 16;
        const int wnv = (wid & 1) * 16;
        #pragma unroll 2
        for (int kk = 0; kk < 8; ++kk) {
            uint32_t ash[4], asl[4];
            uint32_t aaddr = sbase + A_SH + (uint32_t)(wm2 + (lane & 15))*SSTR
                           + (uint32_t)(kk*32 + ((lane >> 4) << 4));
            ldsm4(ash, aaddr);
            ldsm4(asl, aaddr + (A_SL - A_SH));
            uint32_t bh[4], bl[4];
            uint32_t vrow = (uint32_t)(kk*16 + (lane & 15))*RSTR
                          + (uint32_t)((lane >> 4) << 4) + (uint32_t)wnv*2;
            ldsm4t(bh, sbase + 40960 + vrow);
            ldsm4t(bl, sbase + 51200 + vrow);
            #pragma unroll
            for (int j = 0; j < 2; ++j) {
                float* d = acc[j];
                mmaf16(d, ash, bh[j*2], bh[j*2+1]);
                mmaf16(d, asl, bh[j*2], bh[j*2+1]);
                mmaf16(d, ash, bl[j*2], bl[j*2+1]);
            }
        }
        const int g = lane >> 2, tg = lane & 3;
        #pragma unroll
        for (int j = 0; j < 2; ++j)
            #pragma unroll
            for (int h2 = 0; h2 < 2; ++h2) {
                int row = t0 + wm2 + g + h2*8;
                int col = h*EDIM + wnv + j*8 + tg*2;
                uint32_t hi, lo;
                split2(acc[j][h2*2], acc[j][h2*2+1], hi, lo);
                *(uint32_t*)&g_oh[(size_t)row*CCH + col] = hi;
                *(uint32_t*)&g_ol[(size_t)row*CCH + col] = lo;
            }
    }
}

// ---------------------------------------------------------------------------
// Kernel 3: out = O @ Wout^T. CTA 128x128, 512 threads, 16 warps (4m x 4n),
// warp tile 32x32. buffer: AH 0, AL 10240, BH 20480, BL 30720 -> 40960/buf
// ---------------------------------------------------------------------------
#define OU_BUF 40960
#define OUT_SMEM (2*OU_BUF)

__global__ __launch_bounds__(512, 1) void out_kernel(float* __restrict__ out)
{
    const int tid = threadIdx.x;
    const int wid = tid >> 5, lane = tid & 31;
    const int n0 = blockIdx.x * 128;
    const int m0 = blockIdx.y * 128;
    const uint32_t sbase = smem_u32(smraw);

    auto issue = [&](int c, int b) {
        const int k0 = c * 32;
        const uint32_t sb = sbase + b * OU_BUF;
        int row = tid >> 2, seg = tid & 3;
        uint32_t so = (uint32_t)(row*RSTR + seg*16);
        size_t ga = (size_t)(m0 + row)*CCH + k0 + seg*8;
        CP16(sb + so,         g_oh + ga);
        CP16(sb + 10240 + so, g_ol + ga);
        size_t gb = (size_t)5*65536 + (size_t)(n0 + row)*CCH + k0 + seg*8;
        CP16(sb + 20480 + so, g_wh + gb);
        CP16(sb + 30720 + so, g_wl + gb);
    };

    float acc[2][4][4] = {};   // [mi][j over 32 cols][4]
    const int wm = (wid >> 2) * 32;
    const int wn = (wid & 3) * 32;

    auto compute = [&](uint32_t sb) {
        #pragma unroll
        for (int kb = 0; kb < 2; ++kb) {
            uint32_t ah[2][4], al[2][4];
            #pragma unroll
            for (int mi = 0; mi < 2; ++mi) {
                ldsm4(ah[mi], fragA(sb,         wm + mi*16, kb, lane));
                ldsm4(al[mi], fragA(sb + 10240, wm + mi*16, kb, lane));
            }
            #pragma unroll
            for (int nb = 0; nb < 2; ++nb) {
                uint32_t bh[4], bl[4];
                ldsm4(bh, fragA(sb + 20480, wn + nb*16, kb, lane));
                ldsm4(bl, fragA(sb + 30720, wn + nb*16, kb, lane));
                #pragma unroll
                for (int mi = 0; mi < 2; ++mi)
                    #pragma unroll
                    for (int j = 0; j < 2; ++j) {
                        float* d = acc[mi][nb*2 + j];
                        mmaf16(d, ah[mi], bh[j], bh[j+2]);
                        mmaf16(d, al[mi], bh[j], bh[j+2]);
                        mmaf16(d, ah[mi], bl[j], bl[j+2]);
                    }
            }
        }
    };

    issue(0, 0); CPCOMMIT();
    CPWAIT0(); __syncthreads();
    #pragma unroll 1
    for (int c = 0; c < 8; ++c) {
        if (c < 7) { issue(c + 1, (c + 1) & 1); CPCOMMIT(); }
        compute(sbase + (c & 1) * OU_BUF);
        if (c < 7) { CPWAIT0(); __syncthreads(); }
    }

    const int g = lane >> 2, tg = lane & 3;
    #pragma unroll
    for (int mi = 0; mi < 2; ++mi)
        #pragma unroll
        for (int ni = 0; ni < 4; ++ni)
            #pragma unroll
            for (int h2 = 0; h2 < 2; ++h2) {
                const int row = m0 + wm + mi*16 + g + h2*8;
                const int col = n0 + wn + ni*8 + tg*2;
                *(float2*)&out[(size_t)row*CCH + col] =
                    make_float2(acc[mi][ni][h2*2], acc[mi][ni][h2*2+1]);
            }
}

// ---------------------------------------------------------------------------
extern "C" void kernel_launch(void* const* d_in, const int* in_sizes, int n_in,
                              void* d_out, int out_size)
{
    (void)in_sizes; (void)n_in; (void)out_size;
    const float* X      = (const float*)d_in[0];
    const float* CTX    = (const float*)d_in[1];
    const float* Wq     = (const float*)d_in[2];
    const float* Wkv    = (const float*)d_in[3];
    const float* Wout   = (const float*)d_in[4];
    const float* Wscale = (const float*)d_in[5];
    const float* Wshift = (const float*)d_in[6];
    float* out = (float*)d_out;

    __half *xh, *xl, *ch, *cl, *wh, *wl;
    cudaGetSymbolAddress((void**)&xh, g_xh);
    cudaGetSymbolAddress((void**)&xl, g_xl);
    cudaGetSymbolAddress((void**)&ch, g_ch);
    cudaGetSymbolAddress((void**)&cl, g_cl);
    cudaGetSymbolAddress((void**)&wh, g_wh);
    cudaGetSymbolAddress((void**)&wl, g_wl);

    cudaFuncSetAttribute(ss_kernel,   cudaFuncAttributeMaxDynamicSharedMemorySize, SS_SMEM);
    cudaFuncSetAttribute(qkv_kernel,  cudaFuncAttributeMaxDynamicSharedMemorySize, QKV_SMEM);
    cudaFuncSetAttribute(attn_kernel, cudaFuncAttributeMaxDynamicSharedMemorySize, ATTN_SMEM);
    cudaFuncSetAttribute(out_kernel,  cudaFuncAttributeMaxDynamicSharedMemorySize, OUT_SMEM);

    conv_kernel<<<4096, 256>>>((const float4*)X,   (uint2*)xh, (uint2*)xl, TOK*64);
    conv_kernel<<<4096, 256>>>((const float4*)CTX, (uint2*)ch, (uint2*)cl, TOK*64);
    conv_kernel<<<64, 256>>>((const float4*)Wq,     (uint2*)(wh + 0*65536), (uint2*)(wl + 0*65536), 16384);
    conv_kernel<<<128, 256>>>((const float4*)Wkv,   (uint2*)(wh + 1*65536), (uint2*)(wl + 1*65536), 32768);
    conv_kernel<<<64, 256>>>((const float4*)Wscale, (uint2*)(wh + 3*65536), (uint2*)(wl + 3*65536), 16384);
    conv_kernel<<<64, 256>>>((const float4*)Wshift, (uint2*)(wh + 4*65536), (uint2*)(wl + 4*65536), 16384);
    conv_kernel<<<64, 256>>>((const float4*)Wout,   (uint2*)(wh + 5*65536), (uint2*)(wl + 5*65536), 16384);

    ss_kernel<<<dim3(4, 1024), 512, SS_SMEM>>>();
    qkv_kernel<<<dim3(4, 1024), 512, QKV_SMEM>>>();
    attn_kernel<<<NSEQ*NHEADS, 512, ATTN_SMEM>>>();
    out_kernel<<<dim3(2, 1024), 512, OUT_SMEM>>>(out);
}

// round 12
// speedup vs baseline: 2.9310x; 1.3007x over previous
#include <cuda_runtime.h>
#include <cuda_fp16.h>
#include <cstdint>

#define TOK   131072
#define CCH   256
#define SEQ   128
#define NSEQ  1024
#define NHEADS 8
#define EDIM  32

// fp16 hi/lo global buffers (split precision: x = hi + lo)
__device__ __half g_xh[(size_t)TOK * 256], g_xl[(size_t)TOK * 256];
__device__ __half g_ch[(size_t)TOK * 256], g_cl[(size_t)TOK * 256];
__device__ __half g_wh[6 * 65536], g_wl[6 * 65536];   // Wq, Wk, Wv, Wscale, Wshift, Wout
__device__ __half g_qh[(size_t)TOK * 768], g_ql[(size_t)TOK * 768];  // q|k|v post scale/shift
__device__ __half g_oh[(size_t)TOK * 256], g_ol[(size_t)TOK * 256];  // attention out
__device__ float  g_scale[(size_t)TOK * 256], g_shift[(size_t)TOK * 256];

extern __shared__ __align__(16) char smraw[];

// ---------------- helpers ----------------
__device__ __forceinline__ uint32_t smem_u32(const void* p) {
    uint32_t a;
    asm("{ .reg .u64 t; cvta.to.shared.u64 t, %1; cvt.u32.u64 %0, t; }" : "=r"(a) : "l"(p));
    return a;
}
__device__ __forceinline__ void ldsm4(uint32_t* r, uint32_t a) {
    asm volatile("ldmatrix.sync.aligned.m8n8.x4.shared.b16 {%0,%1,%2,%3}, [%4];"
        : "=r"(r[0]), "=r"(r[1]), "=r"(r[2]), "=r"(r[3]) : "r"(a));
}
__device__ __forceinline__ void ldsm4t(uint32_t* r, uint32_t a) {
    asm volatile("ldmatrix.sync.aligned.m8n8.x4.trans.shared.b16 {%0,%1,%2,%3}, [%4];"
        : "=r"(r[0]), "=r"(r[1]), "=r"(r[2]), "=r"(r[3]) : "r"(a));
}
__device__ __forceinline__ void mmaf16(float* d, const uint32_t* a, uint32_t b0, uint32_t b1) {
    asm volatile("mma.sync.aligned.m16n8k16.row.col.f32.f16.f16.f32 "
        "{%0,%1,%2,%3}, {%4,%5,%6,%7}, {%8,%9}, {%0,%1,%2,%3};"
        : "+f"(d[0]), "+f"(d[1]), "+f"(d[2]), "+f"(d[3])
        : "r"(a[0]), "r"(a[1]), "r"(a[2]), "r"(a[3]), "r"(b0), "r"(b1));
}
#define CP16(s, g) asm volatile("cp.async.cg.shared.global [%0], [%1], 16;" :: "r"(s), "l"(g))
#define CPCOMMIT() asm volatile("cp.async.commit_group;")
#define CPWAIT0()  asm volatile("cp.async.wait_group 0;")

struct H4 { uint2 hi, lo; };
__device__ __forceinline__ H4 splitf4(float4 v) {
    __half2 h0 = __floats2half2_rn(v.x, v.y);
    __half2 h1 = __floats2half2_rn(v.z, v.w);
    float2 f0 = __half22float2(h0), f1 = __half22float2(h1);
    __half2 l0 = __floats2half2_rn(v.x - f0.x, v.y - f0.y);
    __half2 l1 = __floats2half2_rn(v.z - f1.x, v.w - f1.y);
    H4 r;
    r.hi.x = *(uint32_t*)&h0; r.hi.y = *(uint32_t*)&h1;
    r.lo.x = *(uint32_t*)&l0; r.lo.y = *(uint32_t*)&l1;
    return r;
}
__device__ __forceinline__ void split2(float a, float b, uint32_t& hi, uint32_t& lo) {
    __half2 h = __floats2half2_rn(a, b);
    float2 f = __half22float2(h);
    __half2 l = __floats2half2_rn(a - f.x, b - f.y);
    hi = *(uint32_t*)&h; lo = *(uint32_t*)&l;
}

#define RSTR 80   // 32 halves (64B) padded to 80B -> conflict-free ldmatrix
__device__ __forceinline__ uint32_t fragA(uint32_t matbase, int row0, int kb, int lane) {
    return matbase + (uint32_t)(row0 + (lane & 15)) * RSTR
                   + (uint32_t)(kb * 32 + ((lane >> 4) << 4));
}

// ---------------------------------------------------------------------------
// Kernel 0: fp32 -> fp16 hi/lo convert (memory bound)
// ---------------------------------------------------------------------------
__global__ __launch_bounds__(256) void conv_kernel(
    const float4* __restrict__ s, uint2* __restrict__ dh, uint2* __restrict__ dl, int n)
{
    for (int i = blockIdx.x * blockDim.x + threadIdx.x; i < n; i += gridDim.x * blockDim.x) {
        H4 h = splitf4(s[i]);
        dh[i] = h.hi; dl[i] = h.lo;
    }
}

// ---------------------------------------------------------------------------
// Kernel 1a: scale/shift = CTX @ {Wscale,Wshift}^T (2-term split: exact CTX,
// rounded weights). CTA 128x64, 512 threads, warps 4m x 4n (32x16).
// buffer: CH 0, CL 10240, W t: 20480 + t*5120 -> 30720/buf
// ---------------------------------------------------------------------------
#define SS_BUF 30720
#define SS_SMEM (2*SS_BUF)

__global__ __launch_bounds__(512, 1) void ss_kernel()
{
    const int tid = threadIdx.x;
    const int wid = tid >> 5, lane = tid & 31;
    const int n0 = blockIdx.x * 64;
    const int m0 = blockIdx.y * 128;
    const uint32_t sbase = smem_u32(smraw);

    auto issue = [&](int c, int b) {
        const int k0 = c * 32;
        const uint32_t sb = sbase + b * SS_BUF;
        {
            int row = tid >> 2, seg = tid & 3;
            uint32_t so = (uint32_t)(row*RSTR + seg*16);
            size_t gi = (size_t)(m0 + row)*CCH + k0 + seg*8;
            CP16(sb + so,         g_ch + gi);
            CP16(sb + 10240 + so, g_cl + gi);
        }
        {   // B hi only: 2 tiles x 64 rows x 4 segs = 512 tasks
            int tile = tid >> 8;
            int r = (tid & 255) >> 2, seg = tid & 3;
            const __half* src = g_wh + (size_t)(3 + tile)*65536
                              + (size_t)(n0 + r)*CCH + k0 + seg*8;
            CP16(sb + 20480 + tile*5120 + r*RSTR + seg*16, src);
        }
    };

    float acc[2][2][2][4] = {};
    const int wm = (wid >> 2) * 32;
    const int wn = (wid & 3) * 16;

    auto compute = [&](uint32_t sb) {
        #pragma unroll
        for (int kb = 0; kb < 2; ++kb) {
            uint32_t ah[2][4], al[2][4];
            #pragma unroll
            for (int mi = 0; mi < 2; ++mi) {
                ldsm4(ah[mi], fragA(sb,         wm + mi*16, kb, lane));
                ldsm4(al[mi], fragA(sb + 10240, wm + mi*16, kb, lane));
            }
            #pragma unroll
            for (int t = 0; t < 2; ++t) {
                uint32_t bh[4];
                ldsm4(bh, fragA(sb + 20480 + t*5120, wn, kb, lane));
                #pragma unroll
                for (int mi = 0; mi < 2; ++mi)
                    #pragma unroll
                    for (int ni = 0; ni < 2; ++ni) {
                        float* d = acc[t][mi][ni];
                        mmaf16(d, ah[mi], bh[ni], bh[ni+2]);
                        mmaf16(d, al[mi], bh[ni], bh[ni+2]);
                    }
            }
        }
    };

    issue(0, 0); CPCOMMIT();
    CPWAIT0(); __syncthreads();
    #pragma unroll 1
    for (int c = 0; c < 8; ++c) {
        if (c < 7) { issue(c + 1, (c + 1) & 1); CPCOMMIT(); }
        compute(sbase + (c & 1) * SS_BUF);
        if (c < 7) { CPWAIT0(); __syncthreads(); }
    }

    const int g = lane >> 2, tg = lane & 3;
    #pragma unroll
    for (int mi = 0; mi < 2; ++mi)
        #pragma unroll
        for (int ni = 0; ni < 2; ++ni)
            #pragma unroll
            for (int h2 = 0; h2 < 2; ++h2) {
                const int row = m0 + wm + mi*16 + g + h2*8;
                const int col = n0 + wn + ni*8 + tg*2;
                *(float2*)&g_scale[(size_t)row*CCH + col] =
                    make_float2(acc[0][mi][ni][h2*2], acc[0][mi][ni][h2*2+1]);
                *(float2*)&g_shift[(size_t)row*CCH + col] =
                    make_float2(acc[1][mi][ni][h2*2], acc[1][mi][ni][h2*2+1]);
            }
}

// ---------------------------------------------------------------------------
// Kernel 1b: q,k,v = X @ {Wq,Wk,Wv}^T (2-term), fused scale*x+shift epilogue.
// CTA 128x64, 512 threads, warps 4m x 4n (32x16).
// buffer: XH 0, XL 10240, W t: 20480 + t*5120 -> 35840/buf
// ---------------------------------------------------------------------------
#define QK_BUF 35840
#define QKV_SMEM (2*QK_BUF)

__global__ __launch_bounds__(512, 1) void qkv_kernel()
{
    const int tid = threadIdx.x;
    const int wid = tid >> 5, lane = tid & 31;
    const int n0 = blockIdx.x * 64;
    const int m0 = blockIdx.y * 128;
    const uint32_t sbase = smem_u32(smraw);

    auto issue = [&](int c, int b) {
        const int k0 = c * 32;
        const uint32_t sb = sbase + b * QK_BUF;
        {
            int row = tid >> 2, seg = tid & 3;
            uint32_t so = (uint32_t)(row*RSTR + seg*16);
            size_t gi = (size_t)(m0 + row)*CCH + k0 + seg*8;
            CP16(sb + so,         g_xh + gi);
            CP16(sb + 10240 + so, g_xl + gi);
        }
        #pragma unroll
        for (int i = 0; i < 2; ++i) {   // B hi only: 3 tiles x 256 = 768 tasks
            int task = tid + i*512;
            if (task < 768) {
                int tile = task >> 8;   // 0..2
                int r = (task & 255) >> 2, seg = task & 3;
                const __half* src = g_wh + (size_t)tile*65536
                                  + (size_t)(n0 + r)*CCH + k0 + seg*8;
                CP16(sb + 20480 + tile*5120 + r*RSTR + seg*16, src);
            }
        }
    };

    float acc[3][2][2][4] = {};
    const int wm = (wid >> 2) * 32;
    const int wn = (wid & 3) * 16;

    auto compute = [&](uint32_t sb) {
        #pragma unroll
        for (int kb = 0; kb < 2; ++kb) {
            uint32_t ah[2][4], al[2][4];
            #pragma unroll
            for (int mi = 0; mi < 2; ++mi) {
                ldsm4(ah[mi], fragA(sb,         wm + mi*16, kb, lane));
                ldsm4(al[mi], fragA(sb + 10240, wm + mi*16, kb, lane));
            }
            #pragma unroll
            for (int t = 0; t < 3; ++t) {
                uint32_t bh[4];
                ldsm4(bh, fragA(sb + 20480 + t*5120, wn, kb, lane));
                #pragma unroll
                for (int mi = 0; mi < 2; ++mi)
                    #pragma unroll
                    for (int ni = 0; ni < 2; ++ni) {
                        float* d = acc[t][mi][ni];
                        mmaf16(d, ah[mi], bh[ni], bh[ni+2]);
                        mmaf16(d, al[mi], bh[ni], bh[ni+2]);
                    }
            }
        }
    };

    issue(0, 0); CPCOMMIT();
    CPWAIT0(); __syncthreads();
    #pragma unroll 1
    for (int c = 0; c < 8; ++c) {
        if (c < 7) { issue(c + 1, (c + 1) & 1); CPCOMMIT(); }
        compute(sbase + (c & 1) * QK_BUF);
        if (c < 7) { CPWAIT0(); __syncthreads(); }
    }

    // Epilogue: fused scale*x+shift; q as hi+lo, k/v hi only (2-term consumers)
    const int g = lane >> 2, tg = lane & 3;
    #pragma unroll
    for (int mi = 0; mi < 2; ++mi)
        #pragma unroll
        for (int ni = 0; ni < 2; ++ni)
            #pragma unroll
            for (int h2 = 0; h2 < 2; ++h2) {
                const int row = m0 + wm + mi*16 + g + h2*8;
                const int col = n0 + wn + ni*8 + tg*2;
                const int i0 = h2*2;
                float2 sc = *(const float2*)&g_scale[(size_t)row*CCH + col];
                float2 sh = *(const float2*)&g_shift[(size_t)row*CCH + col];
                float q0 = fmaf(sc.x, acc[0][mi][ni][i0], sh.x), q1 = fmaf(sc.y, acc[0][mi][ni][i0+1], sh.y);
                float k0 = fmaf(sc.x, acc[1][mi][ni][i0], sh.x), k1 = fmaf(sc.y, acc[1][mi][ni][i0+1], sh.y);
                float v0 = fmaf(sc.x, acc[2][mi][ni][i0], sh.x), v1 = fmaf(sc.y, acc[2][mi][ni][i0+1], sh.y);
                size_t base = (size_t)row*768 + col;
                uint32_t hi, lo;
                split2(q0, q1, hi, lo);
                *(uint32_t*)&g_qh[base] = hi;        *(uint32_t*)&g_ql[base] = lo;
                split2(k0, k1, hi, lo);
                *(uint32_t*)&g_qh[base + 256] = hi;
                split2(v0, v1, hi, lo);
                *(uint32_t*)&g_qh[base + 512] = hi;
            }
}

// ---------------------------------------------------------------------------
// Kernel 2: attention — register-resident softmax, 2-term splits.
// One CTA per (seq, head), 512 threads, warps 4m x 4n for QK (32x32 S tile).
// Probabilities stay in registers; QK C-fragments convert directly into SV
// A-fragments. Per-warp O k-slice partials reduced through smem.
// smem: QH 0, QL 10240, KH 20480, VH 30720, PSUM 40960 (128x4 f32),
//       O4 43008 (4 x 128 x 32 f32) -> 108544
// ---------------------------------------------------------------------------
#define AT_Q  0
#define AT_QL 10240
#define AT_K  20480
#define AT_V  30720
#define AT_PS 40960
#define AT_O  43008
#define ATTN_SMEM 108544

__global__ __launch_bounds__(512, 1) void attn_kernel()
{
    const int bid  = blockIdx.x;
    const int nseq = bid >> 3;
    const int h    = bid & 7;
    const int t0   = nseq * SEQ;
    const int tid  = threadIdx.x;
    const int wid  = tid >> 5, lane = tid & 31;
    const uint32_t sbase = smem_u32(smraw);

    // Load qh, ql, kh, vh tiles: 4 x 512 uint4 tasks
    #pragma unroll
    for (int i = 0; i < 4; ++i) {
        int task = tid + i*512;
        int tensor = task >> 9;            // 0..3
        int within = task & 511;
        int row = within >> 2, seg = within & 3;
        size_t base = (size_t)(t0 + row)*768 + h*EDIM + seg*8;
        const __half* src = (tensor == 0) ? g_qh + base
                          : (tensor == 1) ? g_ql + base
                          : (tensor == 2) ? g_qh + base + 256
                                          : g_qh + base + 512;
        *(uint4*)(smraw + tensor*10240 + row*RSTR + seg*16) = *(const uint4*)src;
    }
    __syncthreads();

    const int wm = (wid >> 2) * 32;
    const int wn = (wid & 3) * 32;
    const int g = lane >> 2, tg = lane & 3;

    // --- S = Q K^T (2-term: exact Q, rounded K); kept in registers
    float p[2][4][4] = {};
    #pragma unroll
    for (int kb = 0; kb < 2; ++kb) {
        uint32_t aqh[2][4], aql[2][4];
        #pragma unroll
        for (int mi = 0; mi < 2; ++mi) {
            ldsm4(aqh[mi], fragA(sbase + AT_Q,  wm + mi*16, kb, lane));
            ldsm4(aql[mi], fragA(sbase + AT_QL, wm + mi*16, kb, lane));
        }
        #pragma unroll
        for (int nb = 0; nb < 2; ++nb) {
            uint32_t bkh[4];
            ldsm4(bkh, fragA(sbase + AT_K, wn + nb*16, kb, lane));
            #pragma unroll
            for (int mi = 0; mi < 2; ++mi)
                #pragma unroll
                for (int j = 0; j < 2; ++j) {
                    float* d = p[mi][nb*2 + j];
                    mmaf16(d, aqh[mi], bkh[j], bkh[j+2]);
                    mmaf16(d, aql[mi], bkh[j], bkh[j+2]);
                }
        }
    }

    // --- exp (no max subtraction: |dots| << 88, fp32 exp safe)
    const float scl = 0.17677669529663688f;  // 1/sqrt(32)
    #pragma unroll
    for (int mi = 0; mi < 2; ++mi)
        #pragma unroll
        for (int ni = 0; ni < 4; ++ni)
            #pragma unroll
            for (int r = 0; r < 4; ++r)
                p[mi][ni][r] = __expf(p[mi][ni][r] * scl);

    // --- row sums: per-warp 32-col partials, combine through smem
    float* psum = (float*)(smraw + AT_PS);
    float rs[2][2];
    #pragma unroll
    for (int mi = 0; mi < 2; ++mi)
        #pragma unroll
        for (int h2 = 0; h2 < 2; ++h2) {
            float s = 0.f;
            #pragma unroll
            for (int ni = 0; ni < 4; ++ni) s += p[mi][ni][h2*2] + p[mi][ni][h2*2+1];
            s += __shfl_xor_sync(0xffffffffu, s, 1);
            s += __shfl_xor_sync(0xffffffffu, s, 2);
            rs[mi][h2] = s;
        }
    if (tg == 0) {
        #pragma unroll
        for (int mi = 0; mi < 2; ++mi)
            #pragma unroll
            for (int h2 = 0; h2 < 2; ++h2)
                psum[(wm + mi*16 + g + h2*8)*4 + (wid & 3)] = rs[mi][h2];
    }
    __syncthreads();
    #pragma unroll
    for (int mi = 0; mi < 2; ++mi)
        #pragma unroll
        for (int h2 = 0; h2 < 2; ++h2) {
            int row = wm + mi*16 + g + h2*8;
            float4 ps = *(float4*)&psum[row*4];
            float inv = 1.0f / (ps.x + ps.y + ps.z + ps.w);
            #pragma unroll
            for (int ni = 0; ni < 4; ++ni) {
                p[mi][ni][h2*2]   *= inv;
                p[mi][ni][h2*2+1] *= inv;
            }
        }

    // --- convert P C-fragments directly into SV A-fragments (hi/lo)
    uint32_t ah[2][2][4], al[2][2][4];
    #pragma unroll
    for (int mi = 0; mi < 2; ++mi)
        #pragma unroll
        for (int kb2 = 0; kb2 < 2; ++kb2) {
            split2(p[mi][2*kb2][0],   p[mi][2*kb2][1],   ah[mi][kb2][0], al[mi][kb2][0]);
            split2(p[mi][2*kb2][2],   p[mi][2*kb2][3],   ah[mi][kb2][1], al[mi][kb2][1]);
            split2(p[mi][2*kb2+1][0], p[mi][2*kb2+1][1], ah[mi][kb2][2], al[mi][kb2][2]);
            split2(p[mi][2*kb2+1][2], p[mi][2*kb2+1][3], ah[mi][kb2][3], al[mi][kb2][3]);
        }

    // --- O partial = P[rows wm..+32, k wn..+32] x V[k, 0..32] (2-term: V rounded)
    float o[2][4][4] = {};
    #pragma unroll
    for (int kb2 = 0; kb2 < 2; ++kb2) {
        uint32_t bh[2][4];
        #pragma unroll
        for (int ch = 0; ch < 2; ++ch) {
            uint32_t vaddr = sbase + AT_V
                + (uint32_t)(wn + kb2*16 + (lane & 15))*RSTR
                + (uint32_t)((lane >> 4) << 4) + (uint32_t)ch*32;
            ldsm4t(bh[ch], vaddr);
        }
        #pragma unroll
        for (int mi = 0; mi < 2; ++mi)
            #pragma unroll
            for (int ch = 0; ch < 2; ++ch)
                #pragma unroll
                for (int j = 0; j < 2; ++j) {
                    float* d = o[mi][ch*2 + j];
                    mmaf16(d, ah[mi][kb2], bh[ch][j*2], bh[ch][j*2+1]);
                    mmaf16(d, al[mi][kb2], bh[ch][j*2], bh[ch][j*2+1]);
                }
    }

    // --- store per-k-slice partials, reduce across the 4 slices
    float* O4 = (float*)(smraw + AT_O);
    const int slice = wid & 3;
    #pragma unroll
    for (int mi = 0; mi < 2; ++mi)
        #pragma unroll
        for (int ni = 0; ni < 4; ++ni)
            #pragma unroll
            for (int h2 = 0; h2 < 2; ++h2) {
                int row = wm + mi*16 + g + h2*8;
                int col = ni*8 + tg*2;
                *(float2*)&O4[((size_t)slice*128 + row)*32 + col] =
                    make_float2(o[mi][ni][h2*2], o[mi][ni][h2*2+1]);
            }
    __syncthreads();

    {
        int row = tid >> 2, c0 = (tid & 3) * 8;
        float4 s0 = make_float4(0,0,0,0), s1 = make_float4(0,0,0,0);
        #pragma unroll
        for (int s = 0; s < 4; ++s) {
            float4 a = *(float4*)&O4[((size_t)s*128 + row)*32 + c0];
            float4 b = *(float4*)&O4[((size_t)s*128 + row)*32 + c0 + 4];
            s0.x += a.x; s0.y += a.y; s0.z += a.z; s0.w += a.w;
            s1.x += b.x; s1.y += b.y; s1.z += b.z; s1.w += b.w;
        }
        uint32_t h0,h1,h2_,h3, l0,l1,l2,l3;
        split2(s0.x, s0.y, h0, l0);
        split2(s0.z, s0.w, h1, l1);
        split2(s1.x, s1.y, h2_, l2);
        split2(s1.z, s1.w, h3, l3);
        size_t base = (size_t)(t0 + row)*CCH + h*EDIM + c0;
        *(uint4*)&g_oh[base] = make_uint4(h0, h1, h2_, h3);
        *(uint4*)&g_ol[base] = make_uint4(l0, l1, l2, l3);
    }
}

// ---------------------------------------------------------------------------
// Kernel 3: out = O @ Wout^T (3-term, unchanged). CTA 128x128, 512 threads.
// buffer: AH 0, AL 10240, BH 20480, BL 30720 -> 40960/buf
// ---------------------------------------------------------------------------
#define OU_BUF 40960
#define OUT_SMEM (2*OU_BUF)

__global__ __launch_bounds__(512, 1) void out_kernel(float* __restrict__ out)
{
    const int tid = threadIdx.x;
    const int wid = tid >> 5, lane = tid & 31;
    const int n0 = blockIdx.x * 128;
    const int m0 = blockIdx.y * 128;
    const uint32_t sbase = smem_u32(smraw);

    auto issue = [&](int c, int b) {
        const int k0 = c * 32;
        const uint32_t sb = sbase + b * OU_BUF;
        int row = tid >> 2, seg = tid & 3;
        uint32_t so = (uint32_t)(row*RSTR + seg*16);
        size_t ga = (size_t)(m0 + row)*CCH + k0 + seg*8;
        CP16(sb + so,         g_oh + ga);
        CP16(sb + 10240 + so, g_ol + ga);
        size_t gb = (size_t)5*65536 + (size_t)(n0 + row)*CCH + k0 + seg*8;
        CP16(sb + 20480 + so, g_wh + gb);
        CP16(sb + 30720 + so, g_wl + gb);
    };

    float acc[2][4][4] = {};
    const int wm = (wid >> 2) * 32;
    const int wn = (wid & 3) * 32;

    auto compute = [&](uint32_t sb) {
        #pragma unroll
        for (int kb = 0; kb < 2; ++kb) {
            uint32_t ah[2][4], al[2][4];
            #pragma unroll
            for (int mi = 0; mi < 2; ++mi) {
                ldsm4(ah[mi], fragA(sb,         wm + mi*16, kb, lane));
                ldsm4(al[mi], fragA(sb + 10240, wm + mi*16, kb, lane));
            }
            #pragma unroll
            for (int nb = 0; nb < 2; ++nb) {
                uint32_t bh[4], bl[4];
                ldsm4(bh, fragA(sb + 20480, wn + nb*16, kb, lane));
                ldsm4(bl, fragA(sb + 30720, wn + nb*16, kb, lane));
                #pragma unroll
                for (int mi = 0; mi < 2; ++mi)
                    #pragma unroll
                    for (int j = 0; j < 2; ++j) {
                        float* d = acc[mi][nb*2 + j];
                        mmaf16(d, ah[mi], bh[j], bh[j+2]);
                        mmaf16(d, al[mi], bh[j], bh[j+2]);
                        mmaf16(d, ah[mi], bl[j], bl[j+2]);
                    }
            }
        }
    };

    issue(0, 0); CPCOMMIT();
    CPWAIT0(); __syncthreads();
    #pragma unroll 1
    for (int c = 0; c < 8; ++c) {
        if (c < 7) { issue(c + 1, (c + 1) & 1); CPCOMMIT(); }
        compute(sbase + (c & 1) * OU_BUF);
        if (c < 7) { CPWAIT0(); __syncthreads(); }
    }

    const int g = lane >> 2, tg = lane & 3;
    #pragma unroll
    for (int mi = 0; mi < 2; ++mi)
        #pragma unroll
        for (int ni = 0; ni < 4; ++ni)
            #pragma unroll
            for (int h2 = 0; h2 < 2; ++h2) {
                const int row = m0 + wm + mi*16 + g + h2*8;
                const int col = n0 + wn + ni*8 + tg*2;
                *(float2*)&out[(size_t)row*CCH + col] =
                    make_float2(acc[mi][ni][h2*2], acc[mi][ni][h2*2+1]);
            }
}

// ---------------------------------------------------------------------------
extern "C" void kernel_launch(void* const* d_in, const int* in_sizes, int n_in,
                              void* d_out, int out_size)
{
    (void)in_sizes; (void)n_in; (void)out_size;
    const float* X      = (const float*)d_in[0];
    const float* CTX    = (const float*)d_in[1];
    const float* Wq     = (const float*)d_in[2];
    const float* Wkv    = (const float*)d_in[3];
    const float* Wout   = (const float*)d_in[4];
    const float* Wscale = (const float*)d_in[5];
    const float* Wshift = (const float*)d_in[6];
    float* out = (float*)d_out;

    __half *xh, *xl, *ch, *cl, *wh, *wl;
    cudaGetSymbolAddress((void**)&xh, g_xh);
    cudaGetSymbolAddress((void**)&xl, g_xl);
    cudaGetSymbolAddress((void**)&ch, g_ch);
    cudaGetSymbolAddress((void**)&cl, g_cl);
    cudaGetSymbolAddress((void**)&wh, g_wh);
    cudaGetSymbolAddress((void**)&wl, g_wl);

    cudaFuncSetAttribute(ss_kernel,   cudaFuncAttributeMaxDynamicSharedMemorySize, SS_SMEM);
    cudaFuncSetAttribute(qkv_kernel,  cudaFuncAttributeMaxDynamicSharedMemorySize, QKV_SMEM);
    cudaFuncSetAttribute(attn_kernel, cudaFuncAttributeMaxDynamicSharedMemorySize, ATTN_SMEM);
    cudaFuncSetAttribute(out_kernel,  cudaFuncAttributeMaxDynamicSharedMemorySize, OUT_SMEM);

    conv_kernel<<<4096, 256>>>((const float4*)X,   (uint2*)xh, (uint2*)xl, TOK*64);
    conv_kernel<<<4096, 256>>>((const float4*)CTX, (uint2*)ch, (uint2*)cl, TOK*64);
    conv_kernel<<<64, 256>>>((const float4*)Wq,     (uint2*)(wh + 0*65536), (uint2*)(wl + 0*65536), 16384);
    conv_kernel<<<128, 256>>>((const float4*)Wkv,   (uint2*)(wh + 1*65536), (uint2*)(wl + 1*65536), 32768);
    conv_kernel<<<64, 256>>>((const float4*)Wscale, (uint2*)(wh + 3*65536), (uint2*)(wl + 3*65536), 16384);
    conv_kernel<<<64, 256>>>((const float4*)Wshift, (uint2*)(wh + 4*65536), (uint2*)(wl + 4*65536), 16384);
    conv_kernel<<<64, 256>>>((const float4*)Wout,   (uint2*)(wh + 5*65536), (uint2*)(wl + 5*65536), 16384);

    ss_kernel<<<dim3(4, 1024), 512, SS_SMEM>>>();
    qkv_kernel<<<dim3(4, 1024), 512, QKV_SMEM>>>();
    attn_kernel<<<NSEQ*NHEADS, 512, ATTN_SMEM>>>();
    out_kernel<<<dim3(2, 1024), 512, OUT_SMEM>>>(out);
}

// round 13
// speedup vs baseline: 3.1941x; 1.0898x over previous
#include <cuda_runtime.h>
#include <cuda_fp16.h>
#include <cstdint>

#define TOK   131072
#define CCH   256
#define SEQ   128
#define NSEQ  1024
#define NHEADS 8
#define EDIM  32

// fp16 hi/lo global buffers (split precision: x = hi + lo)
__device__ __half g_xh[(size_t)TOK * 256], g_xl[(size_t)TOK * 256];
__device__ __half g_ch[(size_t)TOK * 256], g_cl[(size_t)TOK * 256];
__device__ __half g_wh[6 * 65536], g_wl[6 * 65536];   // Wq, Wk, Wv, Wscale, Wshift, Wout
__device__ __half g_qh[(size_t)TOK * 768], g_ql[(size_t)TOK * 768];  // q|k|v post scale/shift
__device__ __half g_oh[(size_t)TOK * 256], g_ol[(size_t)TOK * 256];  // attention out

extern __shared__ __align__(16) char smraw[];

// ---------------- helpers ----------------
__device__ __forceinline__ uint32_t smem_u32(const void* p) {
    uint32_t a;
    asm("{ .reg .u64 t; cvta.to.shared.u64 t, %1; cvt.u32.u64 %0, t; }" : "=r"(a) : "l"(p));
    return a;
}
__device__ __forceinline__ void ldsm4(uint32_t* r, uint32_t a) {
    asm volatile("ldmatrix.sync.aligned.m8n8.x4.shared.b16 {%0,%1,%2,%3}, [%4];"
        : "=r"(r[0]), "=r"(r[1]), "=r"(r[2]), "=r"(r[3]) : "r"(a));
}
__device__ __forceinline__ void ldsm4t(uint32_t* r, uint32_t a) {
    asm volatile("ldmatrix.sync.aligned.m8n8.x4.trans.shared.b16 {%0,%1,%2,%3}, [%4];"
        : "=r"(r[0]), "=r"(r[1]), "=r"(r[2]), "=r"(r[3]) : "r"(a));
}
__device__ __forceinline__ void mmaf16(float* d, const uint32_t* a, uint32_t b0, uint32_t b1) {
    asm volatile("mma.sync.aligned.m16n8k16.row.col.f32.f16.f16.f32 "
        "{%0,%1,%2,%3}, {%4,%5,%6,%7}, {%8,%9}, {%0,%1,%2,%3};"
        : "+f"(d[0]), "+f"(d[1]), "+f"(d[2]), "+f"(d[3])
        : "r"(a[0]), "r"(a[1]), "r"(a[2]), "r"(a[3]), "r"(b0), "r"(b1));
}
#define CP16(s, g) asm volatile("cp.async.cg.shared.global [%0], [%1], 16;" :: "r"(s), "l"(g))
#define CPCOMMIT() asm volatile("cp.async.commit_group;")
#define CPWAIT0()  asm volatile("cp.async.wait_group 0;")

struct H4 { uint2 hi, lo; };
__device__ __forceinline__ H4 splitf4(float4 v) {
    __half2 h0 = __floats2half2_rn(v.x, v.y);
    __half2 h1 = __floats2half2_rn(v.z, v.w);
    float2 f0 = __half22float2(h0), f1 = __half22float2(h1);
    __half2 l0 = __floats2half2_rn(v.x - f0.x, v.y - f0.y);
    __half2 l1 = __floats2half2_rn(v.z - f1.x, v.w - f1.y);
    H4 r;
    r.hi.x = *(uint32_t*)&h0; r.hi.y = *(uint32_t*)&h1;
    r.lo.x = *(uint32_t*)&l0; r.lo.y = *(uint32_t*)&l1;
    return r;
}
__device__ __forceinline__ void split2(float a, float b, uint32_t& hi, uint32_t& lo) {
    __half2 h = __floats2half2_rn(a, b);
    float2 f = __half22float2(h);
    __half2 l = __floats2half2_rn(a - f.x, b - f.y);
    hi = *(uint32_t*)&h; lo = *(uint32_t*)&l;
}

#define RSTR 80   // 32 halves (64B) padded to 80B -> conflict-free ldmatrix
__device__ __forceinline__ uint32_t fragA(uint32_t matbase, int row0, int kb, int lane) {
    return matbase + (uint32_t)(row0 + (lane & 15)) * RSTR
                   + (uint32_t)(kb * 32 + ((lane >> 4) << 4));
}

// ---------------------------------------------------------------------------
// Kernel 0: fp32 -> fp16 hi/lo convert (memory bound); hi-only variant for
// weights consumed as 2-term B operands.
// ---------------------------------------------------------------------------
__global__ __launch_bounds__(256) void conv_kernel(
    const float4* __restrict__ s, uint2* __restrict__ dh, uint2* __restrict__ dl, int n)
{
    for (int i = blockIdx.x * blockDim.x + threadIdx.x; i < n; i += gridDim.x * blockDim.x) {
        H4 h = splitf4(s[i]);
        dh[i] = h.hi; dl[i] = h.lo;
    }
}
__global__ __launch_bounds__(256) void conv_hi_kernel(
    const float4* __restrict__ s, uint2* __restrict__ dh, int n)
{
    for (int i = blockIdx.x * blockDim.x + threadIdx.x; i < n; i += gridDim.x * blockDim.x) {
        float4 v = s[i];
        __half2 h0 = __floats2half2_rn(v.x, v.y);
        __half2 h1 = __floats2half2_rn(v.z, v.w);
        dh[i] = make_uint2(*(uint32_t*)&h0, *(uint32_t*)&h1);
    }
}

// ---------------------------------------------------------------------------
// Kernel 1: fused projection, all 5 tensors (q,k,v from X; scale,shift from
// CTX), 2-term split (exact activations, rounded weights), fused epilogue.
// CTA 128 x 64, 256 threads, 8 warps (4m x 2n), warp tile 32x32.
// buffer: XH 0, XL 10240, CH 20480, CL 30720, W t: 40960 + t*5120 -> 66560
// ---------------------------------------------------------------------------
#define PJ_BUF 66560
#define PROJ_SMEM (2*PJ_BUF)

__global__ __launch_bounds__(256, 1) void proj_kernel()
{
    const int tid = threadIdx.x;
    const int wid = tid >> 5, lane = tid & 31;
    const int n0 = blockIdx.x * 64;
    const int m0 = blockIdx.y * 128;
    const uint32_t sbase = smem_u32(smraw);

    auto issue = [&](int c, int b) {
        const int k0 = c * 32;
        const uint32_t sb = sbase + b * PJ_BUF;
        #pragma unroll
        for (int u = 0; u < 2; ++u) {       // A tiles: 512 tasks per tensor
            int idx = tid + u*256;
            int row = idx >> 2, seg = idx & 3;
            uint32_t so = (uint32_t)(row*RSTR + seg*16);
            size_t gi = (size_t)(m0 + row)*CCH + k0 + seg*8;
            CP16(sb + so,         g_xh + gi);
            CP16(sb + 10240 + so, g_xl + gi);
            CP16(sb + 20480 + so, g_ch + gi);
            CP16(sb + 30720 + so, g_cl + gi);
        }
        {   // weights hi only: 5 tiles x 256 tasks
            int r = tid >> 2, seg = tid & 3;
            uint32_t so = (uint32_t)(r*RSTR + seg*16);
            #pragma unroll
            for (int t = 0; t < 5; ++t) {
                const __half* src = g_wh + (size_t)t*65536
                                  + (size_t)(n0 + r)*CCH + k0 + seg*8;
                CP16(sb + 40960 + t*5120 + so, src);
            }
        }
    };

    float acc[5][2][4][4] = {};   // [tensor][mi][nj][4]
    const int wm = (wid >> 1) * 32;
    const int wn = (wid & 1) * 32;

    auto compute = [&](uint32_t sb) {
        #pragma unroll
        for (int kb = 0; kb < 2; ++kb) {
            uint32_t axh[2][4], axl[2][4], ach[2][4], acl[2][4];
            #pragma unroll
            for (int mi = 0; mi < 2; ++mi) {
                ldsm4(axh[mi], fragA(sb,         wm + mi*16, kb, lane));
                ldsm4(axl[mi], fragA(sb + 10240, wm + mi*16, kb, lane));
                ldsm4(ach[mi], fragA(sb + 20480, wm + mi*16, kb, lane));
                ldsm4(acl[mi], fragA(sb + 30720, wm + mi*16, kb, lane));
            }
            #pragma unroll
            for (int t = 0; t < 5; ++t) {
                const uint32_t (*Ah)[4] = (t < 3) ? axh : ach;
                const uint32_t (*Al)[4] = (t < 3) ? axl : acl;
                #pragma unroll
                for (int nb = 0; nb < 2; ++nb) {
                    uint32_t bh[4];
                    ldsm4(bh, fragA(sb + 40960 + t*5120, wn + nb*16, kb, lane));
                    #pragma unroll
                    for (int mi = 0; mi < 2; ++mi)
                        #pragma unroll
                        for (int j = 0; j < 2; ++j) {
                            float* d = acc[t][mi][nb*2 + j];
                            mmaf16(d, Ah[mi], bh[j], bh[j+2]);
                            mmaf16(d, Al[mi], bh[j], bh[j+2]);
                        }
                }
            }
        }
    };

    issue(0, 0); CPCOMMIT();
    CPWAIT0(); __syncthreads();
    #pragma unroll 1
    for (int c = 0; c < 8; ++c) {
        if (c < 7) { issue(c + 1, (c + 1) & 1); CPCOMMIT(); }
        compute(sbase + (c & 1) * PJ_BUF);
        if (c < 7) { CPWAIT0(); __syncthreads(); }
    }

    // Epilogue: scale*x+shift; q hi+lo, k/v hi only (2-term consumers)
    const int g = lane >> 2, tg = lane & 3;
    #pragma unroll
    for (int mi = 0; mi < 2; ++mi)
        #pragma unroll
        for (int nj = 0; nj < 4; ++nj)
            #pragma unroll
            for (int h2 = 0; h2 < 2; ++h2) {
                const int row = m0 + wm + mi*16 + g + h2*8;
                const int col = n0 + wn + nj*8 + tg*2;
                const int i0 = h2*2;
                float sc0 = acc[3][mi][nj][i0],   sc1 = acc[3][mi][nj][i0+1];
                float sh0 = acc[4][mi][nj][i0],   sh1 = acc[4][mi][nj][i0+1];
                float q0 = fmaf(sc0, acc[0][mi][nj][i0], sh0), q1 = fmaf(sc1, acc[0][mi][nj][i0+1], sh1);
                float k0 = fmaf(sc0, acc[1][mi][nj][i0], sh0), k1 = fmaf(sc1, acc[1][mi][nj][i0+1], sh1);
                float v0 = fmaf(sc0, acc[2][mi][nj][i0], sh0), v1 = fmaf(sc1, acc[2][mi][nj][i0+1], sh1);
                size_t base = (size_t)row*768 + col;
                uint32_t hi, lo;
                split2(q0, q1, hi, lo);
                *(uint32_t*)&g_qh[base] = hi;        *(uint32_t*)&g_ql[base] = lo;
                split2(k0, k1, hi, lo);
                *(uint32_t*)&g_qh[base + 256] = hi;
                split2(v0, v1, hi, lo);
                *(uint32_t*)&g_qh[base + 512] = hi;
            }
}

// ---------------------------------------------------------------------------
// Kernel 2: attention — register-resident softmax, 2-term splits (unchanged
// from R12, validated). One CTA per (seq, head), 512 threads.
// smem: QH 0, QL 10240, KH 20480, VH 30720, PSUM 40960, O4 43008 -> 108544
// ---------------------------------------------------------------------------
#define AT_Q  0
#define AT_QL 10240
#define AT_K  20480
#define AT_V  30720
#define AT_PS 40960
#define AT_O  43008
#define ATTN_SMEM 108544

__global__ __launch_bounds__(512, 1) void attn_kernel()
{
    const int bid  = blockIdx.x;
    const int nseq = bid >> 3;
    const int h    = bid & 7;
    const int t0   = nseq * SEQ;
    const int tid  = threadIdx.x;
    const int wid  = tid >> 5, lane = tid & 31;
    const uint32_t sbase = smem_u32(smraw);

    #pragma unroll
    for (int i = 0; i < 4; ++i) {
        int task = tid + i*512;
        int tensor = task >> 9;
        int within = task & 511;
        int row = within >> 2, seg = within & 3;
        size_t base = (size_t)(t0 + row)*768 + h*EDIM + seg*8;
        const __half* src = (tensor == 0) ? g_qh + base
                          : (tensor == 1) ? g_ql + base
                          : (tensor == 2) ? g_qh + base + 256
                                          : g_qh + base + 512;
        *(uint4*)(smraw + tensor*10240 + row*RSTR + seg*16) = *(const uint4*)src;
    }
    __syncthreads();

    const int wm = (wid >> 2) * 32;
    const int wn = (wid & 3) * 32;
    const int g = lane >> 2, tg = lane & 3;

    float p[2][4][4] = {};
    #pragma unroll
    for (int kb = 0; kb < 2; ++kb) {
        uint32_t aqh[2][4], aql[2][4];
        #pragma unroll
        for (int mi = 0; mi < 2; ++mi) {
            ldsm4(aqh[mi], fragA(sbase + AT_Q,  wm + mi*16, kb, lane));
            ldsm4(aql[mi], fragA(sbase + AT_QL, wm + mi*16, kb, lane));
        }
        #pragma unroll
        for (int nb = 0; nb < 2; ++nb) {
            uint32_t bkh[4];
            ldsm4(bkh, fragA(sbase + AT_K, wn + nb*16, kb, lane));
            #pragma unroll
            for (int mi = 0; mi < 2; ++mi)
                #pragma unroll
                for (int j = 0; j < 2; ++j) {
                    float* d = p[mi][nb*2 + j];
                    mmaf16(d, aqh[mi], bkh[j], bkh[j+2]);
                    mmaf16(d, aql[mi], bkh[j], bkh[j+2]);
                }
        }
    }

    const float scl = 0.17677669529663688f;
    #pragma unroll
    for (int mi = 0; mi < 2; ++mi)
        #pragma unroll
        for (int ni = 0; ni < 4; ++ni)
            #pragma unroll
            for (int r = 0; r < 4; ++r)
                p[mi][ni][r] = __expf(p[mi][ni][r] * scl);

    float* psum = (float*)(smraw + AT_PS);
    float rs[2][2];
    #pragma unroll
    for (int mi = 0; mi < 2; ++mi)
        #pragma unroll
        for (int h2 = 0; h2 < 2; ++h2) {
            float s = 0.f;
            #pragma unroll
            for (int ni = 0; ni < 4; ++ni) s += p[mi][ni][h2*2] + p[mi][ni][h2*2+1];
            s += __shfl_xor_sync(0xffffffffu, s, 1);
            s += __shfl_xor_sync(0xffffffffu, s, 2);
            rs[mi][h2] = s;
        }
    if (tg == 0) {
        #pragma unroll
        for (int mi = 0; mi < 2; ++mi)
            #pragma unroll
            for (int h2 = 0; h2 < 2; ++h2)
                psum[(wm + mi*16 + g + h2*8)*4 + (wid & 3)] = rs[mi][h2];
    }
    __syncthreads();
    #pragma unroll
    for (int mi = 0; mi < 2; ++mi)
        #pragma unroll
        for (int h2 = 0; h2 < 2; ++h2) {
            int row = wm + mi*16 + g + h2*8;
            float4 ps = *(float4*)&psum[row*4];
            float inv = 1.0f / (ps.x + ps.y + ps.z + ps.w);
            #pragma unroll
            for (int ni = 0; ni < 4; ++ni) {
                p[mi][ni][h2*2]   *= inv;
                p[mi][ni][h2*2+1] *= inv;
            }
        }

    uint32_t ah[2][2][4], al[2][2][4];
    #pragma unroll
    for (int mi = 0; mi < 2; ++mi)
        #pragma unroll
        for (int kb2 = 0; kb2 < 2; ++kb2) {
            split2(p[mi][2*kb2][0],   p[mi][2*kb2][1],   ah[mi][kb2][0], al[mi][kb2][0]);
            split2(p[mi][2*kb2][2],   p[mi][2*kb2][3],   ah[mi][kb2][1], al[mi][kb2][1]);
            split2(p[mi][2*kb2+1][0], p[mi][2*kb2+1][1], ah[mi][kb2][2], al[mi][kb2][2]);
            split2(p[mi][2*kb2+1][2], p[mi][2*kb2+1][3], ah[mi][kb2][3], al[mi][kb2][3]);
        }

    float o[2][4][4] = {};
    #pragma unroll
    for (int kb2 = 0; kb2 < 2; ++kb2) {
        uint32_t bh[2][4];
        #pragma unroll
        for (int ch = 0; ch < 2; ++ch) {
            uint32_t vaddr = sbase + AT_V
                + (uint32_t)(wn + kb2*16 + (lane & 15))*RSTR
                + (uint32_t)((lane >> 4) << 4) + (uint32_t)ch*32;
            ldsm4t(bh[ch], vaddr);
        }
        #pragma unroll
        for (int mi = 0; mi < 2; ++mi)
            #pragma unroll
            for (int ch = 0; ch < 2; ++ch)
                #pragma unroll
                for (int j = 0; j < 2; ++j) {
                    float* d = o[mi][ch*2 + j];
                    mmaf16(d, ah[mi][kb2], bh[ch][j*2], bh[ch][j*2+1]);
                    mmaf16(d, al[mi][kb2], bh[ch][j*2], bh[ch][j*2+1]);
                }
    }

    float* O4 = (float*)(smraw + AT_O);
    const int slice = wid & 3;
    #pragma unroll
    for (int mi = 0; mi < 2; ++mi)
        #pragma unroll
        for (int ni = 0; ni < 4; ++ni)
            #pragma unroll
            for (int h2 = 0; h2 < 2; ++h2) {
                int row = wm + mi*16 + g + h2*8;
                int col = ni*8 + tg*2;
                *(float2*)&O4[((size_t)slice*128 + row)*32 + col] =
                    make_float2(o[mi][ni][h2*2], o[mi][ni][h2*2+1]);
            }
    __syncthreads();

    {
        int row = tid >> 2, c0 = (tid & 3) * 8;
        float4 s0 = make_float4(0,0,0,0), s1 = make_float4(0,0,0,0);
        #pragma unroll
        for (int s = 0; s < 4; ++s) {
            float4 a = *(float4*)&O4[((size_t)s*128 + row)*32 + c0];
            float4 b = *(float4*)&O4[((size_t)s*128 + row)*32 + c0 + 4];
            s0.x += a.x; s0.y += a.y; s0.z += a.z; s0.w += a.w;
            s1.x += b.x; s1.y += b.y; s1.z += b.z; s1.w += b.w;
        }
        uint32_t h0,h1,h2_,h3, l0,l1,l2,l3;
        split2(s0.x, s0.y, h0, l0);
        split2(s0.z, s0.w, h1, l1);
        split2(s1.x, s1.y, h2_, l2);
        split2(s1.z, s1.w, h3, l3);
        size_t base = (size_t)(t0 + row)*CCH + h*EDIM + c0;
        *(uint4*)&g_oh[base] = make_uint4(h0, h1, h2_, h3);
        *(uint4*)&g_ol[base] = make_uint4(l0, l1, l2, l3);
    }
}

// ---------------------------------------------------------------------------
// Kernel 3: out = O @ Wout^T (3-term, unchanged). CTA 128x128, 512 threads.
// buffer: AH 0, AL 10240, BH 20480, BL 30720 -> 40960/buf
// ---------------------------------------------------------------------------
#define OU_BUF 40960
#define OUT_SMEM (2*OU_BUF)

__global__ __launch_bounds__(512, 1) void out_kernel(float* __restrict__ out)
{
    const int tid = threadIdx.x;
    const int wid = tid >> 5, lane = tid & 31;
    const int n0 = blockIdx.x * 128;
    const int m0 = blockIdx.y * 128;
    const uint32_t sbase = smem_u32(smraw);

    auto issue = [&](int c, int b) {
        const int k0 = c * 32;
        const uint32_t sb = sbase + b * OU_BUF;
        int row = tid >> 2, seg = tid & 3;
        uint32_t so = (uint32_t)(row*RSTR + seg*16);
        size_t ga = (size_t)(m0 + row)*CCH + k0 + seg*8;
        CP16(sb + so,         g_oh + ga);
        CP16(sb + 10240 + so, g_ol + ga);
        size_t gb = (size_t)5*65536 + (size_t)(n0 + row)*CCH + k0 + seg*8;
        CP16(sb + 20480 + so, g_wh + gb);
        CP16(sb + 30720 + so, g_wl + gb);
    };

    float acc[2][4][4] = {};
    const int wm = (wid >> 2) * 32;
    const int wn = (wid & 3) * 32;

    auto compute = [&](uint32_t sb) {
        #pragma unroll
        for (int kb = 0; kb < 2; ++kb) {
            uint32_t ah[2][4], al[2][4];
            #pragma unroll
            for (int mi = 0; mi < 2; ++mi) {
                ldsm4(ah[mi], fragA(sb,         wm + mi*16, kb, lane));
                ldsm4(al[mi], fragA(sb + 10240, wm + mi*16, kb, lane));
            }
            #pragma unroll
            for (int nb = 0; nb < 2; ++nb) {
                uint32_t bh[4], bl[4];
                ldsm4(bh, fragA(sb + 20480, wn + nb*16, kb, lane));
                ldsm4(bl, fragA(sb + 30720, wn + nb*16, kb, lane));
                #pragma unroll
                for (int mi = 0; mi < 2; ++mi)
                    #pragma unroll
                    for (int j = 0; j < 2; ++j) {
                        float* d = acc[mi][nb*2 + j];
                        mmaf16(d, ah[mi], bh[j], bh[j+2]);
                        mmaf16(d, al[mi], bh[j], bh[j+2]);
                        mmaf16(d, ah[mi], bl[j], bl[j+2]);
                    }
            }
        }
    };

    issue(0, 0); CPCOMMIT();
    CPWAIT0(); __syncthreads();
    #pragma unroll 1
    for (int c = 0; c < 8; ++c) {
        if (c < 7) { issue(c + 1, (c + 1) & 1); CPCOMMIT(); }
        compute(sbase + (c & 1) * OU_BUF);
        if (c < 7) { CPWAIT0(); __syncthreads(); }
    }

    const int g = lane >> 2, tg = lane & 3;
    #pragma unroll
    for (int mi = 0; mi < 2; ++mi)
        #pragma unroll
        for (int ni = 0; ni < 4; ++ni)
            #pragma unroll
            for (int h2 = 0; h2 < 2; ++h2) {
                const int row = m0 + wm + mi*16 + g + h2*8;
                const int col = n0 + wn + ni*8 + tg*2;
                *(float2*)&out[(size_t)row*CCH + col] =
                    make_float2(acc[mi][ni][h2*2], acc[mi][ni][h2*2+1]);
            }
}

// ---------------------------------------------------------------------------
extern "C" void kernel_launch(void* const* d_in, const int* in_sizes, int n_in,
                              void* d_out, int out_size)
{
    (void)in_sizes; (void)n_in; (void)out_size;
    const float* X      = (const float*)d_in[0];
    const float* CTX    = (const float*)d_in[1];
    const float* Wq     = (const float*)d_in[2];
    const float* Wkv    = (const float*)d_in[3];
    const float* Wout   = (const float*)d_in[4];
    const float* Wscale = (const float*)d_in[5];
    const float* Wshift = (const float*)d_in[6];
    float* out = (float*)d_out;

    __half *xh, *xl, *ch, *cl, *wh, *wl;
    cudaGetSymbolAddress((void**)&xh, g_xh);
    cudaGetSymbolAddress((void**)&xl, g_xl);
    cudaGetSymbolAddress((void**)&ch, g_ch);
    cudaGetSymbolAddress((void**)&cl, g_cl);
    cudaGetSymbolAddress((void**)&wh, g_wh);
    cudaGetSymbolAddress((void**)&wl, g_wl);

    cudaFuncSetAttribute(proj_kernel, cudaFuncAttributeMaxDynamicSharedMemorySize, PROJ_SMEM);
    cudaFuncSetAttribute(attn_kernel, cudaFuncAttributeMaxDynamicSharedMemorySize, ATTN_SMEM);
    cudaFuncSetAttribute(out_kernel,  cudaFuncAttributeMaxDynamicSharedMemorySize, OUT_SMEM);

    conv_kernel<<<4096, 256>>>((const float4*)X,   (uint2*)xh, (uint2*)xl, TOK*64);
    conv_kernel<<<4096, 256>>>((const float4*)CTX, (uint2*)ch, (uint2*)cl, TOK*64);
    conv_hi_kernel<<<64, 256>>>((const float4*)Wq,     (uint2*)(wh + 0*65536), 16384);
    conv_hi_kernel<<<128, 256>>>((const float4*)Wkv,   (uint2*)(wh + 1*65536), 32768);
    conv_hi_kernel<<<64, 256>>>((const float4*)Wscale, (uint2*)(wh + 3*65536), 16384);
    conv_hi_kernel<<<64, 256>>>((const float4*)Wshift, (uint2*)(wh + 4*65536), 16384);
    conv_kernel<<<64, 256>>>((const float4*)Wout,      (uint2*)(wh + 5*65536), (uint2*)(wl + 5*65536), 16384);

    proj_kernel<<<dim3(4, 1024), 256, PROJ_SMEM>>>();
    attn_kernel<<<NSEQ*NHEADS, 512, ATTN_SMEM>>>();
    out_kernel<<<dim3(2, 1024), 512, OUT_SMEM>>>(out);
}

// round 15
// speedup vs baseline: 4.0037x; 1.2534x over previous
#include <cuda_runtime.h>
#include <cuda_fp16.h>
#include <cstdint>

#define TOK   131072
#define CCH   256
#define SEQ   128
#define NSEQ  1024
#define NHEADS 8
#define EDIM  32

// fp16 hi/lo global buffers (split precision: x = hi + lo)
__device__ __half g_xh[(size_t)TOK * 256], g_xl[(size_t)TOK * 256];
__device__ __half g_ch[(size_t)TOK * 256], g_cl[(size_t)TOK * 256];
__device__ __half g_wh[6 * 65536], g_wl[6 * 65536];   // Wq, Wk, Wv, Wscale, Wshift, Wout
__device__ __half g_oh[(size_t)TOK * 256], g_ol[(size_t)TOK * 256];  // attention out

extern __shared__ __align__(16) char smraw[];

// ---------------- helpers ----------------
__device__ __forceinline__ uint32_t smem_u32(const void* p) {
    uint32_t a;
    asm("{ .reg .u64 t; cvta.to.shared.u64 t, %1; cvt.u32.u64 %0, t; }" : "=r"(a) : "l"(p));
    return a;
}
__device__ __forceinline__ void ldsm4(uint32_t* r, uint32_t a) {
    asm volatile("ldmatrix.sync.aligned.m8n8.x4.shared.b16 {%0,%1,%2,%3}, [%4];"
        : "=r"(r[0]), "=r"(r[1]), "=r"(r[2]), "=r"(r[3]) : "r"(a));
}
__device__ __forceinline__ void ldsm4t(uint32_t* r, uint32_t a) {
    asm volatile("ldmatrix.sync.aligned.m8n8.x4.trans.shared.b16 {%0,%1,%2,%3}, [%4];"
        : "=r"(r[0]), "=r"(r[1]), "=r"(r[2]), "=r"(r[3]) : "r"(a));
}
__device__ __forceinline__ void mmaf16(float* d, const uint32_t* a, uint32_t b0, uint32_t b1) {
    asm volatile("mma.sync.aligned.m16n8k16.row.col.f32.f16.f16.f32 "
        "{%0,%1,%2,%3}, {%4,%5,%6,%7}, {%8,%9}, {%0,%1,%2,%3};"
        : "+f"(d[0]), "+f"(d[1]), "+f"(d[2]), "+f"(d[3])
        : "r"(a[0]), "r"(a[1]), "r"(a[2]), "r"(a[3]), "r"(b0), "r"(b1));
}
#define CP16(s, g) asm volatile("cp.async.cg.shared.global [%0], [%1], 16;" :: "r"(s), "l"(g))
#define CPCOMMIT() asm volatile("cp.async.commit_group;")
#define CPWAIT0()  asm volatile("cp.async.wait_group 0;")

struct H4 { uint2 hi, lo; };
__device__ __forceinline__ H4 splitf4(float4 v) {
    __half2 h0 = __floats2half2_rn(v.x, v.y);
    __half2 h1 = __floats2half2_rn(v.z, v.w);
    float2 f0 = __half22float2(h0), f1 = __half22float2(h1);
    __half2 l0 = __floats2half2_rn(v.x - f0.x, v.y - f0.y);
    __half2 l1 = __floats2half2_rn(v.z - f1.x, v.w - f1.y);
    H4 r;
    r.hi.x = *(uint32_t*)&h0; r.hi.y = *(uint32_t*)&h1;
    r.lo.x = *(uint32_t*)&l0; r.lo.y = *(uint32_t*)&l1;
    return r;
}
__device__ __forceinline__ void split2(float a, float b, uint32_t& hi, uint32_t& lo) {
    __half2 h = __floats2half2_rn(a, b);
    float2 f = __half22float2(h);
    __half2 l = __floats2half2_rn(a - f.x, b - f.y);
    hi = *(uint32_t*)&h; lo = *(uint32_t*)&l;
}

#define RSTR 80   // 32 halves (64B) padded to 80B -> conflict-free ldmatrix
__device__ __forceinline__ uint32_t fragA(uint32_t matbase, int row0, int kb, int lane) {
    return matbase + (uint32_t)(row0 + (lane & 15)) * RSTR
                   + (uint32_t)(kb * 32 + ((lane >> 4) << 4));
}

// ---------------------------------------------------------------------------
// Kernel 0: fp32 -> fp16 hi/lo convert; hi-only variant for 2-term B weights.
// ---------------------------------------------------------------------------
__global__ __launch_bounds__(256) void conv_kernel(
    const float4* __restrict__ s, uint2* __restrict__ dh, uint2* __restrict__ dl, int n)
{
    for (int i = blockIdx.x * blockDim.x + threadIdx.x; i < n; i += gridDim.x * blockDim.x) {
        H4 h = splitf4(s[i]);
        dh[i] = h.hi; dl[i] = h.lo;
    }
}
__global__ __launch_bounds__(256) void conv_hi_kernel(
    const float4* __restrict__ s, uint2* __restrict__ dh, int n)
{
    for (int i = blockIdx.x * blockDim.x + threadIdx.x; i < n; i += gridDim.x * blockDim.x) {
        float4 v = s[i];
        __half2 h0 = __floats2half2_rn(v.x, v.y);
        __half2 h1 = __floats2half2_rn(v.z, v.w);
        dh[i] = make_uint2(*(uint32_t*)&h0, *(uint32_t*)&h1);
    }
}

// ---------------------------------------------------------------------------
// Kernel 1: FUSED projection + attention.
// CTA = one sequence (128 tokens, blockIdx.y) x one head-pair (64 channels,
// blockIdx.x). Phase 1: 5-tensor 2-term GEMM (R13-validated). Epilogue writes
// q(hi/lo), k(hi), v(hi) to SMEM per head. Phase 2: attention — 4 warps per
// head, each warp owns a full 32x128 S stripe (warp-local softmax, full-K SV,
// direct O writes). No q/k/v global round-trip.
// GEMM buffers: XH 0, XL 10240, CH 20480, CL 30720, W t: 40960+t*5120 -> 66560
// Attn tiles (after GEMM): head hh at hh*40960: QH 0, QL 10240, KH 20480, VH 30720
// ---------------------------------------------------------------------------
#define PJ_BUF 66560
#define PROJ_SMEM (2*PJ_BUF)

__global__ __launch_bounds__(256, 1) void proj_attn_kernel()
{
    const int tid = threadIdx.x;
    const int wid = tid >> 5, lane = tid & 31;
    const int n0 = blockIdx.x * 64;
    const int m0 = blockIdx.y * 128;   // == t0 (sequence start)
    const uint32_t sbase = smem_u32(smraw);

    auto issue = [&](int c, int b) {
        const int k0 = c * 32;
        const uint32_t sb = sbase + b * PJ_BUF;
        #pragma unroll
        for (int u = 0; u < 2; ++u) {
            int idx = tid + u*256;
            int row = idx >> 2, seg = idx & 3;
            uint32_t so = (uint32_t)(row*RSTR + seg*16);
            size_t gi = (size_t)(m0 + row)*CCH + k0 + seg*8;
            CP16(sb + so,         g_xh + gi);
            CP16(sb + 10240 + so, g_xl + gi);
            CP16(sb + 20480 + so, g_ch + gi);
            CP16(sb + 30720 + so, g_cl + gi);
        }
        {
            int r = tid >> 2, seg = tid & 3;
            uint32_t so = (uint32_t)(r*RSTR + seg*16);
            #pragma unroll
            for (int t = 0; t < 5; ++t) {
                const __half* src = g_wh + (size_t)t*65536
                                  + (size_t)(n0 + r)*CCH + k0 + seg*8;
                CP16(sb + 40960 + t*5120 + so, src);
            }
        }
    };

    float acc[5][2][4][4] = {};   // [tensor][mi][nj][4]
    const int wm = (wid >> 1) * 32;
    const int hh = wid & 1;       // head within pair (channel half)

    auto compute = [&](uint32_t sb) {
        const int wn = hh * 32;
        #pragma unroll
        for (int kb = 0; kb < 2; ++kb) {
            uint32_t axh[2][4], axl[2][4], ach[2][4], acl[2][4];
            #pragma unroll
            for (int mi = 0; mi < 2; ++mi) {
                ldsm4(axh[mi], fragA(sb,         wm + mi*16, kb, lane));
                ldsm4(axl[mi], fragA(sb + 10240, wm + mi*16, kb, lane));
                ldsm4(ach[mi], fragA(sb + 20480, wm + mi*16, kb, lane));
                ldsm4(acl[mi], fragA(sb + 30720, wm + mi*16, kb, lane));
            }
            #pragma unroll
            for (int t = 0; t < 5; ++t) {
                const uint32_t (*Ah)[4] = (t < 3) ? axh : ach;
                const uint32_t (*Al)[4] = (t < 3) ? axl : acl;
                #pragma unroll
                for (int nb = 0; nb < 2; ++nb) {
                    uint32_t bh[4];
                    ldsm4(bh, fragA(sb + 40960 + t*5120, wn + nb*16, kb, lane));
                    #pragma unroll
                    for (int mi = 0; mi < 2; ++mi)
                        #pragma unroll
                        for (int j = 0; j < 2; ++j) {
                            float* d = acc[t][mi][nb*2 + j];
                            mmaf16(d, Ah[mi], bh[j], bh[j+2]);
                            mmaf16(d, Al[mi], bh[j], bh[j+2]);
                        }
                }
            }
        }
    };

    issue(0, 0); CPCOMMIT();
    CPWAIT0(); __syncthreads();
    #pragma unroll 1
    for (int c = 0; c < 8; ++c) {
        if (c < 7) { issue(c + 1, (c + 1) & 1); CPCOMMIT(); }
        compute(sbase + (c & 1) * PJ_BUF);
        if (c < 7) { CPWAIT0(); __syncthreads(); }
    }
    __syncthreads();   // all reads of GEMM buffers done before tiles are overwritten

    // --- Epilogue: scale*x+shift; write q(hi/lo), k(hi), v(hi) to SMEM ---
    const int g = lane >> 2, tg = lane & 3;
    const uint32_t abase = sbase + hh * 40960;
    #pragma unroll
    for (int mi = 0; mi < 2; ++mi)
        #pragma unroll
        for (int nj = 0; nj < 4; ++nj)
            #pragma unroll
            for (int h2 = 0; h2 < 2; ++h2) {
                const int row = wm + mi*16 + g + h2*8;        // token within seq
                const int col = nj*8 + tg*2;                  // channel within head
                const int i0 = h2*2;
                float sc0 = acc[3][mi][nj][i0],   sc1 = acc[3][mi][nj][i0+1];
                float sh0 = acc[4][mi][nj][i0],   sh1 = acc[4][mi][nj][i0+1];
                float q0 = fmaf(sc0, acc[0][mi][nj][i0], sh0), q1 = fmaf(sc1, acc[0][mi][nj][i0+1], sh1);
                float k0 = fmaf(sc0, acc[1][mi][nj][i0], sh0), k1 = fmaf(sc1, acc[1][mi][nj][i0+1], sh1);
                float v0 = fmaf(sc0, acc[2][mi][nj][i0], sh0), v1 = fmaf(sc1, acc[2][mi][nj][i0+1], sh1);
                uint32_t off = (uint32_t)(row*RSTR + col*2);
                uint32_t hi, lo;
                split2(q0, q1, hi, lo);
                *(uint32_t*)(smraw + (abase - sbase) + off)         = hi;   // QH
                *(uint32_t*)(smraw + (abase - sbase) + 10240 + off) = lo;   // QL
                split2(k0, k1, hi, lo);
                *(uint32_t*)(smraw + (abase - sbase) + 20480 + off) = hi;   // KH
                split2(v0, v1, hi, lo);
                *(uint32_t*)(smraw + (abase - sbase) + 30720 + off) = hi;   // VH
            }
    __syncthreads();

    // --- Attention phase: warp = (head hh, row stripe wm). S stripe 32x128. ---
    float p[2][16][4] = {};
    #pragma unroll
    for (int kb = 0; kb < 2; ++kb) {
        uint32_t aqh[2][4], aql[2][4];
        #pragma unroll
        for (int mi = 0; mi < 2; ++mi) {
            ldsm4(aqh[mi], fragA(abase,         wm + mi*16, kb, lane));
            ldsm4(aql[mi], fragA(abase + 10240, wm + mi*16, kb, lane));
        }
        #pragma unroll
        for (int nb = 0; nb < 8; ++nb) {
            uint32_t bkh[4];
            ldsm4(bkh, fragA(abase + 20480, nb*16, kb, lane));
            #pragma unroll
            for (int mi = 0; mi < 2; ++mi)
                #pragma unroll
                for (int j = 0; j < 2; ++j) {
                    float* d = p[mi][nb*2 + j];
                    mmaf16(d, aqh[mi], bkh[j], bkh[j+2]);
                    mmaf16(d, aql[mi], bkh[j], bkh[j+2]);
                }
        }
    }

    const float scl = 0.17677669529663688f;  // 1/sqrt(32)
    #pragma unroll
    for (int mi = 0; mi < 2; ++mi)
        #pragma unroll
        for (int nb = 0; nb < 16; ++nb)
            #pragma unroll
            for (int r = 0; r < 4; ++r)
                p[mi][nb][r] = __expf(p[mi][nb][r] * scl);

    // warp-local row softmax (each warp owns full 128 cols of its rows)
    #pragma unroll
    for (int mi = 0; mi < 2; ++mi)
        #pragma unroll
        for (int h2 = 0; h2 < 2; ++h2) {
            float s = 0.f;
            #pragma unroll
            for (int nb = 0; nb < 16; ++nb) s += p[mi][nb][h2*2] + p[mi][nb][h2*2+1];
            s += __shfl_xor_sync(0xffffffffu, s, 1);
            s += __shfl_xor_sync(0xffffffffu, s, 2);
            const float inv = 1.0f / s;
            #pragma unroll
            for (int nb = 0; nb < 16; ++nb) {
                p[mi][nb][h2*2]   *= inv;
                p[mi][nb][h2*2+1] *= inv;
            }
        }

    // SV: full K range per warp; P C-frags -> A-frags per 16-wide k block
    float o[2][4][4] = {};
    #pragma unroll
    for (int kk = 0; kk < 8; ++kk) {
        uint32_t ah[2][4], al[2][4];
        #pragma unroll
        for (int mi = 0; mi < 2; ++mi) {
            split2(p[mi][2*kk][0],   p[mi][2*kk][1],   ah[mi][0], al[mi][0]);
            split2(p[mi][2*kk][2],   p[mi][2*kk][3],   ah[mi][1], al[mi][1]);
            split2(p[mi][2*kk+1][0], p[mi][2*kk+1][1], ah[mi][2], al[mi][2]);
            split2(p[mi][2*kk+1][2], p[mi][2*kk+1][3], ah[mi][3], al[mi][3]);
        }
        uint32_t bh[2][4];
        #pragma unroll
        for (int ch = 0; ch < 2; ++ch) {
            uint32_t vaddr = abase + 30720
                + (uint32_t)(kk*16 + (lane & 15))*RSTR
                + (uint32_t)((lane >> 4) << 4) + (uint32_t)ch*32;
            ldsm4t(bh[ch], vaddr);
        }
        #pragma unroll
        for (int mi = 0; mi < 2; ++mi)
            #pragma unroll
            for (int ch = 0; ch < 2; ++ch)
                #pragma unroll
                for (int j = 0; j < 2; ++j) {
                    float* d = o[mi][ch*2 + j];
                    mmaf16(d, ah[mi], bh[ch][j*2], bh[ch][j*2+1]);
                    mmaf16(d, al[mi], bh[ch][j*2], bh[ch][j*2+1]);
                }
    }

    // direct O writes (hi/lo) — no cross-warp reduction needed
    const int hcol = (blockIdx.x*2 + hh) * EDIM;
    #pragma unroll
    for (int mi = 0; mi < 2; ++mi)
        #pragma unroll
        for (int nj = 0; nj < 4; ++nj)
            #pragma unroll
            for (int h2 = 0; h2 < 2; ++h2) {
                int row = m0 + wm + mi*16 + g + h2*8;
                int col = hcol + nj*8 + tg*2;
                uint32_t hi, lo;
                split2(o[mi][nj][h2*2], o[mi][nj][h2*2+1], hi, lo);
                *(uint32_t*)&g_oh[(size_t)row*CCH + col] = hi;
                *(uint32_t*)&g_ol[(size_t)row*CCH + col] = lo;
            }
}

// ---------------------------------------------------------------------------
// Kernel 3: out = O @ Wout^T (3-term, unchanged). CTA 128x128, 512 threads.
// buffer: AH 0, AL 10240, BH 20480, BL 30720 -> 40960/buf
// ---------------------------------------------------------------------------
#define OU_BUF 40960
#define OUT_SMEM (2*OU_BUF)

__global__ __launch_bounds__(512, 1) void out_kernel(float* __restrict__ out)
{
    const int tid = threadIdx.x;
    const int wid = tid >> 5, lane = tid & 31;
    const int n0 = blockIdx.x * 128;
    const int m0 = blockIdx.y * 128;
    const uint32_t sbase = smem_u32(smraw);

    auto issue = [&](int c, int b) {
        const int k0 = c * 32;
        const uint32_t sb = sbase + b * OU_BUF;
        int row = tid >> 2, seg = tid & 3;
        uint32_t so = (uint32_t)(row*RSTR + seg*16);
        size_t ga = (size_t)(m0 + row)*CCH + k0 + seg*8;
        CP16(sb + so,         g_oh + ga);
        CP16(sb + 10240 + so, g_ol + ga);
        size_t gb = (size_t)5*65536 + (size_t)(n0 + row)*CCH + k0 + seg*8;
        CP16(sb + 20480 + so, g_wh + gb);
        CP16(sb + 30720 + so, g_wl + gb);
    };

    float acc[2][4][4] = {};
    const int wm = (wid >> 2) * 32;
    const int wn = (wid & 3) * 32;

    auto compute = [&](uint32_t sb) {
        #pragma unroll
        for (int kb = 0; kb < 2; ++kb) {
            uint32_t ah[2][4], al[2][4];
            #pragma unroll
            for (int mi = 0; mi < 2; ++mi) {
                ldsm4(ah[mi], fragA(sb,         wm + mi*16, kb, lane));
                ldsm4(al[mi], fragA(sb + 10240, wm + mi*16, kb, lane));
            }
            #pragma unroll
            for (int nb = 0; nb < 2; ++nb) {
                uint32_t bh[4], bl[4];
                ldsm4(bh, fragA(sb + 20480, wn + nb*16, kb, lane));
                ldsm4(bl, fragA(sb + 30720, wn + nb*16, kb, lane));
                #pragma unroll
                for (int mi = 0; mi < 2; ++mi)
                    #pragma unroll
                    for (int j = 0; j < 2; ++j) {
                        float* d = acc[mi][nb*2 + j];
                        mmaf16(d, ah[mi], bh[j], bh[j+2]);
                        mmaf16(d, al[mi], bh[j], bh[j+2]);
                        mmaf16(d, ah[mi], bl[j], bl[j+2]);
                    }
            }
        }
    };

    issue(0, 0); CPCOMMIT();
    CPWAIT0(); __syncthreads();
    #pragma unroll 1
    for (int c = 0; c < 8; ++c) {
        if (c < 7) { issue(c + 1, (c + 1) & 1); CPCOMMIT(); }
        compute(sbase + (c & 1) * OU_BUF);
        if (c < 7) { CPWAIT0(); __syncthreads(); }
    }

    const int g = lane >> 2, tg = lane & 3;
    #pragma unroll
    for (int mi = 0; mi < 2; ++mi)
        #pragma unroll
        for (int ni = 0; ni < 4; ++ni)
            #pragma unroll
            for (int h2 = 0; h2 < 2; ++h2) {
                const int row = m0 + wm + mi*16 + g + h2*8;
                const int col = n0 + wn + ni*8 + tg*2;
                *(float2*)&out[(size_t)row*CCH + col] =
                    make_float2(acc[mi][ni][h2*2], acc[mi][ni][h2*2+1]);
            }
}

// ---------------------------------------------------------------------------
extern "C" void kernel_launch(void* const* d_in, const int* in_sizes, int n_in,
                              void* d_out, int out_size)
{
    (void)in_sizes; (void)n_in; (void)out_size;
    const float* X      = (const float*)d_in[0];
    const float* CTX    = (const float*)d_in[1];
    const float* Wq     = (const float*)d_in[2];
    const float* Wkv    = (const float*)d_in[3];
    const float* Wout   = (const float*)d_in[4];
    const float* Wscale = (const float*)d_in[5];
    const float* Wshift = (const float*)d_in[6];
    float* out = (float*)d_out;

    __half *xh, *xl, *ch, *cl, *wh, *wl;
    cudaGetSymbolAddress((void**)&xh, g_xh);
    cudaGetSymbolAddress((void**)&xl, g_xl);
    cudaGetSymbolAddress((void**)&ch, g_ch);
    cudaGetSymbolAddress((void**)&cl, g_cl);
    cudaGetSymbolAddress((void**)&wh, g_wh);
    cudaGetSymbolAddress((void**)&wl, g_wl);

    cudaFuncSetAttribute(proj_attn_kernel, cudaFuncAttributeMaxDynamicSharedMemorySize, PROJ_SMEM);
    cudaFuncSetAttribute(out_kernel,       cudaFuncAttributeMaxDynamicSharedMemorySize, OUT_SMEM);

    conv_kernel<<<4096, 256>>>((const float4*)X,   (uint2*)xh, (uint2*)xl, TOK*64);
    conv_kernel<<<4096, 256>>>((const float4*)CTX, (uint2*)ch, (uint2*)cl, TOK*64);
    conv_hi_kernel<<<64, 256>>>((const float4*)Wq,     (uint2*)(wh + 0*65536), 16384);
    conv_hi_kernel<<<128, 256>>>((const float4*)Wkv,   (uint2*)(wh + 1*65536), 32768);
    conv_hi_kernel<<<64, 256>>>((const float4*)Wscale, (uint2*)(wh + 3*65536), 16384);
    conv_hi_kernel<<<64, 256>>>((const float4*)Wshift, (uint2*)(wh + 4*65536), 16384);
    conv_kernel<<<64, 256>>>((const float4*)Wout,      (uint2*)(wh + 5*65536), (uint2*)(wl + 5*65536), 16384);

    proj_attn_kernel<<<dim3(4, 1024), 256, PROJ_SMEM>>>();
    out_kernel<<<dim3(2, 1024), 512, OUT_SMEM>>>(out);
}

// round 16
// speedup vs baseline: 4.4382x; 1.1085x over previous
#include <cuda_runtime.h>
#include <cuda_fp16.h>
#include <cstdint>

#define TOK   131072
#define CCH   256
#define SEQ   128
#define NSEQ  1024
#define NHEADS 8
#define EDIM  32

// fp16 global buffers
__device__ __half g_wh[6 * 65536], g_wl[6 * 65536];   // Wq, Wk, Wv, Wscale, Wshift, Wout
__device__ __half g_oh[(size_t)TOK * 256], g_ol[(size_t)TOK * 256];  // attention out

extern __shared__ __align__(16) char smraw[];

// ---------------- helpers ----------------
__device__ __forceinline__ uint32_t smem_u32(const void* p) {
    uint32_t a;
    asm("{ .reg .u64 t; cvta.to.shared.u64 t, %1; cvt.u32.u64 %0, t; }" : "=r"(a) : "l"(p));
    return a;
}
__device__ __forceinline__ void ldsm4(uint32_t* r, uint32_t a) {
    asm volatile("ldmatrix.sync.aligned.m8n8.x4.shared.b16 {%0,%1,%2,%3}, [%4];"
        : "=r"(r[0]), "=r"(r[1]), "=r"(r[2]), "=r"(r[3]) : "r"(a));
}
__device__ __forceinline__ void ldsm4t(uint32_t* r, uint32_t a) {
    asm volatile("ldmatrix.sync.aligned.m8n8.x4.trans.shared.b16 {%0,%1,%2,%3}, [%4];"
        : "=r"(r[0]), "=r"(r[1]), "=r"(r[2]), "=r"(r[3]) : "r"(a));
}
__device__ __forceinline__ void mmaf16(float* d, const uint32_t* a, uint32_t b0, uint32_t b1) {
    asm volatile("mma.sync.aligned.m16n8k16.row.col.f32.f16.f16.f32 "
        "{%0,%1,%2,%3}, {%4,%5,%6,%7}, {%8,%9}, {%0,%1,%2,%3};"
        : "+f"(d[0]), "+f"(d[1]), "+f"(d[2]), "+f"(d[3])
        : "r"(a[0]), "r"(a[1]), "r"(a[2]), "r"(a[3]), "r"(b0), "r"(b1));
}
#define CP16(s, g) asm volatile("cp.async.cg.shared.global [%0], [%1], 16;" :: "r"(s), "l"(g))
#define CPCOMMIT() asm volatile("cp.async.commit_group;")
#define CPWAIT0()  asm volatile("cp.async.wait_group 0;")

struct H4 { uint2 hi, lo; };
__device__ __forceinline__ H4 splitf4(float4 v) {
    __half2 h0 = __floats2half2_rn(v.x, v.y);
    __half2 h1 = __floats2half2_rn(v.z, v.w);
    float2 f0 = __half22float2(h0), f1 = __half22float2(h1);
    __half2 l0 = __floats2half2_rn(v.x - f0.x, v.y - f0.y);
    __half2 l1 = __floats2half2_rn(v.z - f1.x, v.w - f1.y);
    H4 r;
    r.hi.x = *(uint32_t*)&h0; r.hi.y = *(uint32_t*)&h1;
    r.lo.x = *(uint32_t*)&l0; r.lo.y = *(uint32_t*)&l1;
    return r;
}
__device__ __forceinline__ void split2(float a, float b, uint32_t& hi, uint32_t& lo) {
    __half2 h = __floats2half2_rn(a, b);
    float2 f = __half22float2(h);
    __half2 l = __floats2half2_rn(a - f.x, b - f.y);
    hi = *(uint32_t*)&h; lo = *(uint32_t*)&l;
}

#define RSTR 80   // 32 halves (64B) padded to 80B -> conflict-free ldmatrix
__device__ __forceinline__ uint32_t fragA(uint32_t matbase, int row0, int kb, int lane) {
    return matbase + (uint32_t)(row0 + (lane & 15)) * RSTR
                   + (uint32_t)(kb * 32 + ((lane >> 4) << 4));
}

// ---------------------------------------------------------------------------
// Kernel 0: weight conversion only (tiny). hi/lo and hi-only variants.
// ---------------------------------------------------------------------------
__global__ __launch_bounds__(256) void conv_kernel(
    const float4* __restrict__ s, uint2* __restrict__ dh, uint2* __restrict__ dl, int n)
{
    for (int i = blockIdx.x * blockDim.x + threadIdx.x; i < n; i += gridDim.x * blockDim.x) {
        H4 h = splitf4(s[i]);
        dh[i] = h.hi; dl[i] = h.lo;
    }
}
__global__ __launch_bounds__(256) void conv_hi_kernel(
    const float4* __restrict__ s, uint2* __restrict__ dh, int n)
{
    for (int i = blockIdx.x * blockDim.x + threadIdx.x; i < n; i += gridDim.x * blockDim.x) {
        float4 v = s[i];
        __half2 h0 = __floats2half2_rn(v.x, v.y);
        __half2 h1 = __floats2half2_rn(v.z, v.w);
        dh[i] = make_uint2(*(uint32_t*)&h0, *(uint32_t*)&h1);
    }
}

// ---------------------------------------------------------------------------
// Kernel 1: FUSED projection + attention (R14-validated), now reading X/CTX
// directly in fp32 (LDG + in-register hi/lo split + STS fp16), no conv pass.
// CTA = one sequence (blockIdx.y) x one head-pair (blockIdx.x).
// GEMM buffers: XH 0, XL 10240, CH 20480, CL 30720, W t: 40960+t*5120 -> 66560
// Attn tiles (after GEMM): head hh at hh*40960: QH 0, QL 10240, KH 20480, VH 30720
// ---------------------------------------------------------------------------
#define PJ_BUF 66560
#define PROJ_SMEM (2*PJ_BUF)

__global__ __launch_bounds__(256, 1) void proj_attn_kernel(
    const float* __restrict__ X, const float* __restrict__ CTX)
{
    const int tid = threadIdx.x;
    const int wid = tid >> 5, lane = tid & 31;
    const int n0 = blockIdx.x * 64;
    const int m0 = blockIdx.y * 128;   // == t0 (sequence start)
    const uint32_t sbase = smem_u32(smraw);

    float4 rx[4], rc[4];
    auto ldgA = [&](int c) {
        const int k0 = c * 32;
        #pragma unroll
        for (int u = 0; u < 4; ++u) {
            int idx = tid + u*256;              // 0..1023
            int r = idx >> 3, f = idx & 7;      // row 0..127, seg 0..7 (4 floats)
            size_t gi = (size_t)(m0 + r)*CCH + k0 + f*4;
            rx[u] = *(const float4*)&X[gi];
            rc[u] = *(const float4*)&CTX[gi];
        }
    };
    auto stsA = [&](int b) {
        char* p = smraw + b * PJ_BUF;
        #pragma unroll
        for (int u = 0; u < 4; ++u) {
            int idx = tid + u*256;
            int r = idx >> 3, f = idx & 7;
            uint32_t off = (uint32_t)(r*RSTR + f*8);
            H4 hx = splitf4(rx[u]);
            *(uint2*)(p + off)         = hx.hi;   // XH
            *(uint2*)(p + 10240 + off) = hx.lo;   // XL
            H4 hc = splitf4(rc[u]);
            *(uint2*)(p + 20480 + off) = hc.hi;   // CH
            *(uint2*)(p + 30720 + off) = hc.lo;   // CL
        }
    };
    auto issueW = [&](int c, int b) {
        const int k0 = c * 32;
        const uint32_t sb = sbase + b * PJ_BUF;
        int r = tid >> 2, seg = tid & 3;
        uint32_t so = (uint32_t)(r*RSTR + seg*16);
        #pragma unroll
        for (int t = 0; t < 5; ++t) {
            const __half* src = g_wh + (size_t)t*65536
                              + (size_t)(n0 + r)*CCH + k0 + seg*8;
            CP16(sb + 40960 + t*5120 + so, src);
        }
    };

    float acc[5][2][4][4] = {};   // [tensor][mi][nj][4]
    const int wm = (wid >> 1) * 32;
    const int hh = wid & 1;       // head within pair (channel half)

    auto compute = [&](uint32_t sb) {
        const int wn = hh * 32;
        #pragma unroll
        for (int kb = 0; kb < 2; ++kb) {
            uint32_t axh[2][4], axl[2][4], ach[2][4], acl[2][4];
            #pragma unroll
            for (int mi = 0; mi < 2; ++mi) {
                ldsm4(axh[mi], fragA(sb,         wm + mi*16, kb, lane));
                ldsm4(axl[mi], fragA(sb + 10240, wm + mi*16, kb, lane));
                ldsm4(ach[mi], fragA(sb + 20480, wm + mi*16, kb, lane));
                ldsm4(acl[mi], fragA(sb + 30720, wm + mi*16, kb, lane));
            }
            #pragma unroll
            for (int t = 0; t < 5; ++t) {
                const uint32_t (*Ah)[4] = (t < 3) ? axh : ach;
                const uint32_t (*Al)[4] = (t < 3) ? axl : acl;
                #pragma unroll
                for (int nb = 0; nb < 2; ++nb) {
                    uint32_t bh[4];
                    ldsm4(bh, fragA(sb + 40960 + t*5120, wn + nb*16, kb, lane));
                    #pragma unroll
                    for (int mi = 0; mi < 2; ++mi)
                        #pragma unroll
                        for (int j = 0; j < 2; ++j) {
                            float* d = acc[t][mi][nb*2 + j];
                            mmaf16(d, Ah[mi], bh[j], bh[j+2]);
                            mmaf16(d, Al[mi], bh[j], bh[j+2]);
                        }
                }
            }
        }
    };

    // Prologue: chunk 0 into buffer 0
    ldgA(0);
    issueW(0, 0); CPCOMMIT();
    stsA(0);
    CPWAIT0(); __syncthreads();

    #pragma unroll 1
    for (int c = 0; c < 8; ++c) {
        const int b  = c & 1;
        const int nb = b ^ 1;
        if (c < 7) { ldgA(c + 1); issueW(c + 1, nb); CPCOMMIT(); }
        compute(sbase + b * PJ_BUF);
        if (c < 7) {
            CPWAIT0();
            stsA(nb);           // writes buffer nb; compute(c) read buffer b
            __syncthreads();
        }
    }
    __syncthreads();   // all reads of GEMM buffers done before tiles are overwritten

    // --- Epilogue: scale*x+shift; write q(hi/lo), k(hi), v(hi) to SMEM ---
    const int g = lane >> 2, tg = lane & 3;
    const uint32_t abase = sbase + hh * 40960;
    #pragma unroll
    for (int mi = 0; mi < 2; ++mi)
        #pragma unroll
        for (int nj = 0; nj < 4; ++nj)
            #pragma unroll
            for (int h2 = 0; h2 < 2; ++h2) {
                const int row = wm + mi*16 + g + h2*8;        // token within seq
                const int col = nj*8 + tg*2;                  // channel within head
                const int i0 = h2*2;
                float sc0 = acc[3][mi][nj][i0],   sc1 = acc[3][mi][nj][i0+1];
                float sh0 = acc[4][mi][nj][i0],   sh1 = acc[4][mi][nj][i0+1];
                float q0 = fmaf(sc0, acc[0][mi][nj][i0], sh0), q1 = fmaf(sc1, acc[0][mi][nj][i0+1], sh1);
                float k0 = fmaf(sc0, acc[1][mi][nj][i0], sh0), k1 = fmaf(sc1, acc[1][mi][nj][i0+1], sh1);
                float v0 = fmaf(sc0, acc[2][mi][nj][i0], sh0), v1 = fmaf(sc1, acc[2][mi][nj][i0+1], sh1);
                uint32_t off = (uint32_t)(row*RSTR + col*2);
                uint32_t hi, lo;
                split2(q0, q1, hi, lo);
                *(uint32_t*)(smraw + (abase - sbase) + off)         = hi;   // QH
                *(uint32_t*)(smraw + (abase - sbase) + 10240 + off) = lo;   // QL
                split2(k0, k1, hi, lo);
                *(uint32_t*)(smraw + (abase - sbase) + 20480 + off) = hi;   // KH
                split2(v0, v1, hi, lo);
                *(uint32_t*)(smraw + (abase - sbase) + 30720 + off) = hi;   // VH
            }
    __syncthreads();

    // --- Attention phase: warp = (head hh, row stripe wm). S stripe 32x128. ---
    float p[2][16][4] = {};
    #pragma unroll
    for (int kb = 0; kb < 2; ++kb) {
        uint32_t aqh[2][4], aql[2][4];
        #pragma unroll
        for (int mi = 0; mi < 2; ++mi) {
            ldsm4(aqh[mi], fragA(abase,         wm + mi*16, kb, lane));
            ldsm4(aql[mi], fragA(abase + 10240, wm + mi*16, kb, lane));
        }
        #pragma unroll
        for (int nb = 0; nb < 8; ++nb) {
            uint32_t bkh[4];
            ldsm4(bkh, fragA(abase + 20480, nb*16, kb, lane));
            #pragma unroll
            for (int mi = 0; mi < 2; ++mi)
                #pragma unroll
                for (int j = 0; j < 2; ++j) {
                    float* d = p[mi][nb*2 + j];
                    mmaf16(d, aqh[mi], bkh[j], bkh[j+2]);
                    mmaf16(d, aql[mi], bkh[j], bkh[j+2]);
                }
        }
    }

    const float scl = 0.17677669529663688f;  // 1/sqrt(32)
    #pragma unroll
    for (int mi = 0; mi < 2; ++mi)
        #pragma unroll
        for (int nb = 0; nb < 16; ++nb)
            #pragma unroll
            for (int r = 0; r < 4; ++r)
                p[mi][nb][r] = __expf(p[mi][nb][r] * scl);

    // warp-local row softmax (each warp owns full 128 cols of its rows)
    #pragma unroll
    for (int mi = 0; mi < 2; ++mi)
        #pragma unroll
        for (int h2 = 0; h2 < 2; ++h2) {
            float s = 0.f;
            #pragma unroll
            for (int nb = 0; nb < 16; ++nb) s += p[mi][nb][h2*2] + p[mi][nb][h2*2+1];
            s += __shfl_xor_sync(0xffffffffu, s, 1);
            s += __shfl_xor_sync(0xffffffffu, s, 2);
            const float inv = 1.0f / s;
            #pragma unroll
            for (int nb = 0; nb < 16; ++nb) {
                p[mi][nb][h2*2]   *= inv;
                p[mi][nb][h2*2+1] *= inv;
            }
        }

    // SV: full K range per warp; P C-frags -> A-frags per 16-wide k block
    float o[2][4][4] = {};
    #pragma unroll
    for (int kk = 0; kk < 8; ++kk) {
        uint32_t ah[2][4], al[2][4];
        #pragma unroll
        for (int mi = 0; mi < 2; ++mi) {
            split2(p[mi][2*kk][0],   p[mi][2*kk][1],   ah[mi][0], al[mi][0]);
            split2(p[mi][2*kk][2],   p[mi][2*kk][3],   ah[mi][1], al[mi][1]);
            split2(p[mi][2*kk+1][0], p[mi][2*kk+1][1], ah[mi][2], al[mi][2]);
            split2(p[mi][2*kk+1][2], p[mi][2*kk+1][3], ah[mi][3], al[mi][3]);
        }
        uint32_t bh[2][4];
        #pragma unroll
        for (int ch = 0; ch < 2; ++ch) {
            uint32_t vaddr = abase + 30720
                + (uint32_t)(kk*16 + (lane & 15))*RSTR
                + (uint32_t)((lane >> 4) << 4) + (uint32_t)ch*32;
            ldsm4t(bh[ch], vaddr);
        }
        #pragma unroll
        for (int mi = 0; mi < 2; ++mi)
            #pragma unroll
            for (int ch = 0; ch < 2; ++ch)
                #pragma unroll
                for (int j = 0; j < 2; ++j) {
                    float* d = o[mi][ch*2 + j];
                    mmaf16(d, ah[mi], bh[ch][j*2], bh[ch][j*2+1]);
                    mmaf16(d, al[mi], bh[ch][j*2], bh[ch][j*2+1]);
                }
    }

    // direct O writes (hi/lo)
    const int hcol = (blockIdx.x*2 + hh) * EDIM;
    #pragma unroll
    for (int mi = 0; mi < 2; ++mi)
        #pragma unroll
        for (int nj = 0; nj < 4; ++nj)
            #pragma unroll
            for (int h2 = 0; h2 < 2; ++h2) {
                int row = m0 + wm + mi*16 + g + h2*8;
                int col = hcol + nj*8 + tg*2;
                uint32_t hi, lo;
                split2(o[mi][nj][h2*2], o[mi][nj][h2*2+1], hi, lo);
                *(uint32_t*)&g_oh[(size_t)row*CCH + col] = hi;
                *(uint32_t*)&g_ol[(size_t)row*CCH + col] = lo;
            }
}

// ---------------------------------------------------------------------------
// Kernel 3: out = O @ Wout^T (3-term, unchanged). CTA 128x128, 512 threads.
// buffer: AH 0, AL 10240, BH 20480, BL 30720 -> 40960/buf
// ---------------------------------------------------------------------------
#define OU_BUF 40960
#define OUT_SMEM (2*OU_BUF)

__global__ __launch_bounds__(512, 1) void out_kernel(float* __restrict__ out)
{
    const int tid = threadIdx.x;
    const int wid = tid >> 5, lane = tid & 31;
    const int n0 = blockIdx.x * 128;
    const int m0 = blockIdx.y * 128;
    const uint32_t sbase = smem_u32(smraw);

    auto issue = [&](int c, int b) {
        const int k0 = c * 32;
        const uint32_t sb = sbase + b * OU_BUF;
        int row = tid >> 2, seg = tid & 3;
        uint32_t so = (uint32_t)(row*RSTR + seg*16);
        size_t ga = (size_t)(m0 + row)*CCH + k0 + seg*8;
        CP16(sb + so,         g_oh + ga);
        CP16(sb + 10240 + so, g_ol + ga);
        size_t gb = (size_t)5*65536 + (size_t)(n0 + row)*CCH + k0 + seg*8;
        CP16(sb + 20480 + so, g_wh + gb);
        CP16(sb + 30720 + so, g_wl + gb);
    };

    float acc[2][4][4] = {};
    const int wm = (wid >> 2) * 32;
    const int wn = (wid & 3) * 32;

    auto compute = [&](uint32_t sb) {
        #pragma unroll
        for (int kb = 0; kb < 2; ++kb) {
            uint32_t ah[2][4], al[2][4];
            #pragma unroll
            for (int mi = 0; mi < 2; ++mi) {
                ldsm4(ah[mi], fragA(sb,         wm + mi*16, kb, lane));
                ldsm4(al[mi], fragA(sb + 10240, wm + mi*16, kb, lane));
            }
            #pragma unroll
            for (int nb = 0; nb < 2; ++nb) {
                uint32_t bh[4], bl[4];
                ldsm4(bh, fragA(sb + 20480, wn + nb*16, kb, lane));
                ldsm4(bl, fragA(sb + 30720, wn + nb*16, kb, lane));
                #pragma unroll
                for (int mi = 0; mi < 2; ++mi)
                    #pragma unroll
                    for (int j = 0; j < 2; ++j) {
                        float* d = acc[mi][nb*2 + j];
                        mmaf16(d, ah[mi], bh[j], bh[j+2]);
                        mmaf16(d, al[mi], bh[j], bh[j+2]);
                        mmaf16(d, ah[mi], bl[j], bl[j+2]);
                    }
            }
        }
    };

    issue(0, 0); CPCOMMIT();
    CPWAIT0(); __syncthreads();
    #pragma unroll 1
    for (int c = 0; c < 8; ++c) {
        if (c < 7) { issue(c + 1, (c + 1) & 1); CPCOMMIT(); }
        compute(sbase + (c & 1) * OU_BUF);
        if (c < 7) { CPWAIT0(); __syncthreads(); }
    }

    const int g = lane >> 2, tg = lane & 3;
    #pragma unroll
    for (int mi = 0; mi < 2; ++mi)
        #pragma unroll
        for (int ni = 0; ni < 4; ++ni)
            #pragma unroll
            for (int h2 = 0; h2 < 2; ++h2) {
                const int row = m0 + wm + mi*16 + g + h2*8;
                const int col = n0 + wn + ni*8 + tg*2;
                *(float2*)&out[(size_t)row*CCH + col] =
                    make_float2(acc[mi][ni][h2*2], acc[mi][ni][h2*2+1]);
            }
}

// ---------------------------------------------------------------------------
extern "C" void kernel_launch(void* const* d_in, const int* in_sizes, int n_in,
                              void* d_out, int out_size)
{
    (void)in_sizes; (void)n_in; (void)out_size;
    const float* X      = (const float*)d_in[0];
    const float* CTX    = (const float*)d_in[1];
    const float* Wq     = (const float*)d_in[2];
    const float* Wkv    = (const float*)d_in[3];
    const float* Wout   = (const float*)d_in[4];
    const float* Wscale = (const float*)d_in[5];
    const float* Wshift = (const float*)d_in[6];
    float* out = (float*)d_out;

    __half *wh, *wl;
    cudaGetSymbolAddress((void**)&wh, g_wh);
    cudaGetSymbolAddress((void**)&wl, g_wl);

    cudaFuncSetAttribute(proj_attn_kernel, cudaFuncAttributeMaxDynamicSharedMemorySize, PROJ_SMEM);
    cudaFuncSetAttribute(out_kernel,       cudaFuncAttributeMaxDynamicSharedMemorySize, OUT_SMEM);

    // weight conversion only (tiny)
    conv_hi_kernel<<<64, 256>>>((const float4*)Wq,     (uint2*)(wh + 0*65536), 16384);
    conv_hi_kernel<<<128, 256>>>((const float4*)Wkv,   (uint2*)(wh + 1*65536), 32768);
    conv_hi_kernel<<<64, 256>>>((const float4*)Wscale, (uint2*)(wh + 3*65536), 16384);
    conv_hi_kernel<<<64, 256>>>((const float4*)Wshift, (uint2*)(wh + 4*65536), 16384);
    conv_kernel<<<64, 256>>>((const float4*)Wout,      (uint2*)(wh + 5*65536), (uint2*)(wl + 5*65536), 16384);

    proj_attn_kernel<<<dim3(4, 1024), 256, PROJ_SMEM>>>(X, CTX);
    out_kernel<<<dim3(2, 1024), 512, OUT_SMEM>>>(out);
}